// round 8
// baseline (speedup 1.0000x reference)
#include <cuda_runtime.h>
#include <cuda_bf16.h>
#include <math.h>
#include <stdint.h>

// Problem constants
#define BB   2
#define TT   2048
#define CC   1024
#define HH   16
#define KVH  4
#define DH   64
#define NREP 4
#define FF   4096
#define EE   8
#define TOPK 2
#define WIN  1024
#define NTOK (BB*TT)            // 4096
#define OUT_MAIN (NTOK*CC)      // 4194304
#define QKVN (CC + 2*KVH*DH)    // 1536
#define ECAP 9216               // 8192 real rows + padding, 128-aligned

// ---------------- scratch (device globals; no allocation) ----------------
__device__ float g_qkv [NTOK*QKVN];
__device__ float g_h   [NTOK*CC];
__device__ float g_xf  [NTOK*CC];
__device__ float g_moe [NTOK*CC];
__device__ float g_eo  [(size_t)ECAP*CC];
__device__ float g_probs[NTOK*EE];
__device__ float g_lse2[NTOK];
__device__ int   g_sel [NTOK*2];
__device__ float g_selw[NTOK*2];
__device__ int   g_cnt [EE];
__device__ int   g_cnt2[EE];
__device__ int   g_off [EE+1];
__device__ int   g_idx [ECAP];
__device__ int   g_tokrow[NTOK*2];
__device__ float g_aux;

// bf16 activations
__device__ __nv_bfloat16 g_xnb [NTOK*CC];
__device__ __nv_bfloat16 g_aob [NTOK*CC];
__device__ __nv_bfloat16 g_xfb [NTOK*CC];
__device__ __nv_bfloat16 g_xgb [(size_t)ECAP*CC];
__device__ __nv_bfloat16 g_g1b [(size_t)ECAP*FF];

// bf16 transposed weights [N,K] (w12 interleaved: w1->2f, w2->2f+1)
__device__ __nv_bfloat16 g_wqkvt[QKVN*CC];
__device__ __nv_bfloat16 g_wot  [CC*CC];
__device__ __nv_bfloat16 g_sw12t[2*FF*CC];
__device__ __nv_bfloat16 g_sw3t [CC*FF];
__device__ __nv_bfloat16 g_ew12t[(size_t)EE*2*FF*CC];
__device__ __nv_bfloat16 g_ew3t [(size_t)EE*CC*FF];

__device__ __forceinline__ uint32_t su32(const void* p) {
    uint32_t a;
    asm("{ .reg .u64 t; cvta.to.shared.u64 t, %1; cvt.u32.u64 %0, t; }" : "=r"(a) : "l"(p));
    return a;
}
__device__ __forceinline__ uint32_t packbf(float a, float b) {
    __nv_bfloat162 t = __floats2bfloat162_rn(a, b);
    return *(uint32_t*)&t;
}

#define CP_ASYNC16(d, s) asm volatile("cp.async.cg.shared.global [%0], [%1], 16;" :: "r"(d), "l"(s))
#define CP_COMMIT()      asm volatile("cp.async.commit_group;" ::: "memory")
#define CP_WAIT(n)       asm volatile("cp.async.wait_group %0;" :: "n"(n) : "memory")

#define BM 128
#define BN 128
#define BK 32
#define ASTR 40          // padded row stride in bf16 elems
#define STGSZ (BM*ASTR)  // 5120 elems per stage
#define GEMM_SMEM (6*STGSZ*2)  // 61440 bytes (3 stages x A,B)

// ================= 3-stage GEMM mainloop (dynamic smem) ==================
#define GEMM_PREFETCH(A_, Bt_, K_, sidx, k0)                                   \
    {                                                                          \
        const __nv_bfloat16* srcA = (A_) + (size_t)(rowBase + lrow) * (K_) + (k0) + lc16; \
        const __nv_bfloat16* srcB = (Bt_) + (size_t)(colBase + lrow) * (K_) + (k0) + lc16; \
        uint32_t dA = su32(&smA[(sidx)*STGSZ + lrow * ASTR + lc16]);           \
        uint32_t dB = su32(&smB[(sidx)*STGSZ + lrow * ASTR + lc16]);           \
        CP_ASYNC16(dA, srcA); CP_ASYNC16(dA + 16, srcA + 8);                   \
        CP_ASYNC16(dB, srcB); CP_ASYNC16(dB + 16, srcB + 8);                   \
        CP_COMMIT();                                                           \
    }

#define GEMM_MAIN(A_, Bt_, K_)                                                 \
    extern __shared__ __nv_bfloat16 smemd[];                                   \
    __nv_bfloat16* smA = smemd;                                                \
    __nv_bfloat16* smB = smemd + 3*STGSZ;                                      \
    int tid = threadIdx.x;                                                     \
    int wid = tid >> 5, lane = tid & 31;                                       \
    int wm = wid >> 2, wn = wid & 3;                                           \
    float cr[4][4][4];                                                         \
    _Pragma("unroll") for (int i = 0; i < 4; i++)                              \
    _Pragma("unroll") for (int j = 0; j < 4; j++)                              \
    _Pragma("unroll") for (int r = 0; r < 4; r++) cr[i][j][r] = 0.f;           \
    int lrow = tid >> 1;                                                       \
    int lc16 = (tid & 1) * 16;                                                 \
    int nCh = (K_) / BK;                                                       \
    GEMM_PREFETCH(A_, Bt_, K_, 0, 0)                                           \
    GEMM_PREFETCH(A_, Bt_, K_, 1, BK)                                          \
    int bufc = 0;                                                              \
    for (int ch = 0; ch < nCh; ch++) {                                         \
        if (ch + 2 < nCh) {                                                    \
            int bp = bufc + 2; if (bp >= 3) bp -= 3;                           \
            GEMM_PREFETCH(A_, Bt_, K_, bp, (ch + 2) * BK)                      \
            CP_WAIT(2);                                                        \
        } else if (ch + 1 < nCh) { CP_WAIT(1); } else { CP_WAIT(0); }          \
        __syncthreads();                                                       \
        int r16 = lane & 15, kh = lane >> 4;                                   \
        int rn = lane & 7, knh = (lane >> 3) & 1;                              \
        _Pragma("unroll") for (int kk = 0; kk < 2; kk++) {                     \
            uint32_t af[4][4];                                                 \
            _Pragma("unroll") for (int mf = 0; mf < 4; mf++) {                 \
                uint32_t ad = su32(&smA[bufc*STGSZ + (wm * 64 + mf * 16 + r16) * ASTR + kk * 16 + kh * 8]); \
                asm volatile("ldmatrix.sync.aligned.m8n8.x4.shared.b16 {%0,%1,%2,%3}, [%4];" \
                    : "=r"(af[mf][0]), "=r"(af[mf][1]), "=r"(af[mf][2]), "=r"(af[mf][3]) : "r"(ad)); \
            }                                                                  \
            uint32_t bfr[4][2];                                                \
            _Pragma("unroll") for (int nf = 0; nf < 4; nf++) {                 \
                uint32_t bd = su32(&smB[bufc*STGSZ + (wn * 32 + nf * 8 + rn) * ASTR + kk * 16 + knh * 8]); \
                asm volatile("ldmatrix.sync.aligned.m8n8.x2.shared.b16 {%0,%1}, [%2];" \
                    : "=r"(bfr[nf][0]), "=r"(bfr[nf][1]) : "r"(bd));           \
            }                                                                  \
            _Pragma("unroll") for (int mf = 0; mf < 4; mf++)                   \
            _Pragma("unroll") for (int nf = 0; nf < 4; nf++) {                 \
                asm volatile(                                                  \
                    "mma.sync.aligned.m16n8k16.row.col.f32.bf16.bf16.f32 "     \
                    "{%0,%1,%2,%3}, {%4,%5,%6,%7}, {%8,%9}, {%0,%1,%2,%3};"    \
                    : "+f"(cr[mf][nf][0]), "+f"(cr[mf][nf][1]),                \
                      "+f"(cr[mf][nf][2]), "+f"(cr[mf][nf][3])                 \
                    : "r"(af[mf][0]), "r"(af[mf][1]), "r"(af[mf][2]), "r"(af[mf][3]), \
                      "r"(bfr[nf][0]), "r"(bfr[nf][1]));                       \
            }                                                                  \
        }                                                                      \
        __syncthreads();                                                       \
        bufc = (bufc == 2) ? 0 : bufc + 1;                                     \
    }                                                                          \
    int rr = lane >> 2, cq = (lane & 3) * 2;

// ================= dense GEMM, fp32 out =================
__global__ __launch_bounds__(256) void gemm_mma(
    const __nv_bfloat16* __restrict__ A, const __nv_bfloat16* __restrict__ Bt,
    float* __restrict__ C, int N, int K)
{
    int rowBase = blockIdx.y * BM, colBase = blockIdx.x * BN;
    GEMM_MAIN(A, Bt, K)
#pragma unroll
    for (int mf = 0; mf < 4; mf++)
#pragma unroll
        for (int nf = 0; nf < 4; nf++) {
            int row0 = rowBase + wm * 64 + mf * 16 + rr;
            int col = colBase + wn * 32 + nf * 8 + cq;
            *(float2*)&C[(size_t)row0 * N + col] = make_float2(cr[mf][nf][0], cr[mf][nf][1]);
            *(float2*)&C[(size_t)(row0 + 8) * N + col] = make_float2(cr[mf][nf][2], cr[mf][nf][3]);
        }
}

// ===== dense GEMM with fused ReZero residual: C = X + (*alpha)*(A@Bt) ====
__global__ __launch_bounds__(256) void gemm_mma_add(
    const __nv_bfloat16* __restrict__ A, const __nv_bfloat16* __restrict__ Bt,
    const float* __restrict__ X, const float* __restrict__ alpha,
    float* __restrict__ C, int N, int K)
{
    int rowBase = blockIdx.y * BM, colBase = blockIdx.x * BN;
    GEMM_MAIN(A, Bt, K)
    float a = *alpha;
#pragma unroll
    for (int mf = 0; mf < 4; mf++)
#pragma unroll
        for (int nf = 0; nf < 4; nf++) {
            int row0 = rowBase + wm * 64 + mf * 16 + rr;
            int col = colBase + wn * 32 + nf * 8 + cq;
            float2 x0 = *(const float2*)&X[(size_t)row0 * N + col];
            float2 x1 = *(const float2*)&X[(size_t)(row0 + 8) * N + col];
            *(float2*)&C[(size_t)row0 * N + col] =
                make_float2(x0.x + a * cr[mf][nf][0], x0.y + a * cr[mf][nf][1]);
            *(float2*)&C[(size_t)(row0 + 8) * N + col] =
                make_float2(x1.x + a * cr[mf][nf][2], x1.y + a * cr[mf][nf][3]);
        }
}

// ================= dense GEMM, fused SwiGLU bf16 out (interleaved w12) ===
__global__ __launch_bounds__(256) void gemm_swiglu(
    const __nv_bfloat16* __restrict__ A, const __nv_bfloat16* __restrict__ Bt,
    __nv_bfloat16* __restrict__ Obf, int N2, int K)
{
    int rowBase = blockIdx.y * BM, colBase = blockIdx.x * BN;
    GEMM_MAIN(A, Bt, K)
    int FFo = N2 >> 1;
#pragma unroll
    for (int mf = 0; mf < 4; mf++)
#pragma unroll
        for (int nf = 0; nf < 4; nf++) {
            int row0 = rowBase + wm * 64 + mf * 16 + rr;
            int f = (colBase + wn * 32 + nf * 8 + cq) >> 1;
            float a0 = cr[mf][nf][0], b0 = cr[mf][nf][1];
            Obf[(size_t)row0 * FFo + f] = __float2bfloat16(a0 / (1.f + __expf(-a0)) * b0);
            float a1 = cr[mf][nf][2], b1 = cr[mf][nf][3];
            Obf[(size_t)(row0 + 8) * FFo + f] = __float2bfloat16(a1 / (1.f + __expf(-a1)) * b1);
        }
}

// ================= MoE GEMM, fp32 out =================
__global__ __launch_bounds__(256) void gemm_moe(
    const __nv_bfloat16* __restrict__ A, const __nv_bfloat16* __restrict__ Wb,
    float* __restrict__ C, int N, int K, long wstride)
{
    int rowBase = blockIdx.y * BM;
    if (rowBase >= g_off[EE]) return;
    int colBase = blockIdx.x * BN;
    int e = 0;
    while (g_off[e + 1] <= rowBase) e++;
    const __nv_bfloat16* Bt = Wb + (size_t)e * wstride;
    GEMM_MAIN(A, Bt, K)
#pragma unroll
    for (int mf = 0; mf < 4; mf++)
#pragma unroll
        for (int nf = 0; nf < 4; nf++) {
            int row0 = rowBase + wm * 64 + mf * 16 + rr;
            int col = colBase + wn * 32 + nf * 8 + cq;
            *(float2*)&C[(size_t)row0 * N + col] = make_float2(cr[mf][nf][0], cr[mf][nf][1]);
            *(float2*)&C[(size_t)(row0 + 8) * N + col] = make_float2(cr[mf][nf][2], cr[mf][nf][3]);
        }
}

// ================= MoE GEMM, fused SwiGLU bf16 out =================
__global__ __launch_bounds__(256) void gemm_moe_swiglu(
    const __nv_bfloat16* __restrict__ A, const __nv_bfloat16* __restrict__ Wb,
    __nv_bfloat16* __restrict__ Obf, int N2, int K, long wstride)
{
    int rowBase = blockIdx.y * BM;
    if (rowBase >= g_off[EE]) return;
    int colBase = blockIdx.x * BN;
    int e = 0;
    while (g_off[e + 1] <= rowBase) e++;
    const __nv_bfloat16* Bt = Wb + (size_t)e * wstride;
    GEMM_MAIN(A, Bt, K)
    int FFo = N2 >> 1;
#pragma unroll
    for (int mf = 0; mf < 4; mf++)
#pragma unroll
        for (int nf = 0; nf < 4; nf++) {
            int row0 = rowBase + wm * 64 + mf * 16 + rr;
            int f = (colBase + wn * 32 + nf * 8 + cq) >> 1;
            float a0 = cr[mf][nf][0], b0 = cr[mf][nf][1];
            Obf[(size_t)row0 * FFo + f] = __float2bfloat16(a0 / (1.f + __expf(-a0)) * b0);
            float a1 = cr[mf][nf][2], b1 = cr[mf][nf][3];
            Obf[(size_t)(row0 + 8) * FFo + f] = __float2bfloat16(a1 / (1.f + __expf(-a1)) * b1);
        }
}

// ---------------- weight transpose+convert with row interleave ----------
__global__ void wconv2(const float* __restrict__ W, __nv_bfloat16* __restrict__ Wt,
                       int K, int N, long sstride, long dstride, int rs, int ro) {
    __shared__ float t[64][65];
    const float* Wz = W + (size_t)blockIdx.z * sstride;
    __nv_bfloat16* Wtz = Wt + (size_t)blockIdx.z * dstride;
    int n0 = blockIdx.x * 64, k0 = blockIdx.y * 64;
    int tid = threadIdx.x;
    int rrw = tid >> 4;
    int c4 = (tid & 15) * 4;
#pragma unroll
    for (int r = 0; r < 64; r += 16) {
        float4 v = *(const float4*)&Wz[(size_t)(k0 + r + rrw) * N + n0 + c4];
        t[r + rrw][c4 + 0] = v.x; t[r + rrw][c4 + 1] = v.y;
        t[r + rrw][c4 + 2] = v.z; t[r + rrw][c4 + 3] = v.w;
    }
    __syncthreads();
    int nl = tid >> 3;
    int c8 = (tid & 7) * 8;
#pragma unroll
    for (int r = 0; r < 64; r += 32) {
        int n = nl + r;
        __nv_bfloat16 o[8];
#pragma unroll
        for (int j = 0; j < 8; j++) o[j] = __float2bfloat16(t[c8 + j][n]);
        *(uint4*)&Wtz[((size_t)(n0 + n) * rs + ro) * K + k0 + c8] = *(uint4*)o;
    }
}

// ---------------- RMSNorm (dual output) ----------------
__global__ void rmsnorm_kernel(const float* __restrict__ x,
                               const float* __restrict__ w,
                               float* __restrict__ of,
                               __nv_bfloat16* __restrict__ ob) {
    int row = blockIdx.x;
    int tid = threadIdx.x;
    const float* xr = x + (size_t)row * CC;
    float s = 0.f;
    for (int i = tid; i < CC; i += 256) { float v = xr[i]; s += v * v; }
    __shared__ float red[256];
    red[tid] = s; __syncthreads();
    for (int o2 = 128; o2 > 0; o2 >>= 1) {
        if (tid < o2) red[tid] += red[tid + o2];
        __syncthreads();
    }
    float scale = rsqrtf(red[0] / (float)CC + 1e-6f);
    for (int i = tid; i < CC; i += 256) {
        float v = xr[i] * scale * w[i];
        if (of) of[(size_t)row * CC + i] = v;
        ob[(size_t)row * CC + i] = __float2bfloat16(v);
    }
}

// ---------------- RoPE (in place in qkv buffer) --------------------------
__global__ void rope_kernel(float* __restrict__ X, int nheads, int hoff) {
    int i = blockIdx.x * blockDim.x + threadIdx.x;
    int total = NTOK * nheads * 32;
    if (i >= total) return;
    int p = i & 31;
    int tmp = i >> 5;
    int hh = tmp % nheads;
    int row = tmp / nheads;
    int t = row % TT;
    float invf = expf(-(float)p * (logf(10000.f) / 32.f));
    float ang = (float)t * invf;
    float cs = cosf(ang), sn = sinf(ang);
    size_t base = (size_t)row * QKVN + hoff + hh * 64;
    float a = X[base + p];
    float b = X[base + p + 32];
    X[base + p]      = a * cs - b * sn;
    X[base + p + 32] = b * cs + a * sn;
}

// ---------------- flash attention: 128-row Q tiles, mma.sync -------------
__global__ __launch_bounds__(256) void attn_mma(const float* __restrict__ QKV,
                                                __nv_bfloat16* __restrict__ O) {
    int qb = blockIdx.x, h = blockIdx.y, b = blockIdx.z;
    int tid = threadIdx.x;
    int wid = tid >> 5, lane = tid & 31;
    int kvh = h / NREP;

    __shared__ __align__(16) __nv_bfloat16 Qs[128 * 72];
    __shared__ __align__(16) __nv_bfloat16 Ks[64 * 72];
    __shared__ __align__(16) __nv_bfloat16 Vt[64 * 72];

    for (int i = tid; i < 128 * 32; i += 256) {
        int row = i >> 5, p2 = i & 31;
        const float* src = QKV + ((size_t)(b * TT + qb * 128 + row)) * QKVN + h * DH + p2 * 2;
        *(__nv_bfloat162*)&Qs[row * 72 + p2 * 2] =
            __floats2bfloat162_rn(src[0] * 0.125f, src[1] * 0.125f);
    }
    __syncthreads();

    int r16 = lane & 15, kh = lane >> 4;
    int rn = lane & 7, knh = (lane >> 3) & 1;
    uint32_t qf[4][4];
#pragma unroll
    for (int kk = 0; kk < 4; kk++) {
        uint32_t ad = su32(&Qs[(wid * 16 + r16) * 72 + kk * 16 + kh * 8]);
        asm volatile("ldmatrix.sync.aligned.m8n8.x4.shared.b16 {%0,%1,%2,%3}, [%4];"
            : "=r"(qf[kk][0]), "=r"(qf[kk][1]), "=r"(qf[kk][2]), "=r"(qf[kk][3]) : "r"(ad));
    }

    int rr = lane >> 2, cq = (lane & 3) * 2;
    int t0 = qb * 128 + wid * 16 + rr;  // second row = t0+8
    float m0 = -1e30f, m1 = -1e30f, l0 = 0.f, l1 = 0.f;
    float acc[8][4];
#pragma unroll
    for (int dn = 0; dn < 8; dn++)
#pragma unroll
        for (int r = 0; r < 4; r++) acc[dn][r] = 0.f;

    int kstart = qb * 128 - WIN; if (kstart < 0) kstart = 0;
    int kend = qb * 128 + 64;
    for (int k0 = kstart; k0 <= kend; k0 += 64) {
        __syncthreads();
        for (int i = tid; i < 64 * 32; i += 256) {
            int row = i >> 5, p2 = i & 31;
            const float* kv = QKV + ((size_t)(b * TT + k0 + row)) * QKVN + CC + kvh * DH;
            *(__nv_bfloat162*)&Ks[row * 72 + p2 * 2] =
                __floats2bfloat162_rn(kv[p2 * 2], kv[p2 * 2 + 1]);
            const float* vv = kv + KVH * DH;
            Vt[(p2 * 2) * 72 + row]     = __float2bfloat16(vv[p2 * 2]);
            Vt[(p2 * 2 + 1) * 72 + row] = __float2bfloat16(vv[p2 * 2 + 1]);
        }
        __syncthreads();

        float s[8][4];
#pragma unroll
        for (int j = 0; j < 8; j++) {
            s[j][0] = s[j][1] = s[j][2] = s[j][3] = 0.f;
#pragma unroll
            for (int kk = 0; kk < 4; kk++) {
                uint32_t bfr[2];
                uint32_t bd = su32(&Ks[(j * 8 + rn) * 72 + kk * 16 + knh * 8]);
                asm volatile("ldmatrix.sync.aligned.m8n8.x2.shared.b16 {%0,%1}, [%2];"
                    : "=r"(bfr[0]), "=r"(bfr[1]) : "r"(bd));
                asm volatile(
                    "mma.sync.aligned.m16n8k16.row.col.f32.bf16.bf16.f32 "
                    "{%0,%1,%2,%3}, {%4,%5,%6,%7}, {%8,%9}, {%0,%1,%2,%3};"
                    : "+f"(s[j][0]), "+f"(s[j][1]), "+f"(s[j][2]), "+f"(s[j][3])
                    : "r"(qf[kk][0]), "r"(qf[kk][1]), "r"(qf[kk][2]), "r"(qf[kk][3]),
                      "r"(bfr[0]), "r"(bfr[1]));
            }
        }
#pragma unroll
        for (int j = 0; j < 8; j++) {
            int kg = k0 + j * 8 + cq;
            if (kg > t0 || kg < t0 - WIN) s[j][0] = -1e30f;
            if (kg + 1 > t0 || kg + 1 < t0 - WIN) s[j][1] = -1e30f;
            if (kg > t0 + 8 || kg < t0 + 8 - WIN) s[j][2] = -1e30f;
            if (kg + 1 > t0 + 8 || kg + 1 < t0 + 8 - WIN) s[j][3] = -1e30f;
        }
        float mx0 = -1e30f, mx1 = -1e30f;
#pragma unroll
        for (int j = 0; j < 8; j++) {
            mx0 = fmaxf(mx0, fmaxf(s[j][0], s[j][1]));
            mx1 = fmaxf(mx1, fmaxf(s[j][2], s[j][3]));
        }
        mx0 = fmaxf(mx0, __shfl_xor_sync(0xffffffffu, mx0, 1));
        mx0 = fmaxf(mx0, __shfl_xor_sync(0xffffffffu, mx0, 2));
        mx1 = fmaxf(mx1, __shfl_xor_sync(0xffffffffu, mx1, 1));
        mx1 = fmaxf(mx1, __shfl_xor_sync(0xffffffffu, mx1, 2));
        float mn0 = fmaxf(m0, mx0), mn1 = fmaxf(m1, mx1);
        float z0 = (mn0 > -5e29f) ? 1.f : 0.f;
        float z1 = (mn1 > -5e29f) ? 1.f : 0.f;
        float c0 = __expf(m0 - mn0), c1 = __expf(m1 - mn1);
        m0 = mn0; m1 = mn1;
        l0 *= c0; l1 *= c1;
#pragma unroll
        for (int dn = 0; dn < 8; dn++) {
            acc[dn][0] *= c0; acc[dn][1] *= c0;
            acc[dn][2] *= c1; acc[dn][3] *= c1;
        }
#pragma unroll
        for (int j = 0; j < 8; j++) {
            s[j][0] = __expf(s[j][0] - m0) * z0; s[j][1] = __expf(s[j][1] - m0) * z0;
            s[j][2] = __expf(s[j][2] - m1) * z1; s[j][3] = __expf(s[j][3] - m1) * z1;
            l0 += s[j][0] + s[j][1];
            l1 += s[j][2] + s[j][3];
        }
        uint32_t pa[4][4];
#pragma unroll
        for (int kk = 0; kk < 4; kk++) {
            int j0 = kk * 2, j1 = kk * 2 + 1;
            pa[kk][0] = packbf(s[j0][0], s[j0][1]);
            pa[kk][1] = packbf(s[j0][2], s[j0][3]);
            pa[kk][2] = packbf(s[j1][0], s[j1][1]);
            pa[kk][3] = packbf(s[j1][2], s[j1][3]);
        }
#pragma unroll
        for (int dn = 0; dn < 8; dn++)
#pragma unroll
            for (int kk = 0; kk < 4; kk++) {
                uint32_t bfr[2];
                uint32_t bd = su32(&Vt[(dn * 8 + rn) * 72 + kk * 16 + knh * 8]);
                asm volatile("ldmatrix.sync.aligned.m8n8.x2.shared.b16 {%0,%1}, [%2];"
                    : "=r"(bfr[0]), "=r"(bfr[1]) : "r"(bd));
                asm volatile(
                    "mma.sync.aligned.m16n8k16.row.col.f32.bf16.bf16.f32 "
                    "{%0,%1,%2,%3}, {%4,%5,%6,%7}, {%8,%9}, {%0,%1,%2,%3};"
                    : "+f"(acc[dn][0]), "+f"(acc[dn][1]), "+f"(acc[dn][2]), "+f"(acc[dn][3])
                    : "r"(pa[kk][0]), "r"(pa[kk][1]), "r"(pa[kk][2]), "r"(pa[kk][3]),
                      "r"(bfr[0]), "r"(bfr[1]));
            }
    }
    l0 += __shfl_xor_sync(0xffffffffu, l0, 1);
    l0 += __shfl_xor_sync(0xffffffffu, l0, 2);
    l1 += __shfl_xor_sync(0xffffffffu, l1, 1);
    l1 += __shfl_xor_sync(0xffffffffu, l1, 2);
    float i0 = 1.f / l0, i1 = 1.f / l1;
    __nv_bfloat16* o0 = O + ((size_t)(b * TT + t0)) * CC + h * DH;
    __nv_bfloat16* o1 = o0 + (size_t)8 * CC;
#pragma unroll
    for (int dn = 0; dn < 8; dn++) {
        *(__nv_bfloat162*)&o0[dn * 8 + cq] =
            __floats2bfloat162_rn(acc[dn][0] * i0, acc[dn][1] * i0);
        *(__nv_bfloat162*)&o1[dn * 8 + cq] =
            __floats2bfloat162_rn(acc[dn][2] * i1, acc[dn][3] * i1);
    }
}

// ---------------- router ----------------
__global__ void route_kernel(const float* __restrict__ xf,
                             const float* __restrict__ gw) {
    int warp = threadIdx.x >> 5, lane = threadIdx.x & 31;
    int tok = blockIdx.x * 4 + warp;
    if (tok >= NTOK) return;
    const float* xr = xf + (size_t)tok * CC;
    float part[EE];
#pragma unroll
    for (int e = 0; e < EE; e++) part[e] = 0.f;
    for (int d = lane; d < CC; d += 32) {
        float xv = xr[d];
#pragma unroll
        for (int e = 0; e < EE; e++) part[e] += xv * gw[d * EE + e];
    }
#pragma unroll
    for (int e = 0; e < EE; e++)
#pragma unroll
        for (int o = 16; o > 0; o >>= 1)
            part[e] += __shfl_xor_sync(0xffffffffu, part[e], o);
    if (lane == 0) {
        float v0 = -1e30f; int i0 = 0;
#pragma unroll
        for (int e = 0; e < EE; e++) if (part[e] > v0) { v0 = part[e]; i0 = e; }
        float v1 = -1e30f; int i1 = 0;
#pragma unroll
        for (int e = 0; e < EE; e++)
            if (e != i0 && part[e] > v1) { v1 = part[e]; i1 = e; }
        float ex = expf(v1 - v0);
        float w0 = 1.f / (1.f + ex);
        float w1 = ex / (1.f + ex);
        g_sel[tok * 2] = i0; g_sel[tok * 2 + 1] = i1;
        g_selw[tok * 2] = w0; g_selw[tok * 2 + 1] = w1;
        float mx = v0, sum = 0.f, pe[EE];
#pragma unroll
        for (int e = 0; e < EE; e++) { pe[e] = expf(part[e] - mx); sum += pe[e]; }
#pragma unroll
        for (int e = 0; e < EE; e++) g_probs[tok * EE + e] = pe[e] / sum;
        float lse = mx + logf(sum);
        g_lse2[tok] = lse * lse;
    }
}

// ---------------- aux loss ----------------
__global__ void aux_kernel() {
    __shared__ float red[256];
    int tid = threadIdx.x;
    float loadv[EE];
#pragma unroll
    for (int e = 0; e < EE; e++) loadv[e] = 0.f;
    for (int n = tid; n < NTOK; n += 256) {
#pragma unroll
        for (int e = 0; e < EE; e++) loadv[e] += g_probs[n * EE + e];
    }
    float loads[EE];
    for (int e = 0; e < EE; e++) {
        red[tid] = loadv[e]; __syncthreads();
        for (int o = 128; o > 0; o >>= 1) {
            if (tid < o) red[tid] += red[tid + o];
            __syncthreads();
        }
        loads[e] = red[0]; __syncthreads();
    }
    float zp = 0.f;
    for (int n = tid; n < NTOK; n += 256) zp += g_lse2[n];
    red[tid] = zp; __syncthreads();
    for (int o = 128; o > 0; o >>= 1) {
        if (tid < o) red[tid] += red[tid + o];
        __syncthreads();
    }
    if (tid == 0) {
        float tot = 0.f;
        for (int e = 0; e < EE; e++) tot += loads[e];
        float lb = 0.f;
        for (int e = 0; e < EE; e++) { float f = loads[e] / tot; lb += f * f; }
        lb *= (float)EE;
        float z = red[0] / (float)NTOK;
        g_aux = 0.01f * lb + 0.001f * z;
    }
}

__global__ void zero_cnt_kernel() { if (threadIdx.x < EE) g_cnt[threadIdx.x] = 0; }

__global__ void count_kernel() {
    int i = blockIdx.x * blockDim.x + threadIdx.x;
    if (i >= NTOK) return;
#pragma unroll
    for (int kk = 0; kk < TOPK; kk++)
        atomicAdd(&g_cnt[g_sel[i * 2 + kk]], 1);
}

__global__ void offsets_kernel() {
    if (threadIdx.x == 0) {
        int acc = 0;
        for (int e = 0; e < EE; e++) {
            g_off[e] = acc;
            acc += (g_cnt[e] + BM - 1) & ~(BM - 1);
            g_cnt2[e] = 0;
        }
        g_off[EE] = acc;
    }
}

__global__ void assign_kernel() {
    int i = blockIdx.x * blockDim.x + threadIdx.x;
    if (i >= NTOK) return;
#pragma unroll
    for (int kk = 0; kk < TOPK; kk++) {
        int e = g_sel[i * 2 + kk];
        int pos = atomicAdd(&g_cnt2[e], 1);
        int row = g_off[e] + pos;
        g_idx[row] = i;
        g_tokrow[i * 2 + kk] = row;
    }
}

__global__ void gather_all_kernel(__nv_bfloat16* __restrict__ dst,
                                  const __nv_bfloat16* __restrict__ src) {
    int b = blockIdx.x;
    if (b >= g_off[EE]) return;
    int e = 0;
    while (g_off[e + 1] <= b) e++;
    if (b - g_off[e] >= g_cnt[e]) return;
    int t = g_idx[b];
    uint4* d4 = (uint4*)(dst + (size_t)b * CC);
    const uint4* s4 = (const uint4*)(src + (size_t)t * CC);
    int i = threadIdx.x;
    if (i < CC * 2 / 16) d4[i] = s4[i];
}

// final: out = h + a_moe * (shared + w0*eo[r0] + w1*eo[r1])
__global__ void final_kernel(const float* __restrict__ h, const float* __restrict__ moe,
                             const float* __restrict__ eo,
                             const float* __restrict__ alpha, float* __restrict__ out) {
    int t = blockIdx.x;
    float w0 = g_selw[t * 2], w1 = g_selw[t * 2 + 1];
    int r0 = g_tokrow[t * 2], r1 = g_tokrow[t * 2 + 1];
    float a = *alpha;
    const float* hr = h + (size_t)t * CC;
    const float* mr = moe + (size_t)t * CC;
    const float* e0 = eo + (size_t)r0 * CC;
    const float* e1 = eo + (size_t)r1 * CC;
    float* orow = out + (size_t)t * CC;
    for (int i = threadIdx.x; i < CC; i += blockDim.x)
        orow[i] = hr[i] + a * (mr[i] + w0 * e0[i] + w1 * e1[i]);
}

__global__ void auxwrite_kernel(float* __restrict__ out) { out[OUT_MAIN] = g_aux; }

// ---------------- launch ----------------
extern "C" void kernel_launch(void* const* d_in, const int* in_sizes, int n_in,
                              void* d_out, int out_size) {
    const float* x      = (const float*)d_in[0];
    const float* ln1    = (const float*)d_in[1];
    const float* ln2    = (const float*)d_in[2];
    const float* wq     = (const float*)d_in[3];
    const float* wk     = (const float*)d_in[4];
    const float* wv     = (const float*)d_in[5];
    const float* wo     = (const float*)d_in[6];
    const float* sw1    = (const float*)d_in[7];
    const float* sw2    = (const float*)d_in[8];
    const float* sw3    = (const float*)d_in[9];
    const float* ew1    = (const float*)d_in[10];
    const float* ew2    = (const float*)d_in[11];
    const float* ew3    = (const float*)d_in[12];
    const float* gatew  = (const float*)d_in[13];
    const float* a_attn = (const float*)d_in[14];
    const float* a_moe  = (const float*)d_in[15];
    float* out = (float*)d_out;

    void* p;
    float *qkv, *h, *xf, *moe, *eo;
    __nv_bfloat16 *xnb, *aob, *xfb, *xgb, *g1b;
    __nv_bfloat16 *wqkvt, *wot, *sw12t, *sw3t, *ew12t, *ew3t;
    cudaGetSymbolAddress(&p, g_qkv);  qkv  = (float*)p;
    cudaGetSymbolAddress(&p, g_h);    h    = (float*)p;
    cudaGetSymbolAddress(&p, g_xf);   xf   = (float*)p;
    cudaGetSymbolAddress(&p, g_moe);  moe  = (float*)p;
    cudaGetSymbolAddress(&p, g_eo);   eo   = (float*)p;
    cudaGetSymbolAddress(&p, g_xnb);  xnb  = (__nv_bfloat16*)p;
    cudaGetSymbolAddress(&p, g_aob);  aob  = (__nv_bfloat16*)p;
    cudaGetSymbolAddress(&p, g_xfb);  xfb  = (__nv_bfloat16*)p;
    cudaGetSymbolAddress(&p, g_xgb);  xgb  = (__nv_bfloat16*)p;
    cudaGetSymbolAddress(&p, g_g1b);  g1b  = (__nv_bfloat16*)p;
    cudaGetSymbolAddress(&p, g_wqkvt); wqkvt = (__nv_bfloat16*)p;
    cudaGetSymbolAddress(&p, g_wot);   wot   = (__nv_bfloat16*)p;
    cudaGetSymbolAddress(&p, g_sw12t); sw12t = (__nv_bfloat16*)p;
    cudaGetSymbolAddress(&p, g_sw3t);  sw3t  = (__nv_bfloat16*)p;
    cudaGetSymbolAddress(&p, g_ew12t); ew12t = (__nv_bfloat16*)p;
    cudaGetSymbolAddress(&p, g_ew3t);  ew3t  = (__nv_bfloat16*)p;

    static bool s_init = false;
    if (!s_init) {
        cudaFuncSetAttribute(gemm_mma, cudaFuncAttributeMaxDynamicSharedMemorySize, GEMM_SMEM);
        cudaFuncSetAttribute(gemm_mma_add, cudaFuncAttributeMaxDynamicSharedMemorySize, GEMM_SMEM);
        cudaFuncSetAttribute(gemm_swiglu, cudaFuncAttributeMaxDynamicSharedMemorySize, GEMM_SMEM);
        cudaFuncSetAttribute(gemm_moe, cudaFuncAttributeMaxDynamicSharedMemorySize, GEMM_SMEM);
        cudaFuncSetAttribute(gemm_moe_swiglu, cudaFuncAttributeMaxDynamicSharedMemorySize, GEMM_SMEM);
        s_init = true;
    }

    dim3 cb(256);
    // weight conversions (all on main stream, upfront)
    wconv2<<<dim3(CC/64,  CC/64, 1), cb>>>(wq,  wqkvt, CC, CC, 0, 0, 1, 0);
    wconv2<<<dim3(KVH*DH/64, CC/64, 1), cb>>>(wk, wqkvt + (size_t)CC*CC, CC, KVH*DH, 0, 0, 1, 0);
    wconv2<<<dim3(KVH*DH/64, CC/64, 1), cb>>>(wv, wqkvt + (size_t)(CC+KVH*DH)*CC, CC, KVH*DH, 0, 0, 1, 0);
    wconv2<<<dim3(CC/64,  CC/64, 1), cb>>>(wo,  wot,  CC, CC, 0, 0, 1, 0);
    wconv2<<<dim3(FF/64,  CC/64, 1), cb>>>(sw1, sw12t, CC, FF, 0, 0, 2, 0);
    wconv2<<<dim3(FF/64,  CC/64, 1), cb>>>(sw2, sw12t, CC, FF, 0, 0, 2, 1);
    wconv2<<<dim3(CC/64,  FF/64, 1), cb>>>(sw3, sw3t, FF, CC, 0, 0, 1, 0);
    wconv2<<<dim3(FF/64,  CC/64, EE), cb>>>(ew1, ew12t, CC, FF, (long)CC*FF, (long)2*FF*CC, 2, 0);
    wconv2<<<dim3(FF/64,  CC/64, EE), cb>>>(ew2, ew12t, CC, FF, (long)CC*FF, (long)2*FF*CC, 2, 1);
    wconv2<<<dim3(CC/64,  FF/64, EE), cb>>>(ew3, ew3t, FF, CC, (long)FF*CC, (long)CC*FF, 1, 0);

    // 1) pre-attn norm
    rmsnorm_kernel<<<NTOK, 256>>>(x, ln1, nullptr, xnb);
    // 2) fused QKV projection
    gemm_mma<<<dim3(QKVN/128, NTOK/128), 256, GEMM_SMEM>>>(xnb, wqkvt, qkv, QKVN, CC);
    // 3) RoPE
    rope_kernel<<<(NTOK * HH * 32 + 255) / 256, 256>>>(qkv, HH, 0);
    rope_kernel<<<(NTOK * KVH * 32 + 255) / 256, 256>>>(qkv, KVH, CC);
    // 4) attention (tensor core, 128-row Q tiles)
    attn_mma<<<dim3(TT/128, HH, BB), 256>>>(qkv, aob);
    // 5) output projection with fused ReZero residual
    gemm_mma_add<<<dim3(CC/128, NTOK/128), 256, GEMM_SMEM>>>(aob, wot, x, a_attn, h, CC, CC);
    // 6) post-attn norm
    rmsnorm_kernel<<<NTOK, 256>>>(h, ln2, xf, xfb);
    // 7) routing + aux + compaction
    route_kernel<<<NTOK / 4, 128>>>(xf, gatew);
    aux_kernel<<<1, 256>>>();
    zero_cnt_kernel<<<1, 32>>>();
    count_kernel<<<(NTOK + 255) / 256, 256>>>();
    offsets_kernel<<<1, 32>>>();
    assign_kernel<<<(NTOK + 255) / 256, 256>>>();
    // 8) shared expert: fused w12+SwiGLU, then w3
    gemm_swiglu<<<dim3(2*FF/128, NTOK/128), 256, GEMM_SMEM>>>(xfb, sw12t, g1b, 2*FF, CC);
    gemm_mma<<<dim3(CC/128, NTOK/128), 256, GEMM_SMEM>>>(g1b, sw3t, moe, CC, FF);
    // 9) routed experts, batched
    gather_all_kernel<<<ECAP, 128>>>(xgb, xfb);
    gemm_moe_swiglu<<<dim3(2*FF/128, ECAP/128), 256, GEMM_SMEM>>>(xgb, ew12t, g1b, 2*FF, CC, (long)2*FF*CC);
    gemm_moe<<<dim3(CC/128, ECAP/128), 256, GEMM_SMEM>>>(g1b, ew3t, eo, CC, FF, (long)CC*FF);
    // 10) final combine + aux scalar
    final_kernel<<<NTOK, 256>>>(h, moe, eo, a_moe, out);
    if (out_size > OUT_MAIN) auxwrite_kernel<<<1, 1>>>(out);
}

// round 9
// speedup vs baseline: 1.0792x; 1.0792x over previous
#include <cuda_runtime.h>
#include <cuda_bf16.h>
#include <math.h>
#include <stdint.h>

// Problem constants
#define BB   2
#define TT   2048
#define CC   1024
#define HH   16
#define KVH  4
#define DH   64
#define NREP 4
#define FF   4096
#define EE   8
#define TOPK 2
#define WIN  1024
#define NTOK (BB*TT)            // 4096
#define OUT_MAIN (NTOK*CC)      // 4194304
#define QKVN (CC + 2*KVH*DH)    // 1536
#define KVW  (KVH*DH)           // 256
#define ECAP 9216               // 8192 real rows + padding, 128-aligned

// ---------------- scratch (device globals; no allocation) ----------------
__device__ float g_qkv [NTOK*QKVN];
__device__ float g_h   [NTOK*CC];
__device__ float g_xf  [NTOK*CC];
__device__ float g_moe [NTOK*CC];
__device__ float g_eo  [(size_t)ECAP*CC];
__device__ float g_probs[NTOK*EE];
__device__ float g_lse2[NTOK];
__device__ int   g_sel [NTOK*2];
__device__ float g_selw[NTOK*2];
__device__ int   g_cnt [EE];
__device__ int   g_cnt2[EE];
__device__ int   g_off [EE+1];
__device__ int   g_idx [ECAP];
__device__ int   g_tokrow[NTOK*2];
__device__ float g_aux;

// bf16 activations
__device__ __nv_bfloat16 g_xnb [NTOK*CC];
__device__ __nv_bfloat16 g_aob [NTOK*CC];
__device__ __nv_bfloat16 g_xfb [NTOK*CC];
__device__ __nv_bfloat16 g_xgb [(size_t)ECAP*CC];
__device__ __nv_bfloat16 g_g1b [(size_t)ECAP*FF];
__device__ __nv_bfloat16 g_kb  [NTOK*KVW];
__device__ __nv_bfloat16 g_vb  [NTOK*KVW];

// bf16 transposed weights [N,K] (w12 interleaved: w1->2f, w2->2f+1)
__device__ __nv_bfloat16 g_wqkvt[QKVN*CC];
__device__ __nv_bfloat16 g_wot  [CC*CC];
__device__ __nv_bfloat16 g_sw12t[2*FF*CC];
__device__ __nv_bfloat16 g_sw3t [CC*FF];
__device__ __nv_bfloat16 g_ew12t[(size_t)EE*2*FF*CC];
__device__ __nv_bfloat16 g_ew3t [(size_t)EE*CC*FF];

__device__ __forceinline__ uint32_t su32(const void* p) {
    uint32_t a;
    asm("{ .reg .u64 t; cvta.to.shared.u64 t, %1; cvt.u32.u64 %0, t; }" : "=r"(a) : "l"(p));
    return a;
}
__device__ __forceinline__ uint32_t packbf(float a, float b) {
    __nv_bfloat162 t = __floats2bfloat162_rn(a, b);
    return *(uint32_t*)&t;
}

#define CP_ASYNC16(d, s) asm volatile("cp.async.cg.shared.global [%0], [%1], 16;" :: "r"(d), "l"(s))
#define CP_COMMIT()      asm volatile("cp.async.commit_group;" ::: "memory")
#define CP_WAIT(n)       asm volatile("cp.async.wait_group %0;" :: "n"(n) : "memory")

#define BM 128
#define BN 128
#define BK 32
#define ASTR 40   // padded row stride in bf16 elems

// ================= 2-stage GEMM mainloop (static smem, R6 config) ========
#define GEMM_MAIN(A_, Bt_, K_)                                                 \
    __shared__ __align__(16) __nv_bfloat16 sA[2][BM * ASTR];                   \
    __shared__ __align__(16) __nv_bfloat16 sB[2][BM * ASTR];                   \
    int tid = threadIdx.x;                                                     \
    int wid = tid >> 5, lane = tid & 31;                                       \
    int wm = wid >> 2, wn = wid & 3;                                           \
    float cr[4][4][4];                                                         \
    _Pragma("unroll") for (int i = 0; i < 4; i++)                              \
    _Pragma("unroll") for (int j = 0; j < 4; j++)                              \
    _Pragma("unroll") for (int r = 0; r < 4; r++) cr[i][j][r] = 0.f;           \
    int lrow = tid >> 1;                                                       \
    int lc16 = (tid & 1) * 16;                                                 \
    int nCh = (K_) / BK;                                                       \
    {                                                                          \
        const __nv_bfloat16* srcA0 = (A_) + (size_t)(rowBase + lrow) * (K_) + lc16; \
        const __nv_bfloat16* srcB0 = (Bt_) + (size_t)(colBase + lrow) * (K_) + lc16; \
        uint32_t dA0 = su32(&sA[0][lrow * ASTR + lc16]);                       \
        uint32_t dB0 = su32(&sB[0][lrow * ASTR + lc16]);                       \
        CP_ASYNC16(dA0, srcA0); CP_ASYNC16(dA0 + 16, srcA0 + 8);               \
        CP_ASYNC16(dB0, srcB0); CP_ASYNC16(dB0 + 16, srcB0 + 8);               \
        CP_COMMIT();                                                           \
    }                                                                          \
    for (int ch = 0; ch < nCh; ch++) {                                         \
        int st = ch & 1;                                                       \
        if (ch + 1 < nCh) {                                                    \
            int k0 = (ch + 1) * BK;                                            \
            const __nv_bfloat16* srcA = (A_) + (size_t)(rowBase + lrow) * (K_) + k0 + lc16; \
            const __nv_bfloat16* srcB = (Bt_) + (size_t)(colBase + lrow) * (K_) + k0 + lc16; \
            uint32_t dA = su32(&sA[st ^ 1][lrow * ASTR + lc16]);               \
            uint32_t dB = su32(&sB[st ^ 1][lrow * ASTR + lc16]);               \
            CP_ASYNC16(dA, srcA); CP_ASYNC16(dA + 16, srcA + 8);               \
            CP_ASYNC16(dB, srcB); CP_ASYNC16(dB + 16, srcB + 8);               \
            CP_COMMIT(); CP_WAIT(1);                                           \
        } else { CP_WAIT(0); }                                                 \
        __syncthreads();                                                       \
        int r16 = lane & 15, kh = lane >> 4;                                   \
        int rn = lane & 7, knh = (lane >> 3) & 1;                              \
        _Pragma("unroll") for (int kk = 0; kk < 2; kk++) {                     \
            uint32_t af[4][4];                                                 \
            _Pragma("unroll") for (int mf = 0; mf < 4; mf++) {                 \
                uint32_t ad = su32(&sA[st][(wm * 64 + mf * 16 + r16) * ASTR + kk * 16 + kh * 8]); \
                asm volatile("ldmatrix.sync.aligned.m8n8.x4.shared.b16 {%0,%1,%2,%3}, [%4];" \
                    : "=r"(af[mf][0]), "=r"(af[mf][1]), "=r"(af[mf][2]), "=r"(af[mf][3]) : "r"(ad)); \
            }                                                                  \
            uint32_t bfr[4][2];                                                \
            _Pragma("unroll") for (int nf = 0; nf < 4; nf++) {                 \
                uint32_t bd = su32(&sB[st][(wn * 32 + nf * 8 + rn) * ASTR + kk * 16 + knh * 8]); \
                asm volatile("ldmatrix.sync.aligned.m8n8.x2.shared.b16 {%0,%1}, [%2];" \
                    : "=r"(bfr[nf][0]), "=r"(bfr[nf][1]) : "r"(bd));           \
            }                                                                  \
            _Pragma("unroll") for (int mf = 0; mf < 4; mf++)                   \
            _Pragma("unroll") for (int nf = 0; nf < 4; nf++) {                 \
                asm volatile(                                                  \
                    "mma.sync.aligned.m16n8k16.row.col.f32.bf16.bf16.f32 "     \
                    "{%0,%1,%2,%3}, {%4,%5,%6,%7}, {%8,%9}, {%0,%1,%2,%3};"    \
                    : "+f"(cr[mf][nf][0]), "+f"(cr[mf][nf][1]),                \
                      "+f"(cr[mf][nf][2]), "+f"(cr[mf][nf][3])                 \
                    : "r"(af[mf][0]), "r"(af[mf][1]), "r"(af[mf][2]), "r"(af[mf][3]), \
                      "r"(bfr[nf][0]), "r"(bfr[nf][1]));                       \
            }                                                                  \
        }                                                                      \
        __syncthreads();                                                       \
    }                                                                          \
    int rr = lane >> 2, cq = (lane & 3) * 2;

// ================= dense GEMM, fp32 out =================
__global__ __launch_bounds__(256) void gemm_mma(
    const __nv_bfloat16* __restrict__ A, const __nv_bfloat16* __restrict__ Bt,
    float* __restrict__ C, int N, int K)
{
    int rowBase = blockIdx.y * BM, colBase = blockIdx.x * BN;
    GEMM_MAIN(A, Bt, K)
#pragma unroll
    for (int mf = 0; mf < 4; mf++)
#pragma unroll
        for (int nf = 0; nf < 4; nf++) {
            int row0 = rowBase + wm * 64 + mf * 16 + rr;
            int col = colBase + wn * 32 + nf * 8 + cq;
            *(float2*)&C[(size_t)row0 * N + col] = make_float2(cr[mf][nf][0], cr[mf][nf][1]);
            *(float2*)&C[(size_t)(row0 + 8) * N + col] = make_float2(cr[mf][nf][2], cr[mf][nf][3]);
        }
}

// ===== dense GEMM with fused ReZero residual: C = X + (*alpha)*(A@Bt) ====
__global__ __launch_bounds__(256) void gemm_mma_add(
    const __nv_bfloat16* __restrict__ A, const __nv_bfloat16* __restrict__ Bt,
    const float* __restrict__ X, const float* __restrict__ alpha,
    float* __restrict__ C, int N, int K)
{
    int rowBase = blockIdx.y * BM, colBase = blockIdx.x * BN;
    GEMM_MAIN(A, Bt, K)
    float a = *alpha;
#pragma unroll
    for (int mf = 0; mf < 4; mf++)
#pragma unroll
        for (int nf = 0; nf < 4; nf++) {
            int row0 = rowBase + wm * 64 + mf * 16 + rr;
            int col = colBase + wn * 32 + nf * 8 + cq;
            float2 x0 = *(const float2*)&X[(size_t)row0 * N + col];
            float2 x1 = *(const float2*)&X[(size_t)(row0 + 8) * N + col];
            *(float2*)&C[(size_t)row0 * N + col] =
                make_float2(x0.x + a * cr[mf][nf][0], x0.y + a * cr[mf][nf][1]);
            *(float2*)&C[(size_t)(row0 + 8) * N + col] =
                make_float2(x1.x + a * cr[mf][nf][2], x1.y + a * cr[mf][nf][3]);
        }
}

// ================= dense GEMM, fused SwiGLU bf16 out (interleaved w12) ===
__global__ __launch_bounds__(256) void gemm_swiglu(
    const __nv_bfloat16* __restrict__ A, const __nv_bfloat16* __restrict__ Bt,
    __nv_bfloat16* __restrict__ Obf, int N2, int K)
{
    int rowBase = blockIdx.y * BM, colBase = blockIdx.x * BN;
    GEMM_MAIN(A, Bt, K)
    int FFo = N2 >> 1;
#pragma unroll
    for (int mf = 0; mf < 4; mf++)
#pragma unroll
        for (int nf = 0; nf < 4; nf++) {
            int row0 = rowBase + wm * 64 + mf * 16 + rr;
            int f = (colBase + wn * 32 + nf * 8 + cq) >> 1;
            float a0 = cr[mf][nf][0], b0 = cr[mf][nf][1];
            Obf[(size_t)row0 * FFo + f] = __float2bfloat16(a0 / (1.f + __expf(-a0)) * b0);
            float a1 = cr[mf][nf][2], b1 = cr[mf][nf][3];
            Obf[(size_t)(row0 + 8) * FFo + f] = __float2bfloat16(a1 / (1.f + __expf(-a1)) * b1);
        }
}

// ================= MoE GEMM, fp32 out =================
__global__ __launch_bounds__(256) void gemm_moe(
    const __nv_bfloat16* __restrict__ A, const __nv_bfloat16* __restrict__ Wb,
    float* __restrict__ C, int N, int K, long wstride)
{
    int rowBase = blockIdx.y * BM;
    if (rowBase >= g_off[EE]) return;
    int colBase = blockIdx.x * BN;
    int e = 0;
    while (g_off[e + 1] <= rowBase) e++;
    const __nv_bfloat16* Bt = Wb + (size_t)e * wstride;
    GEMM_MAIN(A, Bt, K)
#pragma unroll
    for (int mf = 0; mf < 4; mf++)
#pragma unroll
        for (int nf = 0; nf < 4; nf++) {
            int row0 = rowBase + wm * 64 + mf * 16 + rr;
            int col = colBase + wn * 32 + nf * 8 + cq;
            *(float2*)&C[(size_t)row0 * N + col] = make_float2(cr[mf][nf][0], cr[mf][nf][1]);
            *(float2*)&C[(size_t)(row0 + 8) * N + col] = make_float2(cr[mf][nf][2], cr[mf][nf][3]);
        }
}

// ================= MoE GEMM, fused SwiGLU bf16 out =================
__global__ __launch_bounds__(256) void gemm_moe_swiglu(
    const __nv_bfloat16* __restrict__ A, const __nv_bfloat16* __restrict__ Wb,
    __nv_bfloat16* __restrict__ Obf, int N2, int K, long wstride)
{
    int rowBase = blockIdx.y * BM;
    if (rowBase >= g_off[EE]) return;
    int colBase = blockIdx.x * BN;
    int e = 0;
    while (g_off[e + 1] <= rowBase) e++;
    const __nv_bfloat16* Bt = Wb + (size_t)e * wstride;
    GEMM_MAIN(A, Bt, K)
    int FFo = N2 >> 1;
#pragma unroll
    for (int mf = 0; mf < 4; mf++)
#pragma unroll
        for (int nf = 0; nf < 4; nf++) {
            int row0 = rowBase + wm * 64 + mf * 16 + rr;
            int f = (colBase + wn * 32 + nf * 8 + cq) >> 1;
            float a0 = cr[mf][nf][0], b0 = cr[mf][nf][1];
            Obf[(size_t)row0 * FFo + f] = __float2bfloat16(a0 / (1.f + __expf(-a0)) * b0);
            float a1 = cr[mf][nf][2], b1 = cr[mf][nf][3];
            Obf[(size_t)(row0 + 8) * FFo + f] = __float2bfloat16(a1 / (1.f + __expf(-a1)) * b1);
        }
}

// ---------------- weight transpose+convert with row interleave ----------
__global__ void wconv2(const float* __restrict__ W, __nv_bfloat16* __restrict__ Wt,
                       int K, int N, long sstride, long dstride, int rs, int ro) {
    __shared__ float t[64][65];
    const float* Wz = W + (size_t)blockIdx.z * sstride;
    __nv_bfloat16* Wtz = Wt + (size_t)blockIdx.z * dstride;
    int n0 = blockIdx.x * 64, k0 = blockIdx.y * 64;
    int tid = threadIdx.x;
    int rrw = tid >> 4;
    int c4 = (tid & 15) * 4;
#pragma unroll
    for (int r = 0; r < 64; r += 16) {
        float4 v = *(const float4*)&Wz[(size_t)(k0 + r + rrw) * N + n0 + c4];
        t[r + rrw][c4 + 0] = v.x; t[r + rrw][c4 + 1] = v.y;
        t[r + rrw][c4 + 2] = v.z; t[r + rrw][c4 + 3] = v.w;
    }
    __syncthreads();
    int nl = tid >> 3;
    int c8 = (tid & 7) * 8;
#pragma unroll
    for (int r = 0; r < 64; r += 32) {
        int n = nl + r;
        __nv_bfloat16 o[8];
#pragma unroll
        for (int j = 0; j < 8; j++) o[j] = __float2bfloat16(t[c8 + j][n]);
        *(uint4*)&Wtz[((size_t)(n0 + n) * rs + ro) * K + k0 + c8] = *(uint4*)o;
    }
}

// ---------------- RMSNorm (dual output) ----------------
__global__ void rmsnorm_kernel(const float* __restrict__ x,
                               const float* __restrict__ w,
                               float* __restrict__ of,
                               __nv_bfloat16* __restrict__ ob) {
    int row = blockIdx.x;
    int tid = threadIdx.x;
    const float* xr = x + (size_t)row * CC;
    float s = 0.f;
    for (int i = tid; i < CC; i += 256) { float v = xr[i]; s += v * v; }
    __shared__ float red[256];
    red[tid] = s; __syncthreads();
    for (int o2 = 128; o2 > 0; o2 >>= 1) {
        if (tid < o2) red[tid] += red[tid + o2];
        __syncthreads();
    }
    float scale = rsqrtf(red[0] / (float)CC + 1e-6f);
    for (int i = tid; i < CC; i += 256) {
        float v = xr[i] * scale * w[i];
        if (of) of[(size_t)row * CC + i] = v;
        ob[(size_t)row * CC + i] = __float2bfloat16(v);
    }
}

// ---------------- RoPE (in place in qkv buffer) --------------------------
__global__ void rope_kernel(float* __restrict__ X, int nheads, int hoff) {
    int i = blockIdx.x * blockDim.x + threadIdx.x;
    int total = NTOK * nheads * 32;
    if (i >= total) return;
    int p = i & 31;
    int tmp = i >> 5;
    int hh = tmp % nheads;
    int row = tmp / nheads;
    int t = row % TT;
    float invf = expf(-(float)p * (logf(10000.f) / 32.f));
    float ang = (float)t * invf;
    float cs = cosf(ang), sn = sinf(ang);
    size_t base = (size_t)row * QKVN + hoff + hh * 64;
    float a = X[base + p];
    float b = X[base + p + 32];
    X[base + p]      = a * cs - b * sn;
    X[base + p + 32] = b * cs + a * sn;
}

// ---------------- K/V fp32 -> bf16 compact (post-RoPE) -------------------
__global__ void kv2bf_kernel(const float* __restrict__ QKV,
                             __nv_bfloat16* __restrict__ Kb,
                             __nv_bfloat16* __restrict__ Vb) {
    int i = blockIdx.x * blockDim.x + threadIdx.x;   // one per 2 elems
    int total = NTOK * KVW / 2;
    if (i >= total) return;
    int row = i >> 7;            // KVW/2 = 128
    int p2 = (i & 127) * 2;
    const float* base = QKV + (size_t)row * QKVN + CC;
    *(__nv_bfloat162*)&Kb[(size_t)row * KVW + p2] =
        __floats2bfloat162_rn(base[p2], base[p2 + 1]);
    *(__nv_bfloat162*)&Vb[(size_t)row * KVW + p2] =
        __floats2bfloat162_rn(base[KVW + p2], base[KVW + p2 + 1]);
}

// ---------------- flash attention: 64-row Q tiles, mma.sync, bf16 K/V ----
// grid (TT/64, HH, BB), 128 threads (4 warps, 16 q rows each)
__global__ __launch_bounds__(128) void attn_mma(const float* __restrict__ QKV,
                                                const __nv_bfloat16* __restrict__ Kb,
                                                const __nv_bfloat16* __restrict__ Vb,
                                                __nv_bfloat16* __restrict__ O) {
    int qb = blockIdx.x, h = blockIdx.y, b = blockIdx.z;
    int tid = threadIdx.x;
    int wid = tid >> 5, lane = tid & 31;
    int kvh = h / NREP;

    __shared__ __align__(16) __nv_bfloat16 Qs[64 * 72];
    __shared__ __align__(16) __nv_bfloat16 Ks[64 * 72];
    __shared__ __align__(16) __nv_bfloat16 Vt[64 * 72];

    for (int i = tid; i < 64 * 32; i += 128) {
        int row = i >> 5, p2 = i & 31;
        const float* src = QKV + ((size_t)(b * TT + qb * 64 + row)) * QKVN + h * DH + p2 * 2;
        *(__nv_bfloat162*)&Qs[row * 72 + p2 * 2] =
            __floats2bfloat162_rn(src[0] * 0.125f, src[1] * 0.125f);
    }
    __syncthreads();

    int r16 = lane & 15, kh = lane >> 4;
    int rn = lane & 7, knh = (lane >> 3) & 1;
    uint32_t qf[4][4];
#pragma unroll
    for (int kk = 0; kk < 4; kk++) {
        uint32_t ad = su32(&Qs[(wid * 16 + r16) * 72 + kk * 16 + kh * 8]);
        asm volatile("ldmatrix.sync.aligned.m8n8.x4.shared.b16 {%0,%1,%2,%3}, [%4];"
            : "=r"(qf[kk][0]), "=r"(qf[kk][1]), "=r"(qf[kk][2]), "=r"(qf[kk][3]) : "r"(ad));
    }

    int rr = lane >> 2, cq = (lane & 3) * 2;
    int t0 = qb * 64 + wid * 16 + rr;   // second row = t0+8
    float m0 = -1e30f, m1 = -1e30f, l0 = 0.f, l1 = 0.f;
    float acc[8][4];
#pragma unroll
    for (int dn = 0; dn < 8; dn++)
#pragma unroll
        for (int r = 0; r < 4; r++) acc[dn][r] = 0.f;

    int kstart = qb * 64 - WIN; if (kstart < 0) kstart = 0;
    for (int k0 = kstart; k0 <= qb * 64; k0 += 64) {
        __syncthreads();
        for (int i = tid; i < 64 * 32; i += 128) {
            int row = i >> 5, p2 = (i & 31) * 2;
            size_t kr = ((size_t)(b * TT + k0 + row)) * KVW + kvh * DH;
            *(__nv_bfloat162*)&Ks[row * 72 + p2] = *(const __nv_bfloat162*)&Kb[kr + p2];
            __nv_bfloat162 vv = *(const __nv_bfloat162*)&Vb[kr + p2];
            Vt[p2 * 72 + row]       = vv.x;
            Vt[(p2 + 1) * 72 + row] = vv.y;
        }
        __syncthreads();

        float s[8][4];
#pragma unroll
        for (int j = 0; j < 8; j++) {
            s[j][0] = s[j][1] = s[j][2] = s[j][3] = 0.f;
#pragma unroll
            for (int kk = 0; kk < 4; kk++) {
                uint32_t bfr[2];
                uint32_t bd = su32(&Ks[(j * 8 + rn) * 72 + kk * 16 + knh * 8]);
                asm volatile("ldmatrix.sync.aligned.m8n8.x2.shared.b16 {%0,%1}, [%2];"
                    : "=r"(bfr[0]), "=r"(bfr[1]) : "r"(bd));
                asm volatile(
                    "mma.sync.aligned.m16n8k16.row.col.f32.bf16.bf16.f32 "
                    "{%0,%1,%2,%3}, {%4,%5,%6,%7}, {%8,%9}, {%0,%1,%2,%3};"
                    : "+f"(s[j][0]), "+f"(s[j][1]), "+f"(s[j][2]), "+f"(s[j][3])
                    : "r"(qf[kk][0]), "r"(qf[kk][1]), "r"(qf[kk][2]), "r"(qf[kk][3]),
                      "r"(bfr[0]), "r"(bfr[1]));
            }
        }
#pragma unroll
        for (int j = 0; j < 8; j++) {
            int kg = k0 + j * 8 + cq;
            if (kg > t0 || kg < t0 - WIN) s[j][0] = -1e30f;
            if (kg + 1 > t0 || kg + 1 < t0 - WIN) s[j][1] = -1e30f;
            if (kg > t0 + 8 || kg < t0 + 8 - WIN) s[j][2] = -1e30f;
            if (kg + 1 > t0 + 8 || kg + 1 < t0 + 8 - WIN) s[j][3] = -1e30f;
        }
        float mx0 = -1e30f, mx1 = -1e30f;
#pragma unroll
        for (int j = 0; j < 8; j++) {
            mx0 = fmaxf(mx0, fmaxf(s[j][0], s[j][1]));
            mx1 = fmaxf(mx1, fmaxf(s[j][2], s[j][3]));
        }
        mx0 = fmaxf(mx0, __shfl_xor_sync(0xffffffffu, mx0, 1));
        mx0 = fmaxf(mx0, __shfl_xor_sync(0xffffffffu, mx0, 2));
        mx1 = fmaxf(mx1, __shfl_xor_sync(0xffffffffu, mx1, 1));
        mx1 = fmaxf(mx1, __shfl_xor_sync(0xffffffffu, mx1, 2));
        float mn0 = fmaxf(m0, mx0), mn1 = fmaxf(m1, mx1);
        float c0 = __expf(m0 - mn0), c1 = __expf(m1 - mn1);
        m0 = mn0; m1 = mn1;
        l0 *= c0; l1 *= c1;
#pragma unroll
        for (int dn = 0; dn < 8; dn++) {
            acc[dn][0] *= c0; acc[dn][1] *= c0;
            acc[dn][2] *= c1; acc[dn][3] *= c1;
        }
#pragma unroll
        for (int j = 0; j < 8; j++) {
            s[j][0] = __expf(s[j][0] - m0); s[j][1] = __expf(s[j][1] - m0);
            s[j][2] = __expf(s[j][2] - m1); s[j][3] = __expf(s[j][3] - m1);
            l0 += s[j][0] + s[j][1];
            l1 += s[j][2] + s[j][3];
        }
        uint32_t pa[4][4];
#pragma unroll
        for (int kk = 0; kk < 4; kk++) {
            int j0 = kk * 2, j1 = kk * 2 + 1;
            pa[kk][0] = packbf(s[j0][0], s[j0][1]);
            pa[kk][1] = packbf(s[j0][2], s[j0][3]);
            pa[kk][2] = packbf(s[j1][0], s[j1][1]);
            pa[kk][3] = packbf(s[j1][2], s[j1][3]);
        }
#pragma unroll
        for (int dn = 0; dn < 8; dn++)
#pragma unroll
            for (int kk = 0; kk < 4; kk++) {
                uint32_t bfr[2];
                uint32_t bd = su32(&Vt[(dn * 8 + rn) * 72 + kk * 16 + knh * 8]);
                asm volatile("ldmatrix.sync.aligned.m8n8.x2.shared.b16 {%0,%1}, [%2];"
                    : "=r"(bfr[0]), "=r"(bfr[1]) : "r"(bd));
                asm volatile(
                    "mma.sync.aligned.m16n8k16.row.col.f32.bf16.bf16.f32 "
                    "{%0,%1,%2,%3}, {%4,%5,%6,%7}, {%8,%9}, {%0,%1,%2,%3};"
                    : "+f"(acc[dn][0]), "+f"(acc[dn][1]), "+f"(acc[dn][2]), "+f"(acc[dn][3])
                    : "r"(pa[kk][0]), "r"(pa[kk][1]), "r"(pa[kk][2]), "r"(pa[kk][3]),
                      "r"(bfr[0]), "r"(bfr[1]));
            }
    }
    l0 += __shfl_xor_sync(0xffffffffu, l0, 1);
    l0 += __shfl_xor_sync(0xffffffffu, l0, 2);
    l1 += __shfl_xor_sync(0xffffffffu, l1, 1);
    l1 += __shfl_xor_sync(0xffffffffu, l1, 2);
    float i0 = 1.f / l0, i1 = 1.f / l1;
    __nv_bfloat16* o0 = O + ((size_t)(b * TT + t0)) * CC + h * DH;
    __nv_bfloat16* o1 = o0 + (size_t)8 * CC;
#pragma unroll
    for (int dn = 0; dn < 8; dn++) {
        *(__nv_bfloat162*)&o0[dn * 8 + cq] =
            __floats2bfloat162_rn(acc[dn][0] * i0, acc[dn][1] * i0);
        *(__nv_bfloat162*)&o1[dn * 8 + cq] =
            __floats2bfloat162_rn(acc[dn][2] * i1, acc[dn][3] * i1);
    }
}

// ---------------- router ----------------
__global__ void route_kernel(const float* __restrict__ xf,
                             const float* __restrict__ gw) {
    int warp = threadIdx.x >> 5, lane = threadIdx.x & 31;
    int tok = blockIdx.x * 4 + warp;
    if (tok >= NTOK) return;
    const float* xr = xf + (size_t)tok * CC;
    float part[EE];
#pragma unroll
    for (int e = 0; e < EE; e++) part[e] = 0.f;
    for (int d = lane; d < CC; d += 32) {
        float xv = xr[d];
#pragma unroll
        for (int e = 0; e < EE; e++) part[e] += xv * gw[d * EE + e];
    }
#pragma unroll
    for (int e = 0; e < EE; e++)
#pragma unroll
        for (int o = 16; o > 0; o >>= 1)
            part[e] += __shfl_xor_sync(0xffffffffu, part[e], o);
    if (lane == 0) {
        float v0 = -1e30f; int i0 = 0;
#pragma unroll
        for (int e = 0; e < EE; e++) if (part[e] > v0) { v0 = part[e]; i0 = e; }
        float v1 = -1e30f; int i1 = 0;
#pragma unroll
        for (int e = 0; e < EE; e++)
            if (e != i0 && part[e] > v1) { v1 = part[e]; i1 = e; }
        float ex = expf(v1 - v0);
        float w0 = 1.f / (1.f + ex);
        float w1 = ex / (1.f + ex);
        g_sel[tok * 2] = i0; g_sel[tok * 2 + 1] = i1;
        g_selw[tok * 2] = w0; g_selw[tok * 2 + 1] = w1;
        float mx = v0, sum = 0.f, pe[EE];
#pragma unroll
        for (int e = 0; e < EE; e++) { pe[e] = expf(part[e] - mx); sum += pe[e]; }
#pragma unroll
        for (int e = 0; e < EE; e++) g_probs[tok * EE + e] = pe[e] / sum;
        float lse = mx + logf(sum);
        g_lse2[tok] = lse * lse;
    }
}

// ---------------- aux loss ----------------
__global__ void aux_kernel() {
    __shared__ float red[256];
    int tid = threadIdx.x;
    float loadv[EE];
#pragma unroll
    for (int e = 0; e < EE; e++) loadv[e] = 0.f;
    for (int n = tid; n < NTOK; n += 256) {
#pragma unroll
        for (int e = 0; e < EE; e++) loadv[e] += g_probs[n * EE + e];
    }
    float loads[EE];
    for (int e = 0; e < EE; e++) {
        red[tid] = loadv[e]; __syncthreads();
        for (int o = 128; o > 0; o >>= 1) {
            if (tid < o) red[tid] += red[tid + o];
            __syncthreads();
        }
        loads[e] = red[0]; __syncthreads();
    }
    float zp = 0.f;
    for (int n = tid; n < NTOK; n += 256) zp += g_lse2[n];
    red[tid] = zp; __syncthreads();
    for (int o = 128; o > 0; o >>= 1) {
        if (tid < o) red[tid] += red[tid + o];
        __syncthreads();
    }
    if (tid == 0) {
        float tot = 0.f;
        for (int e = 0; e < EE; e++) tot += loads[e];
        float lb = 0.f;
        for (int e = 0; e < EE; e++) { float f = loads[e] / tot; lb += f * f; }
        lb *= (float)EE;
        float z = red[0] / (float)NTOK;
        g_aux = 0.01f * lb + 0.001f * z;
    }
}

__global__ void zero_cnt_kernel() { if (threadIdx.x < EE) g_cnt[threadIdx.x] = 0; }

__global__ void count_kernel() {
    int i = blockIdx.x * blockDim.x + threadIdx.x;
    if (i >= NTOK) return;
#pragma unroll
    for (int kk = 0; kk < TOPK; kk++)
        atomicAdd(&g_cnt[g_sel[i * 2 + kk]], 1);
}

__global__ void offsets_kernel() {
    if (threadIdx.x == 0) {
        int acc = 0;
        for (int e = 0; e < EE; e++) {
            g_off[e] = acc;
            acc += (g_cnt[e] + BM - 1) & ~(BM - 1);
            g_cnt2[e] = 0;
        }
        g_off[EE] = acc;
    }
}

__global__ void assign_kernel() {
    int i = blockIdx.x * blockDim.x + threadIdx.x;
    if (i >= NTOK) return;
#pragma unroll
    for (int kk = 0; kk < TOPK; kk++) {
        int e = g_sel[i * 2 + kk];
        int pos = atomicAdd(&g_cnt2[e], 1);
        int row = g_off[e] + pos;
        g_idx[row] = i;
        g_tokrow[i * 2 + kk] = row;
    }
}

__global__ void gather_all_kernel(__nv_bfloat16* __restrict__ dst,
                                  const __nv_bfloat16* __restrict__ src) {
    int b = blockIdx.x;
    if (b >= g_off[EE]) return;
    int e = 0;
    while (g_off[e + 1] <= b) e++;
    if (b - g_off[e] >= g_cnt[e]) return;
    int t = g_idx[b];
    uint4* d4 = (uint4*)(dst + (size_t)b * CC);
    const uint4* s4 = (const uint4*)(src + (size_t)t * CC);
    int i = threadIdx.x;
    if (i < CC * 2 / 16) d4[i] = s4[i];
}

// final: out = h + a_moe * (shared + w0*eo[r0] + w1*eo[r1])
__global__ void final_kernel(const float* __restrict__ h, const float* __restrict__ moe,
                             const float* __restrict__ eo,
                             const float* __restrict__ alpha, float* __restrict__ out) {
    int t = blockIdx.x;
    float w0 = g_selw[t * 2], w1 = g_selw[t * 2 + 1];
    int r0 = g_tokrow[t * 2], r1 = g_tokrow[t * 2 + 1];
    float a = *alpha;
    const float* hr = h + (size_t)t * CC;
    const float* mr = moe + (size_t)t * CC;
    const float* e0 = eo + (size_t)r0 * CC;
    const float* e1 = eo + (size_t)r1 * CC;
    float* orow = out + (size_t)t * CC;
    for (int i = threadIdx.x; i < CC; i += blockDim.x)
        orow[i] = hr[i] + a * (mr[i] + w0 * e0[i] + w1 * e1[i]);
}

__global__ void auxwrite_kernel(float* __restrict__ out) { out[OUT_MAIN] = g_aux; }

// ---------------- launch ----------------
extern "C" void kernel_launch(void* const* d_in, const int* in_sizes, int n_in,
                              void* d_out, int out_size) {
    const float* x      = (const float*)d_in[0];
    const float* ln1    = (const float*)d_in[1];
    const float* ln2    = (const float*)d_in[2];
    const float* wq     = (const float*)d_in[3];
    const float* wk     = (const float*)d_in[4];
    const float* wv     = (const float*)d_in[5];
    const float* wo     = (const float*)d_in[6];
    const float* sw1    = (const float*)d_in[7];
    const float* sw2    = (const float*)d_in[8];
    const float* sw3    = (const float*)d_in[9];
    const float* ew1    = (const float*)d_in[10];
    const float* ew2    = (const float*)d_in[11];
    const float* ew3    = (const float*)d_in[12];
    const float* gatew  = (const float*)d_in[13];
    const float* a_attn = (const float*)d_in[14];
    const float* a_moe  = (const float*)d_in[15];
    float* out = (float*)d_out;

    void* p;
    float *qkv, *h, *xf, *moe, *eo;
    __nv_bfloat16 *xnb, *aob, *xfb, *xgb, *g1b, *kb, *vb;
    __nv_bfloat16 *wqkvt, *wot, *sw12t, *sw3t, *ew12t, *ew3t;
    cudaGetSymbolAddress(&p, g_qkv);  qkv  = (float*)p;
    cudaGetSymbolAddress(&p, g_h);    h    = (float*)p;
    cudaGetSymbolAddress(&p, g_xf);   xf   = (float*)p;
    cudaGetSymbolAddress(&p, g_moe);  moe  = (float*)p;
    cudaGetSymbolAddress(&p, g_eo);   eo   = (float*)p;
    cudaGetSymbolAddress(&p, g_xnb);  xnb  = (__nv_bfloat16*)p;
    cudaGetSymbolAddress(&p, g_aob);  aob  = (__nv_bfloat16*)p;
    cudaGetSymbolAddress(&p, g_xfb);  xfb  = (__nv_bfloat16*)p;
    cudaGetSymbolAddress(&p, g_xgb);  xgb  = (__nv_bfloat16*)p;
    cudaGetSymbolAddress(&p, g_g1b);  g1b  = (__nv_bfloat16*)p;
    cudaGetSymbolAddress(&p, g_kb);   kb   = (__nv_bfloat16*)p;
    cudaGetSymbolAddress(&p, g_vb);   vb   = (__nv_bfloat16*)p;
    cudaGetSymbolAddress(&p, g_wqkvt); wqkvt = (__nv_bfloat16*)p;
    cudaGetSymbolAddress(&p, g_wot);   wot   = (__nv_bfloat16*)p;
    cudaGetSymbolAddress(&p, g_sw12t); sw12t = (__nv_bfloat16*)p;
    cudaGetSymbolAddress(&p, g_sw3t);  sw3t  = (__nv_bfloat16*)p;
    cudaGetSymbolAddress(&p, g_ew12t); ew12t = (__nv_bfloat16*)p;
    cudaGetSymbolAddress(&p, g_ew3t);  ew3t  = (__nv_bfloat16*)p;

    static bool s_init = false;
    static cudaStream_t s2 = 0;
    static cudaEvent_t evA = 0, evB = 0;
    if (!s_init) {
        if (cudaStreamCreateWithFlags(&s2, cudaStreamNonBlocking) != cudaSuccess) s2 = 0;
        if (s2) {
            if (cudaEventCreateWithFlags(&evA, cudaEventDisableTiming) != cudaSuccess) evA = 0;
            if (cudaEventCreateWithFlags(&evB, cudaEventDisableTiming) != cudaSuccess) evB = 0;
            if (!evA || !evB) s2 = 0;
        }
        s_init = true;
    }

    dim3 cb(256);
    // main-stream conversions (needed early)
    wconv2<<<dim3(CC/64,  CC/64, 1), cb>>>(wq,  wqkvt, CC, CC, 0, 0, 1, 0);
    wconv2<<<dim3(KVH*DH/64, CC/64, 1), cb>>>(wk, wqkvt + (size_t)CC*CC, CC, KVH*DH, 0, 0, 1, 0);
    wconv2<<<dim3(KVH*DH/64, CC/64, 1), cb>>>(wv, wqkvt + (size_t)(CC+KVH*DH)*CC, CC, KVH*DH, 0, 0, 1, 0);
    wconv2<<<dim3(CC/64,  CC/64, 1), cb>>>(wo,  wot,  CC, CC, 0, 0, 1, 0);
    wconv2<<<dim3(FF/64,  CC/64, 1), cb>>>(sw1, sw12t, CC, FF, 0, 0, 2, 0);
    wconv2<<<dim3(FF/64,  CC/64, 1), cb>>>(sw2, sw12t, CC, FF, 0, 0, 2, 1);
    wconv2<<<dim3(CC/64,  FF/64, 1), cb>>>(sw3, sw3t, FF, CC, 0, 0, 1, 0);

    // expert conversions: forked onto s2 (measured small win)
    bool forked = (s2 != 0);
    if (forked) {
        cudaEventRecord(evA, 0);
        cudaStreamWaitEvent(s2, evA, 0);
        wconv2<<<dim3(FF/64, CC/64, EE), cb, 0, s2>>>(ew1, ew12t, CC, FF, (long)CC*FF, (long)2*FF*CC, 2, 0);
        wconv2<<<dim3(FF/64, CC/64, EE), cb, 0, s2>>>(ew2, ew12t, CC, FF, (long)CC*FF, (long)2*FF*CC, 2, 1);
        wconv2<<<dim3(CC/64, FF/64, EE), cb, 0, s2>>>(ew3, ew3t, FF, CC, (long)FF*CC, (long)CC*FF, 1, 0);
        cudaEventRecord(evB, s2);
    } else {
        wconv2<<<dim3(FF/64, CC/64, EE), cb>>>(ew1, ew12t, CC, FF, (long)CC*FF, (long)2*FF*CC, 2, 0);
        wconv2<<<dim3(FF/64, CC/64, EE), cb>>>(ew2, ew12t, CC, FF, (long)CC*FF, (long)2*FF*CC, 2, 1);
        wconv2<<<dim3(CC/64, FF/64, EE), cb>>>(ew3, ew3t, FF, CC, (long)FF*CC, (long)CC*FF, 1, 0);
    }

    // 1) pre-attn norm
    rmsnorm_kernel<<<NTOK, 256>>>(x, ln1, nullptr, xnb);
    // 2) fused QKV projection
    gemm_mma<<<dim3(QKVN/128, NTOK/128), 256>>>(xnb, wqkvt, qkv, QKVN, CC);
    // 3) RoPE + K/V bf16 compaction
    rope_kernel<<<(NTOK * HH * 32 + 255) / 256, 256>>>(qkv, HH, 0);
    rope_kernel<<<(NTOK * KVH * 32 + 255) / 256, 256>>>(qkv, KVH, CC);
    kv2bf_kernel<<<(NTOK * KVW / 2 + 255) / 256, 256>>>(qkv, kb, vb);
    // 4) attention (tensor core, 64-row Q tiles, bf16 K/V)
    attn_mma<<<dim3(TT/64, HH, BB), 128>>>(qkv, kb, vb, aob);
    // 5) output projection with fused ReZero residual
    gemm_mma_add<<<dim3(CC/128, NTOK/128), 256>>>(aob, wot, x, a_attn, h, CC, CC);
    // 6) post-attn norm
    rmsnorm_kernel<<<NTOK, 256>>>(h, ln2, xf, xfb);
    // 7) routing + aux + compaction
    route_kernel<<<NTOK / 4, 128>>>(xf, gatew);
    aux_kernel<<<1, 256>>>();
    zero_cnt_kernel<<<1, 32>>>();
    count_kernel<<<(NTOK + 255) / 256, 256>>>();
    offsets_kernel<<<1, 32>>>();
    assign_kernel<<<(NTOK + 255) / 256, 256>>>();
    // 8) shared expert: fused w12+SwiGLU, then w3
    gemm_swiglu<<<dim3(2*FF/128, NTOK/128), 256>>>(xfb, sw12t, g1b, 2*FF, CC);
    gemm_mma<<<dim3(CC/128, NTOK/128), 256>>>(g1b, sw3t, moe, CC, FF);
    // 9) routed experts, batched (join expert-weight conversion first)
    gather_all_kernel<<<ECAP, 128>>>(xgb, xfb);
    if (forked) cudaStreamWaitEvent(0, evB, 0);
    gemm_moe_swiglu<<<dim3(2*FF/128, ECAP/128), 256>>>(xgb, ew12t, g1b, 2*FF, CC, (long)2*FF*CC);
    gemm_moe<<<dim3(CC/128, ECAP/128), 256>>>(g1b, ew3t, eo, CC, FF, (long)CC*FF);
    // 10) final combine + aux scalar
    final_kernel<<<NTOK, 256>>>(h, moe, eo, a_moe, out);
    if (out_size > OUT_MAIN) auxwrite_kernel<<<1, 1>>>(out);
}

// round 10
// speedup vs baseline: 1.1744x; 1.0882x over previous
#include <cuda_runtime.h>
#include <cuda_bf16.h>
#include <math.h>
#include <stdint.h>

// Problem constants
#define BB   2
#define TT   2048
#define CC   1024
#define HH   16
#define KVH  4
#define DH   64
#define NREP 4
#define FF   4096
#define EE   8
#define TOPK 2
#define WIN  1024
#define NTOK (BB*TT)            // 4096
#define OUT_MAIN (NTOK*CC)      // 4194304
#define QKVN (CC + 2*KVH*DH)    // 1536
#define KVW  (KVH*DH)           // 256
#define ECAP 9216               // 8192 real rows + padding, 128-aligned

// ---------------- scratch (device globals; no allocation) ----------------
__device__ float g_qkv [NTOK*QKVN];
__device__ float g_h   [NTOK*CC];
__device__ float g_xf  [NTOK*CC];
__device__ float g_moe [NTOK*CC];
__device__ float g_eo  [(size_t)ECAP*CC];
__device__ float g_probs[NTOK*EE];
__device__ float g_lse2[NTOK];
__device__ int   g_sel [NTOK*2];
__device__ float g_selw[NTOK*2];
__device__ int   g_cnt [EE];
__device__ int   g_cnt2[EE];
__device__ int   g_off [EE+1];
__device__ int   g_idx [ECAP];
__device__ int   g_tokrow[NTOK*2];
__device__ float g_aux;

// bf16 activations
__device__ __nv_bfloat16 g_xnb [NTOK*CC];
__device__ __nv_bfloat16 g_aob [NTOK*CC];
__device__ __nv_bfloat16 g_xfb [NTOK*CC];
__device__ __nv_bfloat16 g_xgb [(size_t)ECAP*CC];
__device__ __nv_bfloat16 g_g1b [(size_t)ECAP*FF];
__device__ __nv_bfloat16 g_kb  [NTOK*KVW];
__device__ __nv_bfloat16 g_vb  [NTOK*KVW];

// bf16 weights, K-major [K,N] (w12 column-interleaved: w1->2f, w2->2f+1)
__device__ __nv_bfloat16 g_wqkvt[CC*QKVN];
__device__ __nv_bfloat16 g_wot  [CC*CC];
__device__ __nv_bfloat16 g_sw12t[CC*2*FF];
__device__ __nv_bfloat16 g_sw3t [FF*CC];
__device__ __nv_bfloat16 g_ew12t[(size_t)EE*CC*2*FF];
__device__ __nv_bfloat16 g_ew3t [(size_t)EE*FF*CC];

__device__ __forceinline__ uint32_t su32(const void* p) {
    uint32_t a;
    asm("{ .reg .u64 t; cvta.to.shared.u64 t, %1; cvt.u32.u64 %0, t; }" : "=r"(a) : "l"(p));
    return a;
}
__device__ __forceinline__ uint32_t packbf(float a, float b) {
    __nv_bfloat162 t = __floats2bfloat162_rn(a, b);
    return *(uint32_t*)&t;
}

#define CP_ASYNC16(d, s) asm volatile("cp.async.cg.shared.global [%0], [%1], 16;" :: "r"(d), "l"(s))
#define CP_COMMIT()      asm volatile("cp.async.commit_group;" ::: "memory")
#define CP_WAIT(n)       asm volatile("cp.async.wait_group %0;" :: "n"(n) : "memory")

#define BM 128
#define BN 128
#define BK 32
#define ASTR 40    // A smem row stride (bf16 elems)
#define BSTR 136   // B smem row stride (bf16 elems)

// ================= 2-stage GEMM mainloop; B is [K,N] via ldmatrix.trans ==
#define GEMM_MAIN(A_, Bt_, N_, K_)                                             \
    __shared__ __align__(16) __nv_bfloat16 sA[2][BM * ASTR];                   \
    __shared__ __align__(16) __nv_bfloat16 sB[2][BK * BSTR];                   \
    int tid = threadIdx.x;                                                     \
    int wid = tid >> 5, lane = tid & 31;                                       \
    int wm = wid >> 2, wn = wid & 3;                                           \
    float cr[4][4][4];                                                         \
    _Pragma("unroll") for (int i = 0; i < 4; i++)                              \
    _Pragma("unroll") for (int j = 0; j < 4; j++)                              \
    _Pragma("unroll") for (int r = 0; r < 4; r++) cr[i][j][r] = 0.f;           \
    int lrow = tid >> 1;                                                       \
    int lc16 = (tid & 1) * 16;                                                 \
    int nCh = (K_) / BK;                                                       \
    {                                                                          \
        const __nv_bfloat16* srcA0 = (A_) + (size_t)(rowBase + lrow) * (K_) + lc16; \
        uint32_t dA0 = su32(&sA[0][lrow * ASTR + lc16]);                       \
        CP_ASYNC16(dA0, srcA0); CP_ASYNC16(dA0 + 16, srcA0 + 8);               \
        _Pragma("unroll") for (int bi = 0; bi < 2; bi++) {                     \
            int seg = tid + bi * 256;                                          \
            int brow = seg >> 4, bcol = (seg & 15) * 8;                        \
            const __nv_bfloat16* srcB = (Bt_) + (size_t)brow * (N_) + colBase + bcol; \
            CP_ASYNC16(su32(&sB[0][brow * BSTR + bcol]), srcB);                \
        }                                                                      \
        CP_COMMIT();                                                           \
    }                                                                          \
    for (int ch = 0; ch < nCh; ch++) {                                         \
        int st = ch & 1;                                                       \
        if (ch + 1 < nCh) {                                                    \
            int k0 = (ch + 1) * BK;                                            \
            const __nv_bfloat16* srcA = (A_) + (size_t)(rowBase + lrow) * (K_) + k0 + lc16; \
            uint32_t dA = su32(&sA[st ^ 1][lrow * ASTR + lc16]);               \
            CP_ASYNC16(dA, srcA); CP_ASYNC16(dA + 16, srcA + 8);               \
            _Pragma("unroll") for (int bi = 0; bi < 2; bi++) {                 \
                int seg = tid + bi * 256;                                      \
                int brow = seg >> 4, bcol = (seg & 15) * 8;                    \
                const __nv_bfloat16* srcB = (Bt_) + (size_t)(k0 + brow) * (N_) + colBase + bcol; \
                CP_ASYNC16(su32(&sB[st ^ 1][brow * BSTR + bcol]), srcB);       \
            }                                                                  \
            CP_COMMIT(); CP_WAIT(1);                                           \
        } else { CP_WAIT(0); }                                                 \
        __syncthreads();                                                       \
        int r16 = lane & 15, kh = lane >> 4;                                   \
        int rn = lane & 7, knh = (lane >> 3) & 1;                              \
        _Pragma("unroll") for (int kk = 0; kk < 2; kk++) {                     \
            uint32_t af[4][4];                                                 \
            _Pragma("unroll") for (int mf = 0; mf < 4; mf++) {                 \
                uint32_t ad = su32(&sA[st][(wm * 64 + mf * 16 + r16) * ASTR + kk * 16 + kh * 8]); \
                asm volatile("ldmatrix.sync.aligned.m8n8.x4.shared.b16 {%0,%1,%2,%3}, [%4];" \
                    : "=r"(af[mf][0]), "=r"(af[mf][1]), "=r"(af[mf][2]), "=r"(af[mf][3]) : "r"(ad)); \
            }                                                                  \
            uint32_t bfr[4][2];                                                \
            _Pragma("unroll") for (int nf = 0; nf < 4; nf++) {                 \
                uint32_t bd = su32(&sB[st][(kk * 16 + knh * 8 + rn) * BSTR + wn * 32 + nf * 8]); \
                asm volatile("ldmatrix.sync.aligned.m8n8.x2.trans.shared.b16 {%0,%1}, [%2];" \
                    : "=r"(bfr[nf][0]), "=r"(bfr[nf][1]) : "r"(bd));           \
            }                                                                  \
            _Pragma("unroll") for (int mf = 0; mf < 4; mf++)                   \
            _Pragma("unroll") for (int nf = 0; nf < 4; nf++) {                 \
                asm volatile(                                                  \
                    "mma.sync.aligned.m16n8k16.row.col.f32.bf16.bf16.f32 "     \
                    "{%0,%1,%2,%3}, {%4,%5,%6,%7}, {%8,%9}, {%0,%1,%2,%3};"    \
                    : "+f"(cr[mf][nf][0]), "+f"(cr[mf][nf][1]),                \
                      "+f"(cr[mf][nf][2]), "+f"(cr[mf][nf][3])                 \
                    : "r"(af[mf][0]), "r"(af[mf][1]), "r"(af[mf][2]), "r"(af[mf][3]), \
                      "r"(bfr[nf][0]), "r"(bfr[nf][1]));                       \
            }                                                                  \
        }                                                                      \
        __syncthreads();                                                       \
    }                                                                          \
    int rr = lane >> 2, cq = (lane & 3) * 2;

// ================= dense GEMM, fp32 out =================
__global__ __launch_bounds__(256) void gemm_mma(
    const __nv_bfloat16* __restrict__ A, const __nv_bfloat16* __restrict__ Bt,
    float* __restrict__ C, int N, int K)
{
    int rowBase = blockIdx.y * BM, colBase = blockIdx.x * BN;
    GEMM_MAIN(A, Bt, N, K)
#pragma unroll
    for (int mf = 0; mf < 4; mf++)
#pragma unroll
        for (int nf = 0; nf < 4; nf++) {
            int row0 = rowBase + wm * 64 + mf * 16 + rr;
            int col = colBase + wn * 32 + nf * 8 + cq;
            *(float2*)&C[(size_t)row0 * N + col] = make_float2(cr[mf][nf][0], cr[mf][nf][1]);
            *(float2*)&C[(size_t)(row0 + 8) * N + col] = make_float2(cr[mf][nf][2], cr[mf][nf][3]);
        }
}

// ===== dense GEMM with fused ReZero residual: C = X + (*alpha)*(A@Bt) ====
__global__ __launch_bounds__(256) void gemm_mma_add(
    const __nv_bfloat16* __restrict__ A, const __nv_bfloat16* __restrict__ Bt,
    const float* __restrict__ X, const float* __restrict__ alpha,
    float* __restrict__ C, int N, int K)
{
    int rowBase = blockIdx.y * BM, colBase = blockIdx.x * BN;
    GEMM_MAIN(A, Bt, N, K)
    float a = *alpha;
#pragma unroll
    for (int mf = 0; mf < 4; mf++)
#pragma unroll
        for (int nf = 0; nf < 4; nf++) {
            int row0 = rowBase + wm * 64 + mf * 16 + rr;
            int col = colBase + wn * 32 + nf * 8 + cq;
            float2 x0 = *(const float2*)&X[(size_t)row0 * N + col];
            float2 x1 = *(const float2*)&X[(size_t)(row0 + 8) * N + col];
            *(float2*)&C[(size_t)row0 * N + col] =
                make_float2(x0.x + a * cr[mf][nf][0], x0.y + a * cr[mf][nf][1]);
            *(float2*)&C[(size_t)(row0 + 8) * N + col] =
                make_float2(x1.x + a * cr[mf][nf][2], x1.y + a * cr[mf][nf][3]);
        }
}

// ================= dense GEMM, fused SwiGLU bf16 out (interleaved w12) ===
__global__ __launch_bounds__(256) void gemm_swiglu(
    const __nv_bfloat16* __restrict__ A, const __nv_bfloat16* __restrict__ Bt,
    __nv_bfloat16* __restrict__ Obf, int N2, int K)
{
    int rowBase = blockIdx.y * BM, colBase = blockIdx.x * BN;
    GEMM_MAIN(A, Bt, N2, K)
    int FFo = N2 >> 1;
#pragma unroll
    for (int mf = 0; mf < 4; mf++)
#pragma unroll
        for (int nf = 0; nf < 4; nf++) {
            int row0 = rowBase + wm * 64 + mf * 16 + rr;
            int f = (colBase + wn * 32 + nf * 8 + cq) >> 1;
            float a0 = cr[mf][nf][0], b0 = cr[mf][nf][1];
            Obf[(size_t)row0 * FFo + f] = __float2bfloat16(a0 / (1.f + __expf(-a0)) * b0);
            float a1 = cr[mf][nf][2], b1 = cr[mf][nf][3];
            Obf[(size_t)(row0 + 8) * FFo + f] = __float2bfloat16(a1 / (1.f + __expf(-a1)) * b1);
        }
}

// ================= MoE GEMM, fp32 out =================
__global__ __launch_bounds__(256) void gemm_moe(
    const __nv_bfloat16* __restrict__ A, const __nv_bfloat16* __restrict__ Wb,
    float* __restrict__ C, int N, int K, long wstride)
{
    int rowBase = blockIdx.y * BM;
    if (rowBase >= g_off[EE]) return;
    int colBase = blockIdx.x * BN;
    int e = 0;
    while (g_off[e + 1] <= rowBase) e++;
    const __nv_bfloat16* Bt = Wb + (size_t)e * wstride;
    GEMM_MAIN(A, Bt, N, K)
#pragma unroll
    for (int mf = 0; mf < 4; mf++)
#pragma unroll
        for (int nf = 0; nf < 4; nf++) {
            int row0 = rowBase + wm * 64 + mf * 16 + rr;
            int col = colBase + wn * 32 + nf * 8 + cq;
            *(float2*)&C[(size_t)row0 * N + col] = make_float2(cr[mf][nf][0], cr[mf][nf][1]);
            *(float2*)&C[(size_t)(row0 + 8) * N + col] = make_float2(cr[mf][nf][2], cr[mf][nf][3]);
        }
}

// ================= MoE GEMM, fused SwiGLU bf16 out =================
__global__ __launch_bounds__(256) void gemm_moe_swiglu(
    const __nv_bfloat16* __restrict__ A, const __nv_bfloat16* __restrict__ Wb,
    __nv_bfloat16* __restrict__ Obf, int N2, int K, long wstride)
{
    int rowBase = blockIdx.y * BM;
    if (rowBase >= g_off[EE]) return;
    int colBase = blockIdx.x * BN;
    int e = 0;
    while (g_off[e + 1] <= rowBase) e++;
    const __nv_bfloat16* Bt = Wb + (size_t)e * wstride;
    GEMM_MAIN(A, Bt, N2, K)
    int FFo = N2 >> 1;
#pragma unroll
    for (int mf = 0; mf < 4; mf++)
#pragma unroll
        for (int nf = 0; nf < 4; nf++) {
            int row0 = rowBase + wm * 64 + mf * 16 + rr;
            int f = (colBase + wn * 32 + nf * 8 + cq) >> 1;
            float a0 = cr[mf][nf][0], b0 = cr[mf][nf][1];
            Obf[(size_t)row0 * FFo + f] = __float2bfloat16(a0 / (1.f + __expf(-a0)) * b0);
            float a1 = cr[mf][nf][2], b1 = cr[mf][nf][3];
            Obf[(size_t)(row0 + 8) * FFo + f] = __float2bfloat16(a1 / (1.f + __expf(-a1)) * b1);
        }
}

// ---------------- streaming weight convert: [K,NWs] f32 -> [K,NWd] bf16 --
__global__ void wcvt(const float* __restrict__ src, __nv_bfloat16* __restrict__ dst,
                     int NWs, int NWd, int coff, long sstride, long dstride, long total8) {
    long i = (long)blockIdx.x * blockDim.x + threadIdx.x;
    if (i >= total8) return;
    long e = i * 8;
    int k = (int)(e / NWs);
    int n = (int)(e - (long)k * NWs);
    const float* s = src + (size_t)blockIdx.z * sstride + (size_t)k * NWs + n;
    float4 v0 = *(const float4*)s;
    float4 v1 = *(const float4*)(s + 4);
    __nv_bfloat16 o[8];
    o[0] = __float2bfloat16(v0.x); o[1] = __float2bfloat16(v0.y);
    o[2] = __float2bfloat16(v0.z); o[3] = __float2bfloat16(v0.w);
    o[4] = __float2bfloat16(v1.x); o[5] = __float2bfloat16(v1.y);
    o[6] = __float2bfloat16(v1.z); o[7] = __float2bfloat16(v1.w);
    *(uint4*)&dst[(size_t)blockIdx.z * dstride + (size_t)k * NWd + coff + n] = *(uint4*)o;
}

// ---------------- streaming pair convert: w1,w2 [K,NW] -> [K,2NW] interleaved
__global__ void wcvt_pair(const float* __restrict__ s1, const float* __restrict__ s2,
                          __nv_bfloat16* __restrict__ dst,
                          int NW, long sstride, long dstride, long total4) {
    long i = (long)blockIdx.x * blockDim.x + threadIdx.x;
    if (i >= total4) return;
    long e = i * 4;
    int k = (int)(e / NW);
    int f = (int)(e - (long)k * NW);
    size_t so = (size_t)blockIdx.z * sstride + (size_t)k * NW + f;
    float4 va = *(const float4*)(s1 + so);
    float4 vb = *(const float4*)(s2 + so);
    __nv_bfloat16 o[8];
    o[0] = __float2bfloat16(va.x); o[1] = __float2bfloat16(vb.x);
    o[2] = __float2bfloat16(va.y); o[3] = __float2bfloat16(vb.y);
    o[4] = __float2bfloat16(va.z); o[5] = __float2bfloat16(vb.z);
    o[6] = __float2bfloat16(va.w); o[7] = __float2bfloat16(vb.w);
    *(uint4*)&dst[(size_t)blockIdx.z * dstride + (size_t)k * (2 * NW) + 2 * f] = *(uint4*)o;
}

// ---------------- RMSNorm (dual output) ----------------
__global__ void rmsnorm_kernel(const float* __restrict__ x,
                               const float* __restrict__ w,
                               float* __restrict__ of,
                               __nv_bfloat16* __restrict__ ob) {
    int row = blockIdx.x;
    int tid = threadIdx.x;
    const float* xr = x + (size_t)row * CC;
    float s = 0.f;
    for (int i = tid; i < CC; i += 256) { float v = xr[i]; s += v * v; }
    __shared__ float red[256];
    red[tid] = s; __syncthreads();
    for (int o2 = 128; o2 > 0; o2 >>= 1) {
        if (tid < o2) red[tid] += red[tid + o2];
        __syncthreads();
    }
    float scale = rsqrtf(red[0] / (float)CC + 1e-6f);
    for (int i = tid; i < CC; i += 256) {
        float v = xr[i] * scale * w[i];
        if (of) of[(size_t)row * CC + i] = v;
        ob[(size_t)row * CC + i] = __float2bfloat16(v);
    }
}

// ---------------- RoPE (in place in qkv buffer) --------------------------
__global__ void rope_kernel(float* __restrict__ X, int nheads, int hoff) {
    int i = blockIdx.x * blockDim.x + threadIdx.x;
    int total = NTOK * nheads * 32;
    if (i >= total) return;
    int p = i & 31;
    int tmp = i >> 5;
    int hh = tmp % nheads;
    int row = tmp / nheads;
    int t = row % TT;
    float invf = expf(-(float)p * (logf(10000.f) / 32.f));
    float ang = (float)t * invf;
    float cs = cosf(ang), sn = sinf(ang);
    size_t base = (size_t)row * QKVN + hoff + hh * 64;
    float a = X[base + p];
    float b = X[base + p + 32];
    X[base + p]      = a * cs - b * sn;
    X[base + p + 32] = b * cs + a * sn;
}

// ---------------- K/V fp32 -> bf16 compact (post-RoPE) -------------------
__global__ void kv2bf_kernel(const float* __restrict__ QKV,
                             __nv_bfloat16* __restrict__ Kb,
                             __nv_bfloat16* __restrict__ Vb) {
    int i = blockIdx.x * blockDim.x + threadIdx.x;
    int total = NTOK * KVW / 2;
    if (i >= total) return;
    int row = i >> 7;
    int p2 = (i & 127) * 2;
    const float* base = QKV + (size_t)row * QKVN + CC;
    *(__nv_bfloat162*)&Kb[(size_t)row * KVW + p2] =
        __floats2bfloat162_rn(base[p2], base[p2 + 1]);
    *(__nv_bfloat162*)&Vb[(size_t)row * KVW + p2] =
        __floats2bfloat162_rn(base[KVW + p2], base[KVW + p2 + 1]);
}

// ---------------- flash attention: 64-row Q tiles, mma.sync, bf16 K/V ----
// V consumed via ldmatrix.trans (no smem transpose)
__global__ __launch_bounds__(128) void attn_mma(const float* __restrict__ QKV,
                                                const __nv_bfloat16* __restrict__ Kb,
                                                const __nv_bfloat16* __restrict__ Vb,
                                                __nv_bfloat16* __restrict__ O) {
    int qb = blockIdx.x, h = blockIdx.y, b = blockIdx.z;
    int tid = threadIdx.x;
    int wid = tid >> 5, lane = tid & 31;
    int kvh = h / NREP;

    __shared__ __align__(16) __nv_bfloat16 Qs[64 * 72];
    __shared__ __align__(16) __nv_bfloat16 Ks[64 * 72];
    __shared__ __align__(16) __nv_bfloat16 Vs[64 * 72];

    for (int i = tid; i < 64 * 32; i += 128) {
        int row = i >> 5, p2 = i & 31;
        const float* src = QKV + ((size_t)(b * TT + qb * 64 + row)) * QKVN + h * DH + p2 * 2;
        *(__nv_bfloat162*)&Qs[row * 72 + p2 * 2] =
            __floats2bfloat162_rn(src[0] * 0.125f, src[1] * 0.125f);
    }
    __syncthreads();

    int r16 = lane & 15, kh = lane >> 4;
    int rn = lane & 7, knh = (lane >> 3) & 1;
    uint32_t qf[4][4];
#pragma unroll
    for (int kk = 0; kk < 4; kk++) {
        uint32_t ad = su32(&Qs[(wid * 16 + r16) * 72 + kk * 16 + kh * 8]);
        asm volatile("ldmatrix.sync.aligned.m8n8.x4.shared.b16 {%0,%1,%2,%3}, [%4];"
            : "=r"(qf[kk][0]), "=r"(qf[kk][1]), "=r"(qf[kk][2]), "=r"(qf[kk][3]) : "r"(ad));
    }

    int rr = lane >> 2, cq = (lane & 3) * 2;
    int t0 = qb * 64 + wid * 16 + rr;   // second row = t0+8
    float m0 = -1e30f, m1 = -1e30f, l0 = 0.f, l1 = 0.f;
    float acc[8][4];
#pragma unroll
    for (int dn = 0; dn < 8; dn++)
#pragma unroll
        for (int r = 0; r < 4; r++) acc[dn][r] = 0.f;

    int kstart = qb * 64 - WIN; if (kstart < 0) kstart = 0;
    for (int k0 = kstart; k0 <= qb * 64; k0 += 64) {
        __syncthreads();
        for (int i = tid; i < 64 * 32; i += 128) {
            int row = i >> 5, p2 = (i & 31) * 2;
            size_t kr = ((size_t)(b * TT + k0 + row)) * KVW + kvh * DH;
            *(__nv_bfloat162*)&Ks[row * 72 + p2] = *(const __nv_bfloat162*)&Kb[kr + p2];
            *(__nv_bfloat162*)&Vs[row * 72 + p2] = *(const __nv_bfloat162*)&Vb[kr + p2];
        }
        __syncthreads();

        float s[8][4];
#pragma unroll
        for (int j = 0; j < 8; j++) {
            s[j][0] = s[j][1] = s[j][2] = s[j][3] = 0.f;
#pragma unroll
            for (int kk = 0; kk < 4; kk++) {
                uint32_t bfr[2];
                uint32_t bd = su32(&Ks[(j * 8 + rn) * 72 + kk * 16 + knh * 8]);
                asm volatile("ldmatrix.sync.aligned.m8n8.x2.shared.b16 {%0,%1}, [%2];"
                    : "=r"(bfr[0]), "=r"(bfr[1]) : "r"(bd));
                asm volatile(
                    "mma.sync.aligned.m16n8k16.row.col.f32.bf16.bf16.f32 "
                    "{%0,%1,%2,%3}, {%4,%5,%6,%7}, {%8,%9}, {%0,%1,%2,%3};"
                    : "+f"(s[j][0]), "+f"(s[j][1]), "+f"(s[j][2]), "+f"(s[j][3])
                    : "r"(qf[kk][0]), "r"(qf[kk][1]), "r"(qf[kk][2]), "r"(qf[kk][3]),
                      "r"(bfr[0]), "r"(bfr[1]));
            }
        }
#pragma unroll
        for (int j = 0; j < 8; j++) {
            int kg = k0 + j * 8 + cq;
            if (kg > t0 || kg < t0 - WIN) s[j][0] = -1e30f;
            if (kg + 1 > t0 || kg + 1 < t0 - WIN) s[j][1] = -1e30f;
            if (kg > t0 + 8 || kg < t0 + 8 - WIN) s[j][2] = -1e30f;
            if (kg + 1 > t0 + 8 || kg + 1 < t0 + 8 - WIN) s[j][3] = -1e30f;
        }
        float mx0 = -1e30f, mx1 = -1e30f;
#pragma unroll
        for (int j = 0; j < 8; j++) {
            mx0 = fmaxf(mx0, fmaxf(s[j][0], s[j][1]));
            mx1 = fmaxf(mx1, fmaxf(s[j][2], s[j][3]));
        }
        mx0 = fmaxf(mx0, __shfl_xor_sync(0xffffffffu, mx0, 1));
        mx0 = fmaxf(mx0, __shfl_xor_sync(0xffffffffu, mx0, 2));
        mx1 = fmaxf(mx1, __shfl_xor_sync(0xffffffffu, mx1, 1));
        mx1 = fmaxf(mx1, __shfl_xor_sync(0xffffffffu, mx1, 2));
        float mn0 = fmaxf(m0, mx0), mn1 = fmaxf(m1, mx1);
        float c0 = __expf(m0 - mn0), c1 = __expf(m1 - mn1);
        m0 = mn0; m1 = mn1;
        l0 *= c0; l1 *= c1;
#pragma unroll
        for (int dn = 0; dn < 8; dn++) {
            acc[dn][0] *= c0; acc[dn][1] *= c0;
            acc[dn][2] *= c1; acc[dn][3] *= c1;
        }
#pragma unroll
        for (int j = 0; j < 8; j++) {
            s[j][0] = __expf(s[j][0] - m0); s[j][1] = __expf(s[j][1] - m0);
            s[j][2] = __expf(s[j][2] - m1); s[j][3] = __expf(s[j][3] - m1);
            l0 += s[j][0] + s[j][1];
            l1 += s[j][2] + s[j][3];
        }
        uint32_t pa[4][4];
#pragma unroll
        for (int kk = 0; kk < 4; kk++) {
            int j0 = kk * 2, j1 = kk * 2 + 1;
            pa[kk][0] = packbf(s[j0][0], s[j0][1]);
            pa[kk][1] = packbf(s[j0][2], s[j0][3]);
            pa[kk][2] = packbf(s[j1][0], s[j1][1]);
            pa[kk][3] = packbf(s[j1][2], s[j1][3]);
        }
#pragma unroll
        for (int dn = 0; dn < 8; dn++)
#pragma unroll
            for (int kk = 0; kk < 4; kk++) {
                uint32_t bfr[2];
                uint32_t bd = su32(&Vs[(kk * 16 + knh * 8 + rn) * 72 + dn * 8]);
                asm volatile("ldmatrix.sync.aligned.m8n8.x2.trans.shared.b16 {%0,%1}, [%2];"
                    : "=r"(bfr[0]), "=r"(bfr[1]) : "r"(bd));
                asm volatile(
                    "mma.sync.aligned.m16n8k16.row.col.f32.bf16.bf16.f32 "
                    "{%0,%1,%2,%3}, {%4,%5,%6,%7}, {%8,%9}, {%0,%1,%2,%3};"
                    : "+f"(acc[dn][0]), "+f"(acc[dn][1]), "+f"(acc[dn][2]), "+f"(acc[dn][3])
                    : "r"(pa[kk][0]), "r"(pa[kk][1]), "r"(pa[kk][2]), "r"(pa[kk][3]),
                      "r"(bfr[0]), "r"(bfr[1]));
            }
    }
    l0 += __shfl_xor_sync(0xffffffffu, l0, 1);
    l0 += __shfl_xor_sync(0xffffffffu, l0, 2);
    l1 += __shfl_xor_sync(0xffffffffu, l1, 1);
    l1 += __shfl_xor_sync(0xffffffffu, l1, 2);
    float i0 = 1.f / l0, i1 = 1.f / l1;
    __nv_bfloat16* o0 = O + ((size_t)(b * TT + t0)) * CC + h * DH;
    __nv_bfloat16* o1 = o0 + (size_t)8 * CC;
#pragma unroll
    for (int dn = 0; dn < 8; dn++) {
        *(__nv_bfloat162*)&o0[dn * 8 + cq] =
            __floats2bfloat162_rn(acc[dn][0] * i0, acc[dn][1] * i0);
        *(__nv_bfloat162*)&o1[dn * 8 + cq] =
            __floats2bfloat162_rn(acc[dn][2] * i1, acc[dn][3] * i1);
    }
}

// ---------------- router ----------------
__global__ void route_kernel(const float* __restrict__ xf,
                             const float* __restrict__ gw) {
    int warp = threadIdx.x >> 5, lane = threadIdx.x & 31;
    int tok = blockIdx.x * 4 + warp;
    if (tok >= NTOK) return;
    const float* xr = xf + (size_t)tok * CC;
    float part[EE];
#pragma unroll
    for (int e = 0; e < EE; e++) part[e] = 0.f;
    for (int d = lane; d < CC; d += 32) {
        float xv = xr[d];
#pragma unroll
        for (int e = 0; e < EE; e++) part[e] += xv * gw[d * EE + e];
    }
#pragma unroll
    for (int e = 0; e < EE; e++)
#pragma unroll
        for (int o = 16; o > 0; o >>= 1)
            part[e] += __shfl_xor_sync(0xffffffffu, part[e], o);
    if (lane == 0) {
        float v0 = -1e30f; int i0 = 0;
#pragma unroll
        for (int e = 0; e < EE; e++) if (part[e] > v0) { v0 = part[e]; i0 = e; }
        float v1 = -1e30f; int i1 = 0;
#pragma unroll
        for (int e = 0; e < EE; e++)
            if (e != i0 && part[e] > v1) { v1 = part[e]; i1 = e; }
        float ex = expf(v1 - v0);
        float w0 = 1.f / (1.f + ex);
        float w1 = ex / (1.f + ex);
        g_sel[tok * 2] = i0; g_sel[tok * 2 + 1] = i1;
        g_selw[tok * 2] = w0; g_selw[tok * 2 + 1] = w1;
        float mx = v0, sum = 0.f, pe[EE];
#pragma unroll
        for (int e = 0; e < EE; e++) { pe[e] = expf(part[e] - mx); sum += pe[e]; }
#pragma unroll
        for (int e = 0; e < EE; e++) g_probs[tok * EE + e] = pe[e] / sum;
        float lse = mx + logf(sum);
        g_lse2[tok] = lse * lse;
    }
}

// ---------------- aux loss ----------------
__global__ void aux_kernel() {
    __shared__ float red[256];
    int tid = threadIdx.x;
    float loadv[EE];
#pragma unroll
    for (int e = 0; e < EE; e++) loadv[e] = 0.f;
    for (int n = tid; n < NTOK; n += 256) {
#pragma unroll
        for (int e = 0; e < EE; e++) loadv[e] += g_probs[n * EE + e];
    }
    float loads[EE];
    for (int e = 0; e < EE; e++) {
        red[tid] = loadv[e]; __syncthreads();
        for (int o = 128; o > 0; o >>= 1) {
            if (tid < o) red[tid] += red[tid + o];
            __syncthreads();
        }
        loads[e] = red[0]; __syncthreads();
    }
    float zp = 0.f;
    for (int n = tid; n < NTOK; n += 256) zp += g_lse2[n];
    red[tid] = zp; __syncthreads();
    for (int o = 128; o > 0; o >>= 1) {
        if (tid < o) red[tid] += red[tid + o];
        __syncthreads();
    }
    if (tid == 0) {
        float tot = 0.f;
        for (int e = 0; e < EE; e++) tot += loads[e];
        float lb = 0.f;
        for (int e = 0; e < EE; e++) { float f = loads[e] / tot; lb += f * f; }
        lb *= (float)EE;
        float z = red[0] / (float)NTOK;
        g_aux = 0.01f * lb + 0.001f * z;
    }
}

__global__ void zero_cnt_kernel() { if (threadIdx.x < EE) g_cnt[threadIdx.x] = 0; }

__global__ void count_kernel() {
    int i = blockIdx.x * blockDim.x + threadIdx.x;
    if (i >= NTOK) return;
#pragma unroll
    for (int kk = 0; kk < TOPK; kk++)
        atomicAdd(&g_cnt[g_sel[i * 2 + kk]], 1);
}

__global__ void offsets_kernel() {
    if (threadIdx.x == 0) {
        int acc = 0;
        for (int e = 0; e < EE; e++) {
            g_off[e] = acc;
            acc += (g_cnt[e] + BM - 1) & ~(BM - 1);
            g_cnt2[e] = 0;
        }
        g_off[EE] = acc;
    }
}

__global__ void assign_kernel() {
    int i = blockIdx.x * blockDim.x + threadIdx.x;
    if (i >= NTOK) return;
#pragma unroll
    for (int kk = 0; kk < TOPK; kk++) {
        int e = g_sel[i * 2 + kk];
        int pos = atomicAdd(&g_cnt2[e], 1);
        int row = g_off[e] + pos;
        g_idx[row] = i;
        g_tokrow[i * 2 + kk] = row;
    }
}

__global__ void gather_all_kernel(__nv_bfloat16* __restrict__ dst,
                                  const __nv_bfloat16* __restrict__ src) {
    int b = blockIdx.x;
    if (b >= g_off[EE]) return;
    int e = 0;
    while (g_off[e + 1] <= b) e++;
    if (b - g_off[e] >= g_cnt[e]) return;
    int t = g_idx[b];
    uint4* d4 = (uint4*)(dst + (size_t)b * CC);
    const uint4* s4 = (const uint4*)(src + (size_t)t * CC);
    int i = threadIdx.x;
    if (i < CC * 2 / 16) d4[i] = s4[i];
}

// final: out = h + a_moe * (shared + w0*eo[r0] + w1*eo[r1])
__global__ void final_kernel(const float* __restrict__ h, const float* __restrict__ moe,
                             const float* __restrict__ eo,
                             const float* __restrict__ alpha, float* __restrict__ out) {
    int t = blockIdx.x;
    float w0 = g_selw[t * 2], w1 = g_selw[t * 2 + 1];
    int r0 = g_tokrow[t * 2], r1 = g_tokrow[t * 2 + 1];
    float a = *alpha;
    const float* hr = h + (size_t)t * CC;
    const float* mr = moe + (size_t)t * CC;
    const float* e0 = eo + (size_t)r0 * CC;
    const float* e1 = eo + (size_t)r1 * CC;
    float* orow = out + (size_t)t * CC;
    for (int i = threadIdx.x; i < CC; i += blockDim.x)
        orow[i] = hr[i] + a * (mr[i] + w0 * e0[i] + w1 * e1[i]);
}

__global__ void auxwrite_kernel(float* __restrict__ out) { out[OUT_MAIN] = g_aux; }

// ---------------- launch ----------------
extern "C" void kernel_launch(void* const* d_in, const int* in_sizes, int n_in,
                              void* d_out, int out_size) {
    const float* x      = (const float*)d_in[0];
    const float* ln1    = (const float*)d_in[1];
    const float* ln2    = (const float*)d_in[2];
    const float* wq     = (const float*)d_in[3];
    const float* wk     = (const float*)d_in[4];
    const float* wv     = (const float*)d_in[5];
    const float* wo     = (const float*)d_in[6];
    const float* sw1    = (const float*)d_in[7];
    const float* sw2    = (const float*)d_in[8];
    const float* sw3    = (const float*)d_in[9];
    const float* ew1    = (const float*)d_in[10];
    const float* ew2    = (const float*)d_in[11];
    const float* ew3    = (const float*)d_in[12];
    const float* gatew  = (const float*)d_in[13];
    const float* a_attn = (const float*)d_in[14];
    const float* a_moe  = (const float*)d_in[15];
    float* out = (float*)d_out;

    void* p;
    float *qkv, *h, *xf, *moe, *eo;
    __nv_bfloat16 *xnb, *aob, *xfb, *xgb, *g1b, *kb, *vb;
    __nv_bfloat16 *wqkvt, *wot, *sw12t, *sw3t, *ew12t, *ew3t;
    cudaGetSymbolAddress(&p, g_qkv);  qkv  = (float*)p;
    cudaGetSymbolAddress(&p, g_h);    h    = (float*)p;
    cudaGetSymbolAddress(&p, g_xf);   xf   = (float*)p;
    cudaGetSymbolAddress(&p, g_moe);  moe  = (float*)p;
    cudaGetSymbolAddress(&p, g_eo);   eo   = (float*)p;
    cudaGetSymbolAddress(&p, g_xnb);  xnb  = (__nv_bfloat16*)p;
    cudaGetSymbolAddress(&p, g_aob);  aob  = (__nv_bfloat16*)p;
    cudaGetSymbolAddress(&p, g_xfb);  xfb  = (__nv_bfloat16*)p;
    cudaGetSymbolAddress(&p, g_xgb);  xgb  = (__nv_bfloat16*)p;
    cudaGetSymbolAddress(&p, g_g1b);  g1b  = (__nv_bfloat16*)p;
    cudaGetSymbolAddress(&p, g_kb);   kb   = (__nv_bfloat16*)p;
    cudaGetSymbolAddress(&p, g_vb);   vb   = (__nv_bfloat16*)p;
    cudaGetSymbolAddress(&p, g_wqkvt); wqkvt = (__nv_bfloat16*)p;
    cudaGetSymbolAddress(&p, g_wot);   wot   = (__nv_bfloat16*)p;
    cudaGetSymbolAddress(&p, g_sw12t); sw12t = (__nv_bfloat16*)p;
    cudaGetSymbolAddress(&p, g_sw3t);  sw3t  = (__nv_bfloat16*)p;
    cudaGetSymbolAddress(&p, g_ew12t); ew12t = (__nv_bfloat16*)p;
    cudaGetSymbolAddress(&p, g_ew3t);  ew3t  = (__nv_bfloat16*)p;

    static bool s_init = false;
    static cudaStream_t s2 = 0;
    static cudaEvent_t evA = 0, evB = 0;
    if (!s_init) {
        if (cudaStreamCreateWithFlags(&s2, cudaStreamNonBlocking) != cudaSuccess) s2 = 0;
        if (s2) {
            if (cudaEventCreateWithFlags(&evA, cudaEventDisableTiming) != cudaSuccess) evA = 0;
            if (cudaEventCreateWithFlags(&evB, cudaEventDisableTiming) != cudaSuccess) evB = 0;
            if (!evA || !evB) s2 = 0;
        }
        s_init = true;
    }

    // streaming weight conversions (K-major, no transpose)
    wcvt<<<512, 256>>>(wq, wqkvt, CC, QKVN, 0, 0, 0, (long)CC*CC/8);
    wcvt<<<128, 256>>>(wk, wqkvt, KVW, QKVN, CC, 0, 0, (long)CC*KVW/8);
    wcvt<<<128, 256>>>(wv, wqkvt, KVW, QKVN, CC+KVW, 0, 0, (long)CC*KVW/8);
    wcvt<<<512, 256>>>(wo, wot, CC, CC, 0, 0, 0, (long)CC*CC/8);
    wcvt_pair<<<4096, 256>>>(sw1, sw2, sw12t, FF, 0, 0, (long)CC*FF/4);
    wcvt<<<2048, 256>>>(sw3, sw3t, CC, CC, 0, 0, 0, (long)FF*CC/8);

    // expert conversions forked onto s2 (overlaps attention-side compute)
    bool forked = (s2 != 0);
    if (forked) {
        cudaEventRecord(evA, 0);
        cudaStreamWaitEvent(s2, evA, 0);
        wcvt_pair<<<dim3(4096,1,EE), 256, 0, s2>>>(ew1, ew2, ew12t, FF,
            (long)CC*FF, (long)CC*2*FF, (long)CC*FF/4);
        wcvt<<<dim3(2048,1,EE), 256, 0, s2>>>(ew3, ew3t, CC, CC, 0,
            (long)FF*CC, (long)FF*CC, (long)FF*CC/8);
        cudaEventRecord(evB, s2);
    } else {
        wcvt_pair<<<dim3(4096,1,EE), 256>>>(ew1, ew2, ew12t, FF,
            (long)CC*FF, (long)CC*2*FF, (long)CC*FF/4);
        wcvt<<<dim3(2048,1,EE), 256>>>(ew3, ew3t, CC, CC, 0,
            (long)FF*CC, (long)FF*CC, (long)FF*CC/8);
    }

    // 1) pre-attn norm
    rmsnorm_kernel<<<NTOK, 256>>>(x, ln1, nullptr, xnb);
    // 2) fused QKV projection
    gemm_mma<<<dim3(QKVN/128, NTOK/128), 256>>>(xnb, wqkvt, qkv, QKVN, CC);
    // 3) RoPE + K/V bf16 compaction
    rope_kernel<<<(NTOK * HH * 32 + 255) / 256, 256>>>(qkv, HH, 0);
    rope_kernel<<<(NTOK * KVH * 32 + 255) / 256, 256>>>(qkv, KVH, CC);
    kv2bf_kernel<<<(NTOK * KVW / 2 + 255) / 256, 256>>>(qkv, kb, vb);
    // 4) attention (tensor core, 64-row Q tiles, bf16 K/V, trans-V)
    attn_mma<<<dim3(TT/64, HH, BB), 128>>>(qkv, kb, vb, aob);
    // 5) output projection with fused ReZero residual
    gemm_mma_add<<<dim3(CC/128, NTOK/128), 256>>>(aob, wot, x, a_attn, h, CC, CC);
    // 6) post-attn norm
    rmsnorm_kernel<<<NTOK, 256>>>(h, ln2, xf, xfb);
    // 7) routing + aux + compaction
    route_kernel<<<NTOK / 4, 128>>>(xf, gatew);
    aux_kernel<<<1, 256>>>();
    zero_cnt_kernel<<<1, 32>>>();
    count_kernel<<<(NTOK + 255) / 256, 256>>>();
    offsets_kernel<<<1, 32>>>();
    assign_kernel<<<(NTOK + 255) / 256, 256>>>();
    // 8) shared expert: fused w12+SwiGLU, then w3
    gemm_swiglu<<<dim3(2*FF/128, NTOK/128), 256>>>(xfb, sw12t, g1b, 2*FF, CC);
    gemm_mma<<<dim3(CC/128, NTOK/128), 256>>>(g1b, sw3t, moe, CC, FF);
    // 9) routed experts, batched (join expert-weight conversion first)
    gather_all_kernel<<<ECAP, 128>>>(xgb, xfb);
    if (forked) cudaStreamWaitEvent(0, evB, 0);
    gemm_moe_swiglu<<<dim3(2*FF/128, ECAP/128), 256>>>(xgb, ew12t, g1b, 2*FF, CC, (long)CC*2*FF);
    gemm_moe<<<dim3(CC/128, ECAP/128), 256>>>(g1b, ew3t, eo, CC, FF, (long)FF*CC);
    // 10) final combine + aux scalar
    final_kernel<<<NTOK, 256>>>(h, moe, eo, a_moe, out);
    if (out_size > OUT_MAIN) auxwrite_kernel<<<1, 1>>>(out);
}

// round 11
// speedup vs baseline: 1.2260x; 1.0440x over previous
#include <cuda_runtime.h>
#include <cuda_bf16.h>
#include <math.h>
#include <stdint.h>

// Problem constants
#define BB   2
#define TT   2048
#define CC   1024
#define HH   16
#define KVH  4
#define DH   64
#define NREP 4
#define FF   4096
#define EE   8
#define TOPK 2
#define WIN  1024
#define NTOK (BB*TT)            // 4096
#define OUT_MAIN (NTOK*CC)      // 4194304
#define QKVN (CC + 2*KVH*DH)    // 1536
#define KVW  (KVH*DH)           // 256
#define ECAP 9216               // 8192 real rows + padding, 128-aligned

// ---------------- scratch (device globals; no allocation) ----------------
__device__ float g_qkv [NTOK*QKVN];
__device__ float g_h   [NTOK*CC];
__device__ float g_xf  [NTOK*CC];
__device__ float g_moe [NTOK*CC];
__device__ float g_eo  [(size_t)ECAP*CC];
__device__ float g_probs[NTOK*EE];
__device__ float g_lse2[NTOK];
__device__ int   g_sel [NTOK*2];
__device__ float g_selw[NTOK*2];
__device__ int   g_cnt [EE];
__device__ int   g_cnt2[EE];
__device__ int   g_off [EE+1];
__device__ int   g_idx [ECAP];
__device__ int   g_tokrow[NTOK*2];
__device__ float g_aux;

// bf16 activations
__device__ __nv_bfloat16 g_xnb [NTOK*CC];
__device__ __nv_bfloat16 g_aob [NTOK*CC];
__device__ __nv_bfloat16 g_xfb [NTOK*CC];
__device__ __nv_bfloat16 g_xgb [(size_t)ECAP*CC];
__device__ __nv_bfloat16 g_g1b [(size_t)ECAP*FF];
__device__ __nv_bfloat16 g_kb  [NTOK*KVW];
__device__ __nv_bfloat16 g_vb  [NTOK*KVW];

// bf16 weights, K-major [K,N] (w12 column-interleaved: w1->2f, w2->2f+1)
__device__ __nv_bfloat16 g_wqkvt[CC*QKVN];
__device__ __nv_bfloat16 g_wot  [CC*CC];
__device__ __nv_bfloat16 g_sw12t[CC*2*FF];
__device__ __nv_bfloat16 g_sw3t [FF*CC];
__device__ __nv_bfloat16 g_ew12t[(size_t)EE*CC*2*FF];
__device__ __nv_bfloat16 g_ew3t [(size_t)EE*FF*CC];

__device__ __forceinline__ uint32_t su32(const void* p) {
    uint32_t a;
    asm("{ .reg .u64 t; cvta.to.shared.u64 t, %1; cvt.u32.u64 %0, t; }" : "=r"(a) : "l"(p));
    return a;
}
__device__ __forceinline__ uint32_t packbf(float a, float b) {
    __nv_bfloat162 t = __floats2bfloat162_rn(a, b);
    return *(uint32_t*)&t;
}

#define CP_ASYNC16(d, s) asm volatile("cp.async.cg.shared.global [%0], [%1], 16;" :: "r"(d), "l"(s))
#define CP_COMMIT()      asm volatile("cp.async.commit_group;" ::: "memory")
#define CP_WAIT(n)       asm volatile("cp.async.wait_group %0;" :: "n"(n) : "memory")

#define BM 128
#define BN 128
#define BK 32
#define ASTR 40    // A smem row stride (bf16 elems)
#define BSTR 136   // B smem row stride (bf16 elems)

// ================= 2-stage GEMM mainloop; B is [K,N] via ldmatrix.x4.trans
#define GEMM_MAIN(A_, Bt_, N_, K_)                                             \
    __shared__ __align__(16) __nv_bfloat16 sA[2][BM * ASTR];                   \
    __shared__ __align__(16) __nv_bfloat16 sB[2][BK * BSTR];                   \
    int tid = threadIdx.x;                                                     \
    int wid = tid >> 5, lane = tid & 31;                                       \
    int wm = wid >> 2, wn = wid & 3;                                           \
    float cr[4][4][4];                                                         \
    _Pragma("unroll") for (int i = 0; i < 4; i++)                              \
    _Pragma("unroll") for (int j = 0; j < 4; j++)                              \
    _Pragma("unroll") for (int r = 0; r < 4; r++) cr[i][j][r] = 0.f;           \
    int lrow = tid >> 1;                                                       \
    int lc16 = (tid & 1) * 16;                                                 \
    int nCh = (K_) / BK;                                                       \
    {                                                                          \
        const __nv_bfloat16* srcA0 = (A_) + (size_t)(rowBase + lrow) * (K_) + lc16; \
        uint32_t dA0 = su32(&sA[0][lrow * ASTR + lc16]);                       \
        CP_ASYNC16(dA0, srcA0); CP_ASYNC16(dA0 + 16, srcA0 + 8);               \
        _Pragma("unroll") for (int bi = 0; bi < 2; bi++) {                     \
            int seg = tid + bi * 256;                                          \
            int brow = seg >> 4, bcol = (seg & 15) * 8;                        \
            const __nv_bfloat16* srcB = (Bt_) + (size_t)brow * (N_) + colBase + bcol; \
            CP_ASYNC16(su32(&sB[0][brow * BSTR + bcol]), srcB);                \
        }                                                                      \
        CP_COMMIT();                                                           \
    }                                                                          \
    for (int ch = 0; ch < nCh; ch++) {                                         \
        int st = ch & 1;                                                       \
        if (ch + 1 < nCh) {                                                    \
            int k0 = (ch + 1) * BK;                                            \
            const __nv_bfloat16* srcA = (A_) + (size_t)(rowBase + lrow) * (K_) + k0 + lc16; \
            uint32_t dA = su32(&sA[st ^ 1][lrow * ASTR + lc16]);               \
            CP_ASYNC16(dA, srcA); CP_ASYNC16(dA + 16, srcA + 8);               \
            _Pragma("unroll") for (int bi = 0; bi < 2; bi++) {                 \
                int seg = tid + bi * 256;                                      \
                int brow = seg >> 4, bcol = (seg & 15) * 8;                    \
                const __nv_bfloat16* srcB = (Bt_) + (size_t)(k0 + brow) * (N_) + colBase + bcol; \
                CP_ASYNC16(su32(&sB[st ^ 1][brow * BSTR + bcol]), srcB);       \
            }                                                                  \
            CP_COMMIT(); CP_WAIT(1);                                           \
        } else { CP_WAIT(0); }                                                 \
        __syncthreads();                                                       \
        int r16 = lane & 15, kh = lane >> 4;                                   \
        int brl = (lane & 7) + ((lane >> 3) & 1) * 8;   /* row within 16 */    \
        int bcl = ((lane >> 4) & 1) * 8;                /* col half */         \
        _Pragma("unroll") for (int kk = 0; kk < 2; kk++) {                     \
            uint32_t af[4][4];                                                 \
            _Pragma("unroll") for (int mf = 0; mf < 4; mf++) {                 \
                uint32_t ad = su32(&sA[st][(wm * 64 + mf * 16 + r16) * ASTR + kk * 16 + kh * 8]); \
                asm volatile("ldmatrix.sync.aligned.m8n8.x4.shared.b16 {%0,%1,%2,%3}, [%4];" \
                    : "=r"(af[mf][0]), "=r"(af[mf][1]), "=r"(af[mf][2]), "=r"(af[mf][3]) : "r"(ad)); \
            }                                                                  \
            uint32_t bfr[4][2];                                                \
            _Pragma("unroll") for (int nfp = 0; nfp < 2; nfp++) {              \
                uint32_t bd = su32(&sB[st][(kk * 16 + brl) * BSTR + wn * 32 + nfp * 16 + bcl]); \
                asm volatile("ldmatrix.sync.aligned.m8n8.x4.trans.shared.b16 {%0,%1,%2,%3}, [%4];" \
                    : "=r"(bfr[2*nfp][0]), "=r"(bfr[2*nfp][1]),                \
                      "=r"(bfr[2*nfp+1][0]), "=r"(bfr[2*nfp+1][1]) : "r"(bd)); \
            }                                                                  \
            _Pragma("unroll") for (int mf = 0; mf < 4; mf++)                   \
            _Pragma("unroll") for (int nf = 0; nf < 4; nf++) {                 \
                asm volatile(                                                  \
                    "mma.sync.aligned.m16n8k16.row.col.f32.bf16.bf16.f32 "     \
                    "{%0,%1,%2,%3}, {%4,%5,%6,%7}, {%8,%9}, {%0,%1,%2,%3};"    \
                    : "+f"(cr[mf][nf][0]), "+f"(cr[mf][nf][1]),                \
                      "+f"(cr[mf][nf][2]), "+f"(cr[mf][nf][3])                 \
                    : "r"(af[mf][0]), "r"(af[mf][1]), "r"(af[mf][2]), "r"(af[mf][3]), \
                      "r"(bfr[nf][0]), "r"(bfr[nf][1]));                       \
            }                                                                  \
        }                                                                      \
        __syncthreads();                                                       \
    }                                                                          \
    int rr = lane >> 2, cq = (lane & 3) * 2;

// ================= dense GEMM, fp32 out =================
__global__ __launch_bounds__(256) void gemm_mma(
    const __nv_bfloat16* __restrict__ A, const __nv_bfloat16* __restrict__ Bt,
    float* __restrict__ C, int N, int K)
{
    int rowBase = blockIdx.y * BM, colBase = blockIdx.x * BN;
    GEMM_MAIN(A, Bt, N, K)
#pragma unroll
    for (int mf = 0; mf < 4; mf++)
#pragma unroll
        for (int nf = 0; nf < 4; nf++) {
            int row0 = rowBase + wm * 64 + mf * 16 + rr;
            int col = colBase + wn * 32 + nf * 8 + cq;
            *(float2*)&C[(size_t)row0 * N + col] = make_float2(cr[mf][nf][0], cr[mf][nf][1]);
            *(float2*)&C[(size_t)(row0 + 8) * N + col] = make_float2(cr[mf][nf][2], cr[mf][nf][3]);
        }
}

// ===== dense GEMM with fused ReZero residual: C = X + (*alpha)*(A@Bt) ====
__global__ __launch_bounds__(256) void gemm_mma_add(
    const __nv_bfloat16* __restrict__ A, const __nv_bfloat16* __restrict__ Bt,
    const float* __restrict__ X, const float* __restrict__ alpha,
    float* __restrict__ C, int N, int K)
{
    int rowBase = blockIdx.y * BM, colBase = blockIdx.x * BN;
    GEMM_MAIN(A, Bt, N, K)
    float a = *alpha;
#pragma unroll
    for (int mf = 0; mf < 4; mf++)
#pragma unroll
        for (int nf = 0; nf < 4; nf++) {
            int row0 = rowBase + wm * 64 + mf * 16 + rr;
            int col = colBase + wn * 32 + nf * 8 + cq;
            float2 x0 = *(const float2*)&X[(size_t)row0 * N + col];
            float2 x1 = *(const float2*)&X[(size_t)(row0 + 8) * N + col];
            *(float2*)&C[(size_t)row0 * N + col] =
                make_float2(x0.x + a * cr[mf][nf][0], x0.y + a * cr[mf][nf][1]);
            *(float2*)&C[(size_t)(row0 + 8) * N + col] =
                make_float2(x1.x + a * cr[mf][nf][2], x1.y + a * cr[mf][nf][3]);
        }
}

// ================= dense GEMM, fused SwiGLU bf16 out (interleaved w12) ===
__global__ __launch_bounds__(256) void gemm_swiglu(
    const __nv_bfloat16* __restrict__ A, const __nv_bfloat16* __restrict__ Bt,
    __nv_bfloat16* __restrict__ Obf, int N2, int K)
{
    int rowBase = blockIdx.y * BM, colBase = blockIdx.x * BN;
    GEMM_MAIN(A, Bt, N2, K)
    int FFo = N2 >> 1;
#pragma unroll
    for (int mf = 0; mf < 4; mf++)
#pragma unroll
        for (int nf = 0; nf < 4; nf++) {
            int row0 = rowBase + wm * 64 + mf * 16 + rr;
            int f = (colBase + wn * 32 + nf * 8 + cq) >> 1;
            float a0 = cr[mf][nf][0], b0 = cr[mf][nf][1];
            Obf[(size_t)row0 * FFo + f] = __float2bfloat16(a0 / (1.f + __expf(-a0)) * b0);
            float a1 = cr[mf][nf][2], b1 = cr[mf][nf][3];
            Obf[(size_t)(row0 + 8) * FFo + f] = __float2bfloat16(a1 / (1.f + __expf(-a1)) * b1);
        }
}

// ================= MoE GEMM, fp32 out =================
__global__ __launch_bounds__(256) void gemm_moe(
    const __nv_bfloat16* __restrict__ A, const __nv_bfloat16* __restrict__ Wb,
    float* __restrict__ C, int N, int K, long wstride)
{
    int rowBase = blockIdx.y * BM;
    if (rowBase >= g_off[EE]) return;
    int colBase = blockIdx.x * BN;
    int e = 0;
    while (g_off[e + 1] <= rowBase) e++;
    const __nv_bfloat16* Bt = Wb + (size_t)e * wstride;
    GEMM_MAIN(A, Bt, N, K)
#pragma unroll
    for (int mf = 0; mf < 4; mf++)
#pragma unroll
        for (int nf = 0; nf < 4; nf++) {
            int row0 = rowBase + wm * 64 + mf * 16 + rr;
            int col = colBase + wn * 32 + nf * 8 + cq;
            *(float2*)&C[(size_t)row0 * N + col] = make_float2(cr[mf][nf][0], cr[mf][nf][1]);
            *(float2*)&C[(size_t)(row0 + 8) * N + col] = make_float2(cr[mf][nf][2], cr[mf][nf][3]);
        }
}

// ================= MoE GEMM, fused SwiGLU bf16 out =================
__global__ __launch_bounds__(256) void gemm_moe_swiglu(
    const __nv_bfloat16* __restrict__ A, const __nv_bfloat16* __restrict__ Wb,
    __nv_bfloat16* __restrict__ Obf, int N2, int K, long wstride)
{
    int rowBase = blockIdx.y * BM;
    if (rowBase >= g_off[EE]) return;
    int colBase = blockIdx.x * BN;
    int e = 0;
    while (g_off[e + 1] <= rowBase) e++;
    const __nv_bfloat16* Bt = Wb + (size_t)e * wstride;
    GEMM_MAIN(A, Bt, N2, K)
    int FFo = N2 >> 1;
#pragma unroll
    for (int mf = 0; mf < 4; mf++)
#pragma unroll
        for (int nf = 0; nf < 4; nf++) {
            int row0 = rowBase + wm * 64 + mf * 16 + rr;
            int f = (colBase + wn * 32 + nf * 8 + cq) >> 1;
            float a0 = cr[mf][nf][0], b0 = cr[mf][nf][1];
            Obf[(size_t)row0 * FFo + f] = __float2bfloat16(a0 / (1.f + __expf(-a0)) * b0);
            float a1 = cr[mf][nf][2], b1 = cr[mf][nf][3];
            Obf[(size_t)(row0 + 8) * FFo + f] = __float2bfloat16(a1 / (1.f + __expf(-a1)) * b1);
        }
}

// ---------------- streaming weight convert: [K,NWs] f32 -> [K,NWd] bf16 --
__global__ void wcvt(const float* __restrict__ src, __nv_bfloat16* __restrict__ dst,
                     int NWs, int NWd, int coff, long sstride, long dstride, long total8) {
    long i = (long)blockIdx.x * blockDim.x + threadIdx.x;
    if (i >= total8) return;
    long e = i * 8;
    int k = (int)(e / NWs);
    int n = (int)(e - (long)k * NWs);
    const float* s = src + (size_t)blockIdx.z * sstride + (size_t)k * NWs + n;
    float4 v0 = *(const float4*)s;
    float4 v1 = *(const float4*)(s + 4);
    __nv_bfloat16 o[8];
    o[0] = __float2bfloat16(v0.x); o[1] = __float2bfloat16(v0.y);
    o[2] = __float2bfloat16(v0.z); o[3] = __float2bfloat16(v0.w);
    o[4] = __float2bfloat16(v1.x); o[5] = __float2bfloat16(v1.y);
    o[6] = __float2bfloat16(v1.z); o[7] = __float2bfloat16(v1.w);
    *(uint4*)&dst[(size_t)blockIdx.z * dstride + (size_t)k * NWd + coff + n] = *(uint4*)o;
}

// ---------------- streaming pair convert: w1,w2 [K,NW] -> [K,2NW] interleaved
__global__ void wcvt_pair(const float* __restrict__ s1, const float* __restrict__ s2,
                          __nv_bfloat16* __restrict__ dst,
                          int NW, long sstride, long dstride, long total4) {
    long i = (long)blockIdx.x * blockDim.x + threadIdx.x;
    if (i >= total4) return;
    long e = i * 4;
    int k = (int)(e / NW);
    int f = (int)(e - (long)k * NW);
    size_t so = (size_t)blockIdx.z * sstride + (size_t)k * NW + f;
    float4 va = *(const float4*)(s1 + so);
    float4 vb = *(const float4*)(s2 + so);
    __nv_bfloat16 o[8];
    o[0] = __float2bfloat16(va.x); o[1] = __float2bfloat16(vb.x);
    o[2] = __float2bfloat16(va.y); o[3] = __float2bfloat16(vb.y);
    o[4] = __float2bfloat16(va.z); o[5] = __float2bfloat16(vb.z);
    o[6] = __float2bfloat16(va.w); o[7] = __float2bfloat16(vb.w);
    *(uint4*)&dst[(size_t)blockIdx.z * dstride + (size_t)k * (2 * NW) + 2 * f] = *(uint4*)o;
}

// ---------------- RMSNorm (dual output) ----------------
__global__ void rmsnorm_kernel(const float* __restrict__ x,
                               const float* __restrict__ w,
                               float* __restrict__ of,
                               __nv_bfloat16* __restrict__ ob) {
    int row = blockIdx.x;
    int tid = threadIdx.x;
    const float* xr = x + (size_t)row * CC;
    float s = 0.f;
    for (int i = tid; i < CC; i += 256) { float v = xr[i]; s += v * v; }
    __shared__ float red[256];
    red[tid] = s; __syncthreads();
    for (int o2 = 128; o2 > 0; o2 >>= 1) {
        if (tid < o2) red[tid] += red[tid + o2];
        __syncthreads();
    }
    float scale = rsqrtf(red[0] / (float)CC + 1e-6f);
    for (int i = tid; i < CC; i += 256) {
        float v = xr[i] * scale * w[i];
        if (of) of[(size_t)row * CC + i] = v;
        ob[(size_t)row * CC + i] = __float2bfloat16(v);
    }
}

// ---------------- fused RoPE(q,k) + K/V bf16 compaction ------------------
__global__ void rope_all_kernel(float* __restrict__ X,
                                __nv_bfloat16* __restrict__ Kb,
                                __nv_bfloat16* __restrict__ Vb) {
    int i = blockIdx.x * blockDim.x + threadIdx.x;
    const int NQ = NTOK * HH * 32;
    const int NK = NTOK * KVH * 32;
    const int NV = NTOK * (KVW / 2);
    if (i < NQ) {
        int p = i & 31;
        int tmp = i >> 5;
        int hh = tmp % HH;
        int row = tmp / HH;
        int t = row % TT;
        float invf = expf(-(float)p * (logf(10000.f) / 32.f));
        float ang = (float)t * invf;
        float cs = cosf(ang), sn = sinf(ang);
        size_t base = (size_t)row * QKVN + hh * 64;
        float a = X[base + p];
        float b = X[base + p + 32];
        X[base + p]      = a * cs - b * sn;
        X[base + p + 32] = b * cs + a * sn;
    } else if (i < NQ + NK) {
        int j = i - NQ;
        int p = j & 31;
        int tmp = j >> 5;
        int hh = tmp % KVH;
        int row = tmp / KVH;
        int t = row % TT;
        float invf = expf(-(float)p * (logf(10000.f) / 32.f));
        float ang = (float)t * invf;
        float cs = cosf(ang), sn = sinf(ang);
        size_t base = (size_t)row * QKVN + CC + hh * 64;
        float a = X[base + p];
        float b = X[base + p + 32];
        Kb[(size_t)row * KVW + hh * 64 + p]      = __float2bfloat16(a * cs - b * sn);
        Kb[(size_t)row * KVW + hh * 64 + p + 32] = __float2bfloat16(b * cs + a * sn);
    } else if (i < NQ + NK + NV) {
        int j = i - NQ - NK;
        int row = j >> 7;
        int p2 = (j & 127) * 2;
        const float* base = X + (size_t)row * QKVN + CC + KVW;
        *(__nv_bfloat162*)&Vb[(size_t)row * KVW + p2] =
            __floats2bfloat162_rn(base[p2], base[p2 + 1]);
    }
}

// ---------------- flash attention: 64-row Q tiles, mma.sync, bf16 K/V ----
__global__ __launch_bounds__(128) void attn_mma(const float* __restrict__ QKV,
                                                const __nv_bfloat16* __restrict__ Kb,
                                                const __nv_bfloat16* __restrict__ Vb,
                                                __nv_bfloat16* __restrict__ O) {
    int qb = blockIdx.x, h = blockIdx.y, b = blockIdx.z;
    int tid = threadIdx.x;
    int wid = tid >> 5, lane = tid & 31;
    int kvh = h / NREP;

    __shared__ __align__(16) __nv_bfloat16 Qs[64 * 72];
    __shared__ __align__(16) __nv_bfloat16 Ks[64 * 72];
    __shared__ __align__(16) __nv_bfloat16 Vs[64 * 72];

    for (int i = tid; i < 64 * 32; i += 128) {
        int row = i >> 5, p2 = i & 31;
        const float* src = QKV + ((size_t)(b * TT + qb * 64 + row)) * QKVN + h * DH + p2 * 2;
        *(__nv_bfloat162*)&Qs[row * 72 + p2 * 2] =
            __floats2bfloat162_rn(src[0] * 0.125f, src[1] * 0.125f);
    }
    __syncthreads();

    int r16 = lane & 15, kh = lane >> 4;
    int rn = lane & 7, knh = (lane >> 3) & 1;
    uint32_t qf[4][4];
#pragma unroll
    for (int kk = 0; kk < 4; kk++) {
        uint32_t ad = su32(&Qs[(wid * 16 + r16) * 72 + kk * 16 + kh * 8]);
        asm volatile("ldmatrix.sync.aligned.m8n8.x4.shared.b16 {%0,%1,%2,%3}, [%4];"
            : "=r"(qf[kk][0]), "=r"(qf[kk][1]), "=r"(qf[kk][2]), "=r"(qf[kk][3]) : "r"(ad));
    }

    int rr = lane >> 2, cq = (lane & 3) * 2;
    int t0 = qb * 64 + wid * 16 + rr;   // second row = t0+8
    float m0 = -1e30f, m1 = -1e30f, l0 = 0.f, l1 = 0.f;
    float acc[8][4];
#pragma unroll
    for (int dn = 0; dn < 8; dn++)
#pragma unroll
        for (int r = 0; r < 4; r++) acc[dn][r] = 0.f;

    int kstart = qb * 64 - WIN; if (kstart < 0) kstart = 0;
    for (int k0 = kstart; k0 <= qb * 64; k0 += 64) {
        __syncthreads();
        for (int i = tid; i < 64 * 32; i += 128) {
            int row = i >> 5, p2 = (i & 31) * 2;
            size_t kr = ((size_t)(b * TT + k0 + row)) * KVW + kvh * DH;
            *(__nv_bfloat162*)&Ks[row * 72 + p2] = *(const __nv_bfloat162*)&Kb[kr + p2];
            *(__nv_bfloat162*)&Vs[row * 72 + p2] = *(const __nv_bfloat162*)&Vb[kr + p2];
        }
        __syncthreads();

        float s[8][4];
#pragma unroll
        for (int j = 0; j < 8; j++) {
            s[j][0] = s[j][1] = s[j][2] = s[j][3] = 0.f;
#pragma unroll
            for (int kk = 0; kk < 4; kk++) {
                uint32_t bfr[2];
                uint32_t bd = su32(&Ks[(j * 8 + rn) * 72 + kk * 16 + knh * 8]);
                asm volatile("ldmatrix.sync.aligned.m8n8.x2.shared.b16 {%0,%1}, [%2];"
                    : "=r"(bfr[0]), "=r"(bfr[1]) : "r"(bd));
                asm volatile(
                    "mma.sync.aligned.m16n8k16.row.col.f32.bf16.bf16.f32 "
                    "{%0,%1,%2,%3}, {%4,%5,%6,%7}, {%8,%9}, {%0,%1,%2,%3};"
                    : "+f"(s[j][0]), "+f"(s[j][1]), "+f"(s[j][2]), "+f"(s[j][3])
                    : "r"(qf[kk][0]), "r"(qf[kk][1]), "r"(qf[kk][2]), "r"(qf[kk][3]),
                      "r"(bfr[0]), "r"(bfr[1]));
            }
        }
#pragma unroll
        for (int j = 0; j < 8; j++) {
            int kg = k0 + j * 8 + cq;
            if (kg > t0 || kg < t0 - WIN) s[j][0] = -1e30f;
            if (kg + 1 > t0 || kg + 1 < t0 - WIN) s[j][1] = -1e30f;
            if (kg > t0 + 8 || kg < t0 + 8 - WIN) s[j][2] = -1e30f;
            if (kg + 1 > t0 + 8 || kg + 1 < t0 + 8 - WIN) s[j][3] = -1e30f;
        }
        float mx0 = -1e30f, mx1 = -1e30f;
#pragma unroll
        for (int j = 0; j < 8; j++) {
            mx0 = fmaxf(mx0, fmaxf(s[j][0], s[j][1]));
            mx1 = fmaxf(mx1, fmaxf(s[j][2], s[j][3]));
        }
        mx0 = fmaxf(mx0, __shfl_xor_sync(0xffffffffu, mx0, 1));
        mx0 = fmaxf(mx0, __shfl_xor_sync(0xffffffffu, mx0, 2));
        mx1 = fmaxf(mx1, __shfl_xor_sync(0xffffffffu, mx1, 1));
        mx1 = fmaxf(mx1, __shfl_xor_sync(0xffffffffu, mx1, 2));
        float mn0 = fmaxf(m0, mx0), mn1 = fmaxf(m1, mx1);
        float c0 = __expf(m0 - mn0), c1 = __expf(m1 - mn1);
        m0 = mn0; m1 = mn1;
        l0 *= c0; l1 *= c1;
#pragma unroll
        for (int dn = 0; dn < 8; dn++) {
            acc[dn][0] *= c0; acc[dn][1] *= c0;
            acc[dn][2] *= c1; acc[dn][3] *= c1;
        }
#pragma unroll
        for (int j = 0; j < 8; j++) {
            s[j][0] = __expf(s[j][0] - m0); s[j][1] = __expf(s[j][1] - m0);
            s[j][2] = __expf(s[j][2] - m1); s[j][3] = __expf(s[j][3] - m1);
            l0 += s[j][0] + s[j][1];
            l1 += s[j][2] + s[j][3];
        }
        uint32_t pa[4][4];
#pragma unroll
        for (int kk = 0; kk < 4; kk++) {
            int j0 = kk * 2, j1 = kk * 2 + 1;
            pa[kk][0] = packbf(s[j0][0], s[j0][1]);
            pa[kk][1] = packbf(s[j0][2], s[j0][3]);
            pa[kk][2] = packbf(s[j1][0], s[j1][1]);
            pa[kk][3] = packbf(s[j1][2], s[j1][3]);
        }
#pragma unroll
        for (int dn = 0; dn < 8; dn++)
#pragma unroll
            for (int kk = 0; kk < 4; kk++) {
                uint32_t bfr[2];
                uint32_t bd = su32(&Vs[(kk * 16 + knh * 8 + rn) * 72 + dn * 8]);
                asm volatile("ldmatrix.sync.aligned.m8n8.x2.trans.shared.b16 {%0,%1}, [%2];"
                    : "=r"(bfr[0]), "=r"(bfr[1]) : "r"(bd));
                asm volatile(
                    "mma.sync.aligned.m16n8k16.row.col.f32.bf16.bf16.f32 "
                    "{%0,%1,%2,%3}, {%4,%5,%6,%7}, {%8,%9}, {%0,%1,%2,%3};"
                    : "+f"(acc[dn][0]), "+f"(acc[dn][1]), "+f"(acc[dn][2]), "+f"(acc[dn][3])
                    : "r"(pa[kk][0]), "r"(pa[kk][1]), "r"(pa[kk][2]), "r"(pa[kk][3]),
                      "r"(bfr[0]), "r"(bfr[1]));
            }
    }
    l0 += __shfl_xor_sync(0xffffffffu, l0, 1);
    l0 += __shfl_xor_sync(0xffffffffu, l0, 2);
    l1 += __shfl_xor_sync(0xffffffffu, l1, 1);
    l1 += __shfl_xor_sync(0xffffffffu, l1, 2);
    float i0 = 1.f / l0, i1 = 1.f / l1;
    __nv_bfloat16* o0 = O + ((size_t)(b * TT + t0)) * CC + h * DH;
    __nv_bfloat16* o1 = o0 + (size_t)8 * CC;
#pragma unroll
    for (int dn = 0; dn < 8; dn++) {
        *(__nv_bfloat162*)&o0[dn * 8 + cq] =
            __floats2bfloat162_rn(acc[dn][0] * i0, acc[dn][1] * i0);
        *(__nv_bfloat162*)&o1[dn * 8 + cq] =
            __floats2bfloat162_rn(acc[dn][2] * i1, acc[dn][3] * i1);
    }
}

// ---------------- router ----------------
__global__ void route_kernel(const float* __restrict__ xf,
                             const float* __restrict__ gw) {
    int warp = threadIdx.x >> 5, lane = threadIdx.x & 31;
    int tok = blockIdx.x * 4 + warp;
    if (tok >= NTOK) return;
    const float* xr = xf + (size_t)tok * CC;
    float part[EE];
#pragma unroll
    for (int e = 0; e < EE; e++) part[e] = 0.f;
    for (int d = lane; d < CC; d += 32) {
        float xv = xr[d];
#pragma unroll
        for (int e = 0; e < EE; e++) part[e] += xv * gw[d * EE + e];
    }
#pragma unroll
    for (int e = 0; e < EE; e++)
#pragma unroll
        for (int o = 16; o > 0; o >>= 1)
            part[e] += __shfl_xor_sync(0xffffffffu, part[e], o);
    if (lane == 0) {
        float v0 = -1e30f; int i0 = 0;
#pragma unroll
        for (int e = 0; e < EE; e++) if (part[e] > v0) { v0 = part[e]; i0 = e; }
        float v1 = -1e30f; int i1 = 0;
#pragma unroll
        for (int e = 0; e < EE; e++)
            if (e != i0 && part[e] > v1) { v1 = part[e]; i1 = e; }
        float ex = expf(v1 - v0);
        float w0 = 1.f / (1.f + ex);
        float w1 = ex / (1.f + ex);
        g_sel[tok * 2] = i0; g_sel[tok * 2 + 1] = i1;
        g_selw[tok * 2] = w0; g_selw[tok * 2 + 1] = w1;
        float mx = v0, sum = 0.f, pe[EE];
#pragma unroll
        for (int e = 0; e < EE; e++) { pe[e] = expf(part[e] - mx); sum += pe[e]; }
#pragma unroll
        for (int e = 0; e < EE; e++) g_probs[tok * EE + e] = pe[e] / sum;
        float lse = mx + logf(sum);
        g_lse2[tok] = lse * lse;
    }
}

// ---------------- aux loss ----------------
__global__ void aux_kernel() {
    __shared__ float red[256];
    int tid = threadIdx.x;
    float loadv[EE];
#pragma unroll
    for (int e = 0; e < EE; e++) loadv[e] = 0.f;
    for (int n = tid; n < NTOK; n += 256) {
#pragma unroll
        for (int e = 0; e < EE; e++) loadv[e] += g_probs[n * EE + e];
    }
    float loads[EE];
    for (int e = 0; e < EE; e++) {
        red[tid] = loadv[e]; __syncthreads();
        for (int o = 128; o > 0; o >>= 1) {
            if (tid < o) red[tid] += red[tid + o];
            __syncthreads();
        }
        loads[e] = red[0]; __syncthreads();
    }
    float zp = 0.f;
    for (int n = tid; n < NTOK; n += 256) zp += g_lse2[n];
    red[tid] = zp; __syncthreads();
    for (int o = 128; o > 0; o >>= 1) {
        if (tid < o) red[tid] += red[tid + o];
        __syncthreads();
    }
    if (tid == 0) {
        float tot = 0.f;
        for (int e = 0; e < EE; e++) tot += loads[e];
        float lb = 0.f;
        for (int e = 0; e < EE; e++) { float f = loads[e] / tot; lb += f * f; }
        lb *= (float)EE;
        float z = red[0] / (float)NTOK;
        g_aux = 0.01f * lb + 0.001f * z;
    }
}

__global__ void zero_cnt_kernel() { if (threadIdx.x < EE) g_cnt[threadIdx.x] = 0; }

__global__ void count_kernel() {
    int i = blockIdx.x * blockDim.x + threadIdx.x;
    if (i >= NTOK) return;
#pragma unroll
    for (int kk = 0; kk < TOPK; kk++)
        atomicAdd(&g_cnt[g_sel[i * 2 + kk]], 1);
}

__global__ void offsets_kernel() {
    if (threadIdx.x == 0) {
        int acc = 0;
        for (int e = 0; e < EE; e++) {
            g_off[e] = acc;
            acc += (g_cnt[e] + BM - 1) & ~(BM - 1);
            g_cnt2[e] = 0;
        }
        g_off[EE] = acc;
    }
}

__global__ void assign_kernel() {
    int i = blockIdx.x * blockDim.x + threadIdx.x;
    if (i >= NTOK) return;
#pragma unroll
    for (int kk = 0; kk < TOPK; kk++) {
        int e = g_sel[i * 2 + kk];
        int pos = atomicAdd(&g_cnt2[e], 1);
        int row = g_off[e] + pos;
        g_idx[row] = i;
        g_tokrow[i * 2 + kk] = row;
    }
}

__global__ void gather_all_kernel(__nv_bfloat16* __restrict__ dst,
                                  const __nv_bfloat16* __restrict__ src) {
    int b = blockIdx.x;
    if (b >= g_off[EE]) return;
    int e = 0;
    while (g_off[e + 1] <= b) e++;
    if (b - g_off[e] >= g_cnt[e]) return;
    int t = g_idx[b];
    uint4* d4 = (uint4*)(dst + (size_t)b * CC);
    const uint4* s4 = (const uint4*)(src + (size_t)t * CC);
    int i = threadIdx.x;
    if (i < CC * 2 / 16) d4[i] = s4[i];
}

// final: out = h + a_moe * (shared + w0*eo[r0] + w1*eo[r1])
__global__ void final_kernel(const float* __restrict__ h, const float* __restrict__ moe,
                             const float* __restrict__ eo,
                             const float* __restrict__ alpha, float* __restrict__ out) {
    int t = blockIdx.x;
    float w0 = g_selw[t * 2], w1 = g_selw[t * 2 + 1];
    int r0 = g_tokrow[t * 2], r1 = g_tokrow[t * 2 + 1];
    float a = *alpha;
    const float* hr = h + (size_t)t * CC;
    const float* mr = moe + (size_t)t * CC;
    const float* e0 = eo + (size_t)r0 * CC;
    const float* e1 = eo + (size_t)r1 * CC;
    float* orow = out + (size_t)t * CC;
    for (int i = threadIdx.x; i < CC; i += blockDim.x)
        orow[i] = hr[i] + a * (mr[i] + w0 * e0[i] + w1 * e1[i]);
}

__global__ void auxwrite_kernel(float* __restrict__ out) { out[OUT_MAIN] = g_aux; }

// ---------------- launch ----------------
extern "C" void kernel_launch(void* const* d_in, const int* in_sizes, int n_in,
                              void* d_out, int out_size) {
    const float* x      = (const float*)d_in[0];
    const float* ln1    = (const float*)d_in[1];
    const float* ln2    = (const float*)d_in[2];
    const float* wq     = (const float*)d_in[3];
    const float* wk     = (const float*)d_in[4];
    const float* wv     = (const float*)d_in[5];
    const float* wo     = (const float*)d_in[6];
    const float* sw1    = (const float*)d_in[7];
    const float* sw2    = (const float*)d_in[8];
    const float* sw3    = (const float*)d_in[9];
    const float* ew1    = (const float*)d_in[10];
    const float* ew2    = (const float*)d_in[11];
    const float* ew3    = (const float*)d_in[12];
    const float* gatew  = (const float*)d_in[13];
    const float* a_attn = (const float*)d_in[14];
    const float* a_moe  = (const float*)d_in[15];
    float* out = (float*)d_out;

    void* p;
    float *qkv, *h, *xf, *moe, *eo;
    __nv_bfloat16 *xnb, *aob, *xfb, *xgb, *g1b, *kb, *vb;
    __nv_bfloat16 *wqkvt, *wot, *sw12t, *sw3t, *ew12t, *ew3t;
    cudaGetSymbolAddress(&p, g_qkv);  qkv  = (float*)p;
    cudaGetSymbolAddress(&p, g_h);    h    = (float*)p;
    cudaGetSymbolAddress(&p, g_xf);   xf   = (float*)p;
    cudaGetSymbolAddress(&p, g_moe);  moe  = (float*)p;
    cudaGetSymbolAddress(&p, g_eo);   eo   = (float*)p;
    cudaGetSymbolAddress(&p, g_xnb);  xnb  = (__nv_bfloat16*)p;
    cudaGetSymbolAddress(&p, g_aob);  aob  = (__nv_bfloat16*)p;
    cudaGetSymbolAddress(&p, g_xfb);  xfb  = (__nv_bfloat16*)p;
    cudaGetSymbolAddress(&p, g_xgb);  xgb  = (__nv_bfloat16*)p;
    cudaGetSymbolAddress(&p, g_g1b);  g1b  = (__nv_bfloat16*)p;
    cudaGetSymbolAddress(&p, g_kb);   kb   = (__nv_bfloat16*)p;
    cudaGetSymbolAddress(&p, g_vb);   vb   = (__nv_bfloat16*)p;
    cudaGetSymbolAddress(&p, g_wqkvt); wqkvt = (__nv_bfloat16*)p;
    cudaGetSymbolAddress(&p, g_wot);   wot   = (__nv_bfloat16*)p;
    cudaGetSymbolAddress(&p, g_sw12t); sw12t = (__nv_bfloat16*)p;
    cudaGetSymbolAddress(&p, g_sw3t);  sw3t  = (__nv_bfloat16*)p;
    cudaGetSymbolAddress(&p, g_ew12t); ew12t = (__nv_bfloat16*)p;
    cudaGetSymbolAddress(&p, g_ew3t);  ew3t  = (__nv_bfloat16*)p;

    static bool s_init = false;
    static cudaStream_t s2 = 0;
    static cudaEvent_t evA = 0, evB = 0, evC = 0, evD = 0;
    if (!s_init) {
        if (cudaStreamCreateWithFlags(&s2, cudaStreamNonBlocking) != cudaSuccess) s2 = 0;
        if (s2) {
            bool ok = true;
            ok &= (cudaEventCreateWithFlags(&evA, cudaEventDisableTiming) == cudaSuccess);
            ok &= (cudaEventCreateWithFlags(&evB, cudaEventDisableTiming) == cudaSuccess);
            ok &= (cudaEventCreateWithFlags(&evC, cudaEventDisableTiming) == cudaSuccess);
            ok &= (cudaEventCreateWithFlags(&evD, cudaEventDisableTiming) == cudaSuccess);
            if (!ok) s2 = 0;
        }
        s_init = true;
    }
    bool forked = (s2 != 0);

    // streaming weight conversions (K-major, no transpose)
    wcvt<<<512, 256>>>(wq, wqkvt, CC, QKVN, 0, 0, 0, (long)CC*CC/8);
    wcvt<<<128, 256>>>(wk, wqkvt, KVW, QKVN, CC, 0, 0, (long)CC*KVW/8);
    wcvt<<<128, 256>>>(wv, wqkvt, KVW, QKVN, CC+KVW, 0, 0, (long)CC*KVW/8);
    wcvt<<<512, 256>>>(wo, wot, CC, CC, 0, 0, 0, (long)CC*CC/8);
    wcvt_pair<<<4096, 256>>>(sw1, sw2, sw12t, FF, 0, 0, (long)CC*FF/4);
    wcvt<<<2048, 256>>>(sw3, sw3t, CC, CC, 0, 0, 0, (long)FF*CC/8);

    // expert conversions forked onto s2 (overlaps attention-side compute)
    if (forked) {
        cudaEventRecord(evA, 0);
        cudaStreamWaitEvent(s2, evA, 0);
        wcvt_pair<<<dim3(4096,1,EE), 256, 0, s2>>>(ew1, ew2, ew12t, FF,
            (long)CC*FF, (long)CC*2*FF, (long)CC*FF/4);
        wcvt<<<dim3(2048,1,EE), 256, 0, s2>>>(ew3, ew3t, CC, CC, 0,
            (long)FF*CC, (long)FF*CC, (long)FF*CC/8);
        cudaEventRecord(evB, s2);
    } else {
        wcvt_pair<<<dim3(4096,1,EE), 256>>>(ew1, ew2, ew12t, FF,
            (long)CC*FF, (long)CC*2*FF, (long)CC*FF/4);
        wcvt<<<dim3(2048,1,EE), 256>>>(ew3, ew3t, CC, CC, 0,
            (long)FF*CC, (long)FF*CC, (long)FF*CC/8);
    }

    // 1) pre-attn norm
    rmsnorm_kernel<<<NTOK, 256>>>(x, ln1, nullptr, xnb);
    // 2) fused QKV projection
    gemm_mma<<<dim3(QKVN/128, NTOK/128), 256>>>(xnb, wqkvt, qkv, QKVN, CC);
    // 3) fused RoPE(q,k) + K/V bf16 compaction (1 kernel)
    {
        int total = NTOK*HH*32 + NTOK*KVH*32 + NTOK*(KVW/2);
        rope_all_kernel<<<(total + 255) / 256, 256>>>(qkv, kb, vb);
    }
    // 4) attention (tensor core, 64-row Q tiles, bf16 K/V, trans-V)
    attn_mma<<<dim3(TT/64, HH, BB), 128>>>(qkv, kb, vb, aob);
    // 5) output projection with fused ReZero residual
    gemm_mma_add<<<dim3(CC/128, NTOK/128), 256>>>(aob, wot, x, a_attn, h, CC, CC);
    // 6) post-attn norm
    rmsnorm_kernel<<<NTOK, 256>>>(h, ln2, xf, xfb);
    // 7) routing + aux + compaction — forked onto s2, overlapped with shared GEMMs
    if (forked) {
        cudaEventRecord(evC, 0);
        cudaStreamWaitEvent(s2, evC, 0);
        route_kernel<<<NTOK / 4, 128, 0, s2>>>(xf, gatew);
        aux_kernel<<<1, 256, 0, s2>>>();
        zero_cnt_kernel<<<1, 32, 0, s2>>>();
        count_kernel<<<(NTOK + 255) / 256, 256, 0, s2>>>();
        offsets_kernel<<<1, 32, 0, s2>>>();
        assign_kernel<<<(NTOK + 255) / 256, 256, 0, s2>>>();
        cudaEventRecord(evD, s2);
    } else {
        route_kernel<<<NTOK / 4, 128>>>(xf, gatew);
        aux_kernel<<<1, 256>>>();
        zero_cnt_kernel<<<1, 32>>>();
        count_kernel<<<(NTOK + 255) / 256, 256>>>();
        offsets_kernel<<<1, 32>>>();
        assign_kernel<<<(NTOK + 255) / 256, 256>>>();
    }
    // 8) shared expert: fused w12+SwiGLU, then w3 (overlaps routing branch)
    gemm_swiglu<<<dim3(2*FF/128, NTOK/128), 256>>>(xfb, sw12t, g1b, 2*FF, CC);
    gemm_mma<<<dim3(CC/128, NTOK/128), 256>>>(g1b, sw3t, moe, CC, FF);
    // 9) routed experts, batched (join routing + expert weights first)
    if (forked) cudaStreamWaitEvent(0, evD, 0);
    gather_all_kernel<<<ECAP, 128>>>(xgb, xfb);
    if (forked) cudaStreamWaitEvent(0, evB, 0);
    gemm_moe_swiglu<<<dim3(2*FF/128, ECAP/128), 256>>>(xgb, ew12t, g1b, 2*FF, CC, (long)CC*2*FF);
    gemm_moe<<<dim3(CC/128, ECAP/128), 256>>>(g1b, ew3t, eo, CC, FF, (long)FF*CC);
    // 10) final combine + aux scalar
    final_kernel<<<NTOK, 256>>>(h, moe, eo, a_moe, out);
    if (out_size > OUT_MAIN) auxwrite_kernel<<<1, 1>>>(out);
}

// round 12
// speedup vs baseline: 1.2432x; 1.0140x over previous
#include <cuda_runtime.h>
#include <cuda_bf16.h>
#include <math.h>
#include <stdint.h>

// Problem constants
#define BB   2
#define TT   2048
#define CC   1024
#define HH   16
#define KVH  4
#define DH   64
#define NREP 4
#define FF   4096
#define EE   8
#define TOPK 2
#define WIN  1024
#define NTOK (BB*TT)            // 4096
#define OUT_MAIN (NTOK*CC)      // 4194304
#define QKVN (CC + 2*KVH*DH)    // 1536
#define KVW  (KVH*DH)           // 256
#define ECAP 9216               // 8192 real rows + padding, 128-aligned

// ---------------- scratch (device globals; no allocation) ----------------
__device__ float g_qkv [NTOK*QKVN];
__device__ float g_h   [NTOK*CC];
__device__ float g_xf  [NTOK*CC];
__device__ float g_moe [NTOK*CC];
__device__ float g_eo  [(size_t)ECAP*CC];
__device__ float g_probs[NTOK*EE];
__device__ float g_lse2[NTOK];
__device__ int   g_sel [NTOK*2];
__device__ float g_selw[NTOK*2];
__device__ int   g_cnt [EE];
__device__ int   g_cnt2[EE];
__device__ int   g_off [EE+1];
__device__ int   g_idx [ECAP];
__device__ int   g_tokrow[NTOK*2];
__device__ float g_aux;

// bf16 activations
__device__ __nv_bfloat16 g_xnb [NTOK*CC];
__device__ __nv_bfloat16 g_qb  [NTOK*CC];
__device__ __nv_bfloat16 g_aob [NTOK*CC];
__device__ __nv_bfloat16 g_xfb [NTOK*CC];
__device__ __nv_bfloat16 g_xgb [(size_t)ECAP*CC];
__device__ __nv_bfloat16 g_g1b [(size_t)ECAP*FF];
__device__ __nv_bfloat16 g_kb  [NTOK*KVW];
__device__ __nv_bfloat16 g_vb  [NTOK*KVW];

// bf16 weights, K-major [K,N] (w12 column-interleaved: w1->2f, w2->2f+1)
__device__ __nv_bfloat16 g_wqkvt[CC*QKVN];
__device__ __nv_bfloat16 g_wot  [CC*CC];
__device__ __nv_bfloat16 g_sw12t[CC*2*FF];
__device__ __nv_bfloat16 g_sw3t [FF*CC];
__device__ __nv_bfloat16 g_ew12t[(size_t)EE*CC*2*FF];
__device__ __nv_bfloat16 g_ew3t [(size_t)EE*FF*CC];

__device__ __forceinline__ uint32_t su32(const void* p) {
    uint32_t a;
    asm("{ .reg .u64 t; cvta.to.shared.u64 t, %1; cvt.u32.u64 %0, t; }" : "=r"(a) : "l"(p));
    return a;
}
__device__ __forceinline__ uint32_t packbf(float a, float b) {
    __nv_bfloat162 t = __floats2bfloat162_rn(a, b);
    return *(uint32_t*)&t;
}

#define CP_ASYNC16(d, s) asm volatile("cp.async.cg.shared.global [%0], [%1], 16;" :: "r"(d), "l"(s))
#define CP_COMMIT()      asm volatile("cp.async.commit_group;" ::: "memory")
#define CP_WAIT(n)       asm volatile("cp.async.wait_group %0;" :: "n"(n) : "memory")

#define BM 128
#define BN 128
#define BK 32
#define ASTR 40    // A smem row stride (bf16 elems)
#define BSTR 136   // B smem row stride (bf16 elems)

// ================= 2-stage GEMM mainloop; B is [K,N] via ldmatrix.x4.trans
#define GEMM_MAIN(A_, Bt_, N_, K_)                                             \
    __shared__ __align__(16) __nv_bfloat16 sA[2][BM * ASTR];                   \
    __shared__ __align__(16) __nv_bfloat16 sB[2][BK * BSTR];                   \
    int tid = threadIdx.x;                                                     \
    int wid = tid >> 5, lane = tid & 31;                                       \
    int wm = wid >> 2, wn = wid & 3;                                           \
    float cr[4][4][4];                                                         \
    _Pragma("unroll") for (int i = 0; i < 4; i++)                              \
    _Pragma("unroll") for (int j = 0; j < 4; j++)                              \
    _Pragma("unroll") for (int r = 0; r < 4; r++) cr[i][j][r] = 0.f;           \
    int lrow = tid >> 1;                                                       \
    int lc16 = (tid & 1) * 16;                                                 \
    int nCh = (K_) / BK;                                                       \
    {                                                                          \
        const __nv_bfloat16* srcA0 = (A_) + (size_t)(rowBase + lrow) * (K_) + lc16; \
        uint32_t dA0 = su32(&sA[0][lrow * ASTR + lc16]);                       \
        CP_ASYNC16(dA0, srcA0); CP_ASYNC16(dA0 + 16, srcA0 + 8);               \
        _Pragma("unroll") for (int bi = 0; bi < 2; bi++) {                     \
            int seg = tid + bi * 256;                                          \
            int brow = seg >> 4, bcol = (seg & 15) * 8;                        \
            const __nv_bfloat16* srcB = (Bt_) + (size_t)brow * (N_) + colBase + bcol; \
            CP_ASYNC16(su32(&sB[0][brow * BSTR + bcol]), srcB);                \
        }                                                                      \
        CP_COMMIT();                                                           \
    }                                                                          \
    for (int ch = 0; ch < nCh; ch++) {                                         \
        int st = ch & 1;                                                       \
        if (ch + 1 < nCh) {                                                    \
            int k0 = (ch + 1) * BK;                                            \
            const __nv_bfloat16* srcA = (A_) + (size_t)(rowBase + lrow) * (K_) + k0 + lc16; \
            uint32_t dA = su32(&sA[st ^ 1][lrow * ASTR + lc16]);               \
            CP_ASYNC16(dA, srcA); CP_ASYNC16(dA + 16, srcA + 8);               \
            _Pragma("unroll") for (int bi = 0; bi < 2; bi++) {                 \
                int seg = tid + bi * 256;                                      \
                int brow = seg >> 4, bcol = (seg & 15) * 8;                    \
                const __nv_bfloat16* srcB = (Bt_) + (size_t)(k0 + brow) * (N_) + colBase + bcol; \
                CP_ASYNC16(su32(&sB[st ^ 1][brow * BSTR + bcol]), srcB);       \
            }                                                                  \
            CP_COMMIT(); CP_WAIT(1);                                           \
        } else { CP_WAIT(0); }                                                 \
        __syncthreads();                                                       \
        int r16 = lane & 15, kh = lane >> 4;                                   \
        int brl = (lane & 7) + ((lane >> 3) & 1) * 8;   /* row within 16 */    \
        int bcl = ((lane >> 4) & 1) * 8;                /* col half */         \
        _Pragma("unroll") for (int kk = 0; kk < 2; kk++) {                     \
            uint32_t af[4][4];                                                 \
            _Pragma("unroll") for (int mf = 0; mf < 4; mf++) {                 \
                uint32_t ad = su32(&sA[st][(wm * 64 + mf * 16 + r16) * ASTR + kk * 16 + kh * 8]); \
                asm volatile("ldmatrix.sync.aligned.m8n8.x4.shared.b16 {%0,%1,%2,%3}, [%4];" \
                    : "=r"(af[mf][0]), "=r"(af[mf][1]), "=r"(af[mf][2]), "=r"(af[mf][3]) : "r"(ad)); \
            }                                                                  \
            uint32_t bfr[4][2];                                                \
            _Pragma("unroll") for (int nfp = 0; nfp < 2; nfp++) {              \
                uint32_t bd = su32(&sB[st][(kk * 16 + brl) * BSTR + wn * 32 + nfp * 16 + bcl]); \
                asm volatile("ldmatrix.sync.aligned.m8n8.x4.trans.shared.b16 {%0,%1,%2,%3}, [%4];" \
                    : "=r"(bfr[2*nfp][0]), "=r"(bfr[2*nfp][1]),                \
                      "=r"(bfr[2*nfp+1][0]), "=r"(bfr[2*nfp+1][1]) : "r"(bd)); \
            }                                                                  \
            _Pragma("unroll") for (int mf = 0; mf < 4; mf++)                   \
            _Pragma("unroll") for (int nf = 0; nf < 4; nf++) {                 \
                asm volatile(                                                  \
                    "mma.sync.aligned.m16n8k16.row.col.f32.bf16.bf16.f32 "     \
                    "{%0,%1,%2,%3}, {%4,%5,%6,%7}, {%8,%9}, {%0,%1,%2,%3};"    \
                    : "+f"(cr[mf][nf][0]), "+f"(cr[mf][nf][1]),                \
                      "+f"(cr[mf][nf][2]), "+f"(cr[mf][nf][3])                 \
                    : "r"(af[mf][0]), "r"(af[mf][1]), "r"(af[mf][2]), "r"(af[mf][3]), \
                      "r"(bfr[nf][0]), "r"(bfr[nf][1]));                       \
            }                                                                  \
        }                                                                      \
        __syncthreads();                                                       \
    }                                                                          \
    int rr = lane >> 2, cq = (lane & 3) * 2;

// ================= dense GEMM, fp32 out =================
__global__ __launch_bounds__(256) void gemm_mma(
    const __nv_bfloat16* __restrict__ A, const __nv_bfloat16* __restrict__ Bt,
    float* __restrict__ C, int N, int K)
{
    int rowBase = blockIdx.y * BM, colBase = blockIdx.x * BN;
    GEMM_MAIN(A, Bt, N, K)
#pragma unroll
    for (int mf = 0; mf < 4; mf++)
#pragma unroll
        for (int nf = 0; nf < 4; nf++) {
            int row0 = rowBase + wm * 64 + mf * 16 + rr;
            int col = colBase + wn * 32 + nf * 8 + cq;
            *(float2*)&C[(size_t)row0 * N + col] = make_float2(cr[mf][nf][0], cr[mf][nf][1]);
            *(float2*)&C[(size_t)(row0 + 8) * N + col] = make_float2(cr[mf][nf][2], cr[mf][nf][3]);
        }
}

// ===== dense GEMM with fused ReZero residual: C = X + (*alpha)*(A@Bt) ====
__global__ __launch_bounds__(256) void gemm_mma_add(
    const __nv_bfloat16* __restrict__ A, const __nv_bfloat16* __restrict__ Bt,
    const float* __restrict__ X, const float* __restrict__ alpha,
    float* __restrict__ C, int N, int K)
{
    int rowBase = blockIdx.y * BM, colBase = blockIdx.x * BN;
    GEMM_MAIN(A, Bt, N, K)
    float a = *alpha;
#pragma unroll
    for (int mf = 0; mf < 4; mf++)
#pragma unroll
        for (int nf = 0; nf < 4; nf++) {
            int row0 = rowBase + wm * 64 + mf * 16 + rr;
            int col = colBase + wn * 32 + nf * 8 + cq;
            float2 x0 = *(const float2*)&X[(size_t)row0 * N + col];
            float2 x1 = *(const float2*)&X[(size_t)(row0 + 8) * N + col];
            *(float2*)&C[(size_t)row0 * N + col] =
                make_float2(x0.x + a * cr[mf][nf][0], x0.y + a * cr[mf][nf][1]);
            *(float2*)&C[(size_t)(row0 + 8) * N + col] =
                make_float2(x1.x + a * cr[mf][nf][2], x1.y + a * cr[mf][nf][3]);
        }
}

// ================= dense GEMM, fused SwiGLU bf16 out (interleaved w12) ===
__global__ __launch_bounds__(256) void gemm_swiglu(
    const __nv_bfloat16* __restrict__ A, const __nv_bfloat16* __restrict__ Bt,
    __nv_bfloat16* __restrict__ Obf, int N2, int K)
{
    int rowBase = blockIdx.y * BM, colBase = blockIdx.x * BN;
    GEMM_MAIN(A, Bt, N2, K)
    int FFo = N2 >> 1;
#pragma unroll
    for (int mf = 0; mf < 4; mf++)
#pragma unroll
        for (int nf = 0; nf < 4; nf++) {
            int row0 = rowBase + wm * 64 + mf * 16 + rr;
            int f = (colBase + wn * 32 + nf * 8 + cq) >> 1;
            float a0 = cr[mf][nf][0], b0 = cr[mf][nf][1];
            Obf[(size_t)row0 * FFo + f] = __float2bfloat16(a0 / (1.f + __expf(-a0)) * b0);
            float a1 = cr[mf][nf][2], b1 = cr[mf][nf][3];
            Obf[(size_t)(row0 + 8) * FFo + f] = __float2bfloat16(a1 / (1.f + __expf(-a1)) * b1);
        }
}

// ================= MoE GEMM, fp32 out =================
__global__ __launch_bounds__(256) void gemm_moe(
    const __nv_bfloat16* __restrict__ A, const __nv_bfloat16* __restrict__ Wb,
    float* __restrict__ C, int N, int K, long wstride)
{
    int rowBase = blockIdx.y * BM;
    if (rowBase >= g_off[EE]) return;
    int colBase = blockIdx.x * BN;
    int e = 0;
    while (g_off[e + 1] <= rowBase) e++;
    const __nv_bfloat16* Bt = Wb + (size_t)e * wstride;
    GEMM_MAIN(A, Bt, N, K)
#pragma unroll
    for (int mf = 0; mf < 4; mf++)
#pragma unroll
        for (int nf = 0; nf < 4; nf++) {
            int row0 = rowBase + wm * 64 + mf * 16 + rr;
            int col = colBase + wn * 32 + nf * 8 + cq;
            *(float2*)&C[(size_t)row0 * N + col] = make_float2(cr[mf][nf][0], cr[mf][nf][1]);
            *(float2*)&C[(size_t)(row0 + 8) * N + col] = make_float2(cr[mf][nf][2], cr[mf][nf][3]);
        }
}

// ================= MoE GEMM, fused SwiGLU bf16 out =================
__global__ __launch_bounds__(256) void gemm_moe_swiglu(
    const __nv_bfloat16* __restrict__ A, const __nv_bfloat16* __restrict__ Wb,
    __nv_bfloat16* __restrict__ Obf, int N2, int K, long wstride)
{
    int rowBase = blockIdx.y * BM;
    if (rowBase >= g_off[EE]) return;
    int colBase = blockIdx.x * BN;
    int e = 0;
    while (g_off[e + 1] <= rowBase) e++;
    const __nv_bfloat16* Bt = Wb + (size_t)e * wstride;
    GEMM_MAIN(A, Bt, N2, K)
    int FFo = N2 >> 1;
#pragma unroll
    for (int mf = 0; mf < 4; mf++)
#pragma unroll
        for (int nf = 0; nf < 4; nf++) {
            int row0 = rowBase + wm * 64 + mf * 16 + rr;
            int f = (colBase + wn * 32 + nf * 8 + cq) >> 1;
            float a0 = cr[mf][nf][0], b0 = cr[mf][nf][1];
            Obf[(size_t)row0 * FFo + f] = __float2bfloat16(a0 / (1.f + __expf(-a0)) * b0);
            float a1 = cr[mf][nf][2], b1 = cr[mf][nf][3];
            Obf[(size_t)(row0 + 8) * FFo + f] = __float2bfloat16(a1 / (1.f + __expf(-a1)) * b1);
        }
}

// ---------------- streaming weight convert: [K,NWs] f32 -> [K,NWd] bf16 --
__global__ void wcvt(const float* __restrict__ src, __nv_bfloat16* __restrict__ dst,
                     int NWs, int NWd, int coff, long sstride, long dstride, long total8) {
    long i = (long)blockIdx.x * blockDim.x + threadIdx.x;
    if (i >= total8) return;
    long e = i * 8;
    int k = (int)(e / NWs);
    int n = (int)(e - (long)k * NWs);
    const float* s = src + (size_t)blockIdx.z * sstride + (size_t)k * NWs + n;
    float4 v0 = *(const float4*)s;
    float4 v1 = *(const float4*)(s + 4);
    __nv_bfloat16 o[8];
    o[0] = __float2bfloat16(v0.x); o[1] = __float2bfloat16(v0.y);
    o[2] = __float2bfloat16(v0.z); o[3] = __float2bfloat16(v0.w);
    o[4] = __float2bfloat16(v1.x); o[5] = __float2bfloat16(v1.y);
    o[6] = __float2bfloat16(v1.z); o[7] = __float2bfloat16(v1.w);
    *(uint4*)&dst[(size_t)blockIdx.z * dstride + (size_t)k * NWd + coff + n] = *(uint4*)o;
}

// ---------------- streaming pair convert: w1,w2 [K,NW] -> [K,2NW] interleaved
__global__ void wcvt_pair(const float* __restrict__ s1, const float* __restrict__ s2,
                          __nv_bfloat16* __restrict__ dst,
                          int NW, long sstride, long dstride, long total4) {
    long i = (long)blockIdx.x * blockDim.x + threadIdx.x;
    if (i >= total4) return;
    long e = i * 4;
    int k = (int)(e / NW);
    int f = (int)(e - (long)k * NW);
    size_t so = (size_t)blockIdx.z * sstride + (size_t)k * NW + f;
    float4 va = *(const float4*)(s1 + so);
    float4 vb = *(const float4*)(s2 + so);
    __nv_bfloat16 o[8];
    o[0] = __float2bfloat16(va.x); o[1] = __float2bfloat16(vb.x);
    o[2] = __float2bfloat16(va.y); o[3] = __float2bfloat16(vb.y);
    o[4] = __float2bfloat16(va.z); o[5] = __float2bfloat16(vb.z);
    o[6] = __float2bfloat16(va.w); o[7] = __float2bfloat16(vb.w);
    *(uint4*)&dst[(size_t)blockIdx.z * dstride + (size_t)k * (2 * NW) + 2 * f] = *(uint4*)o;
}

// ---------------- RMSNorm (dual output) ----------------
__global__ void rmsnorm_kernel(const float* __restrict__ x,
                               const float* __restrict__ w,
                               float* __restrict__ of,
                               __nv_bfloat16* __restrict__ ob) {
    int row = blockIdx.x;
    int tid = threadIdx.x;
    const float* xr = x + (size_t)row * CC;
    float s = 0.f;
    for (int i = tid; i < CC; i += 256) { float v = xr[i]; s += v * v; }
    __shared__ float red[256];
    red[tid] = s; __syncthreads();
    for (int o2 = 128; o2 > 0; o2 >>= 1) {
        if (tid < o2) red[tid] += red[tid + o2];
        __syncthreads();
    }
    float scale = rsqrtf(red[0] / (float)CC + 1e-6f);
    for (int i = tid; i < CC; i += 256) {
        float v = xr[i] * scale * w[i];
        if (of) of[(size_t)row * CC + i] = v;
        ob[(size_t)row * CC + i] = __float2bfloat16(v);
    }
}

// ------- fused RoPE(q,k) + Q bf16 (pre-scaled) + K/V bf16 compaction -----
__global__ void rope_all_kernel(const float* __restrict__ X,
                                __nv_bfloat16* __restrict__ Qb,
                                __nv_bfloat16* __restrict__ Kb,
                                __nv_bfloat16* __restrict__ Vb) {
    int i = blockIdx.x * blockDim.x + threadIdx.x;
    const int NQ = NTOK * HH * 32;
    const int NK = NTOK * KVH * 32;
    const int NV = NTOK * (KVW / 2);
    if (i < NQ) {
        int p = i & 31;
        int tmp = i >> 5;
        int hh = tmp % HH;
        int row = tmp / HH;
        int t = row % TT;
        float invf = expf(-(float)p * (logf(10000.f) / 32.f));
        float ang = (float)t * invf;
        float cs = cosf(ang), sn = sinf(ang);
        size_t base = (size_t)row * QKVN + hh * 64;
        float a = X[base + p];
        float b = X[base + p + 32];
        size_t qo = (size_t)row * CC + hh * 64;
        Qb[qo + p]      = __float2bfloat16(0.125f * (a * cs - b * sn));
        Qb[qo + p + 32] = __float2bfloat16(0.125f * (b * cs + a * sn));
    } else if (i < NQ + NK) {
        int j = i - NQ;
        int p = j & 31;
        int tmp = j >> 5;
        int hh = tmp % KVH;
        int row = tmp / KVH;
        int t = row % TT;
        float invf = expf(-(float)p * (logf(10000.f) / 32.f));
        float ang = (float)t * invf;
        float cs = cosf(ang), sn = sinf(ang);
        size_t base = (size_t)row * QKVN + CC + hh * 64;
        float a = X[base + p];
        float b = X[base + p + 32];
        Kb[(size_t)row * KVW + hh * 64 + p]      = __float2bfloat16(a * cs - b * sn);
        Kb[(size_t)row * KVW + hh * 64 + p + 32] = __float2bfloat16(b * cs + a * sn);
    } else if (i < NQ + NK + NV) {
        int j = i - NQ - NK;
        int row = j >> 7;
        int p2 = (j & 127) * 2;
        const float* base = X + (size_t)row * QKVN + CC + KVW;
        *(__nv_bfloat162*)&Vb[(size_t)row * KVW + p2] =
            __floats2bfloat162_rn(base[p2], base[p2 + 1]);
    }
}

// ---------------- flash attention: 64-row Q tiles, mma.sync, bf16 all ----
__global__ __launch_bounds__(128) void attn_mma(const __nv_bfloat16* __restrict__ Qb,
                                                const __nv_bfloat16* __restrict__ Kb,
                                                const __nv_bfloat16* __restrict__ Vb,
                                                __nv_bfloat16* __restrict__ O) {
    int qb = blockIdx.x, h = blockIdx.y, b = blockIdx.z;
    int tid = threadIdx.x;
    int wid = tid >> 5, lane = tid & 31;
    int kvh = h / NREP;

    __shared__ __align__(16) __nv_bfloat16 Qs[64 * 72];
    __shared__ __align__(16) __nv_bfloat16 Ks[64 * 72];
    __shared__ __align__(16) __nv_bfloat16 Vs[64 * 72];

    for (int i = tid; i < 64 * 8; i += 128) {
        int row = i >> 3, g = (i & 7) * 8;
        *(uint4*)&Qs[row * 72 + g] =
            *(const uint4*)&Qb[((size_t)(b * TT + qb * 64 + row)) * CC + h * DH + g];
    }
    __syncthreads();

    int r16 = lane & 15, kh = lane >> 4;
    int rn = lane & 7, knh = (lane >> 3) & 1;
    uint32_t qf[4][4];
#pragma unroll
    for (int kk = 0; kk < 4; kk++) {
        uint32_t ad = su32(&Qs[(wid * 16 + r16) * 72 + kk * 16 + kh * 8]);
        asm volatile("ldmatrix.sync.aligned.m8n8.x4.shared.b16 {%0,%1,%2,%3}, [%4];"
            : "=r"(qf[kk][0]), "=r"(qf[kk][1]), "=r"(qf[kk][2]), "=r"(qf[kk][3]) : "r"(ad));
    }

    int rr = lane >> 2, cq = (lane & 3) * 2;
    int t0 = qb * 64 + wid * 16 + rr;   // second row = t0+8
    float m0 = -1e30f, m1 = -1e30f, l0 = 0.f, l1 = 0.f;
    float acc[8][4];
#pragma unroll
    for (int dn = 0; dn < 8; dn++)
#pragma unroll
        for (int r = 0; r < 4; r++) acc[dn][r] = 0.f;

    int kstart = qb * 64 - WIN; if (kstart < 0) kstart = 0;
    for (int k0 = kstart; k0 <= qb * 64; k0 += 64) {
        __syncthreads();
        for (int i = tid; i < 64 * 32; i += 128) {
            int row = i >> 5, p2 = (i & 31) * 2;
            size_t kr = ((size_t)(b * TT + k0 + row)) * KVW + kvh * DH;
            *(__nv_bfloat162*)&Ks[row * 72 + p2] = *(const __nv_bfloat162*)&Kb[kr + p2];
            *(__nv_bfloat162*)&Vs[row * 72 + p2] = *(const __nv_bfloat162*)&Vb[kr + p2];
        }
        __syncthreads();

        float s[8][4];
#pragma unroll
        for (int j = 0; j < 8; j++) {
            s[j][0] = s[j][1] = s[j][2] = s[j][3] = 0.f;
#pragma unroll
            for (int kk = 0; kk < 4; kk++) {
                uint32_t bfr[2];
                uint32_t bd = su32(&Ks[(j * 8 + rn) * 72 + kk * 16 + knh * 8]);
                asm volatile("ldmatrix.sync.aligned.m8n8.x2.shared.b16 {%0,%1}, [%2];"
                    : "=r"(bfr[0]), "=r"(bfr[1]) : "r"(bd));
                asm volatile(
                    "mma.sync.aligned.m16n8k16.row.col.f32.bf16.bf16.f32 "
                    "{%0,%1,%2,%3}, {%4,%5,%6,%7}, {%8,%9}, {%0,%1,%2,%3};"
                    : "+f"(s[j][0]), "+f"(s[j][1]), "+f"(s[j][2]), "+f"(s[j][3])
                    : "r"(qf[kk][0]), "r"(qf[kk][1]), "r"(qf[kk][2]), "r"(qf[kk][3]),
                      "r"(bfr[0]), "r"(bfr[1]));
            }
        }
#pragma unroll
        for (int j = 0; j < 8; j++) {
            int kg = k0 + j * 8 + cq;
            if (kg > t0 || kg < t0 - WIN) s[j][0] = -1e30f;
            if (kg + 1 > t0 || kg + 1 < t0 - WIN) s[j][1] = -1e30f;
            if (kg > t0 + 8 || kg < t0 + 8 - WIN) s[j][2] = -1e30f;
            if (kg + 1 > t0 + 8 || kg + 1 < t0 + 8 - WIN) s[j][3] = -1e30f;
        }
        float mx0 = -1e30f, mx1 = -1e30f;
#pragma unroll
        for (int j = 0; j < 8; j++) {
            mx0 = fmaxf(mx0, fmaxf(s[j][0], s[j][1]));
            mx1 = fmaxf(mx1, fmaxf(s[j][2], s[j][3]));
        }
        mx0 = fmaxf(mx0, __shfl_xor_sync(0xffffffffu, mx0, 1));
        mx0 = fmaxf(mx0, __shfl_xor_sync(0xffffffffu, mx0, 2));
        mx1 = fmaxf(mx1, __shfl_xor_sync(0xffffffffu, mx1, 1));
        mx1 = fmaxf(mx1, __shfl_xor_sync(0xffffffffu, mx1, 2));
        float mn0 = fmaxf(m0, mx0), mn1 = fmaxf(m1, mx1);
        float c0 = __expf(m0 - mn0), c1 = __expf(m1 - mn1);
        m0 = mn0; m1 = mn1;
        l0 *= c0; l1 *= c1;
#pragma unroll
        for (int dn = 0; dn < 8; dn++) {
            acc[dn][0] *= c0; acc[dn][1] *= c0;
            acc[dn][2] *= c1; acc[dn][3] *= c1;
        }
#pragma unroll
        for (int j = 0; j < 8; j++) {
            s[j][0] = __expf(s[j][0] - m0); s[j][1] = __expf(s[j][1] - m0);
            s[j][2] = __expf(s[j][2] - m1); s[j][3] = __expf(s[j][3] - m1);
            l0 += s[j][0] + s[j][1];
            l1 += s[j][2] + s[j][3];
        }
        uint32_t pa[4][4];
#pragma unroll
        for (int kk = 0; kk < 4; kk++) {
            int j0 = kk * 2, j1 = kk * 2 + 1;
            pa[kk][0] = packbf(s[j0][0], s[j0][1]);
            pa[kk][1] = packbf(s[j0][2], s[j0][3]);
            pa[kk][2] = packbf(s[j1][0], s[j1][1]);
            pa[kk][3] = packbf(s[j1][2], s[j1][3]);
        }
#pragma unroll
        for (int dn = 0; dn < 8; dn++)
#pragma unroll
            for (int kk = 0; kk < 4; kk++) {
                uint32_t bfr[2];
                uint32_t bd = su32(&Vs[(kk * 16 + knh * 8 + rn) * 72 + dn * 8]);
                asm volatile("ldmatrix.sync.aligned.m8n8.x2.trans.shared.b16 {%0,%1}, [%2];"
                    : "=r"(bfr[0]), "=r"(bfr[1]) : "r"(bd));
                asm volatile(
                    "mma.sync.aligned.m16n8k16.row.col.f32.bf16.bf16.f32 "
                    "{%0,%1,%2,%3}, {%4,%5,%6,%7}, {%8,%9}, {%0,%1,%2,%3};"
                    : "+f"(acc[dn][0]), "+f"(acc[dn][1]), "+f"(acc[dn][2]), "+f"(acc[dn][3])
                    : "r"(pa[kk][0]), "r"(pa[kk][1]), "r"(pa[kk][2]), "r"(pa[kk][3]),
                      "r"(bfr[0]), "r"(bfr[1]));
            }
    }
    l0 += __shfl_xor_sync(0xffffffffu, l0, 1);
    l0 += __shfl_xor_sync(0xffffffffu, l0, 2);
    l1 += __shfl_xor_sync(0xffffffffu, l1, 1);
    l1 += __shfl_xor_sync(0xffffffffu, l1, 2);
    float i0 = 1.f / l0, i1 = 1.f / l1;
    __nv_bfloat16* o0 = O + ((size_t)(b * TT + t0)) * CC + h * DH;
    __nv_bfloat16* o1 = o0 + (size_t)8 * CC;
#pragma unroll
    for (int dn = 0; dn < 8; dn++) {
        *(__nv_bfloat162*)&o0[dn * 8 + cq] =
            __floats2bfloat162_rn(acc[dn][0] * i0, acc[dn][1] * i0);
        *(__nv_bfloat162*)&o1[dn * 8 + cq] =
            __floats2bfloat162_rn(acc[dn][2] * i1, acc[dn][3] * i1);
    }
}

// ---------------- router ----------------
__global__ void route_kernel(const float* __restrict__ xf,
                             const float* __restrict__ gw) {
    int warp = threadIdx.x >> 5, lane = threadIdx.x & 31;
    int tok = blockIdx.x * 4 + warp;
    if (tok >= NTOK) return;
    const float* xr = xf + (size_t)tok * CC;
    float part[EE];
#pragma unroll
    for (int e = 0; e < EE; e++) part[e] = 0.f;
    for (int d = lane; d < CC; d += 32) {
        float xv = xr[d];
#pragma unroll
        for (int e = 0; e < EE; e++) part[e] += xv * gw[d * EE + e];
    }
#pragma unroll
    for (int e = 0; e < EE; e++)
#pragma unroll
        for (int o = 16; o > 0; o >>= 1)
            part[e] += __shfl_xor_sync(0xffffffffu, part[e], o);
    if (lane == 0) {
        float v0 = -1e30f; int i0 = 0;
#pragma unroll
        for (int e = 0; e < EE; e++) if (part[e] > v0) { v0 = part[e]; i0 = e; }
        float v1 = -1e30f; int i1 = 0;
#pragma unroll
        for (int e = 0; e < EE; e++)
            if (e != i0 && part[e] > v1) { v1 = part[e]; i1 = e; }
        float ex = expf(v1 - v0);
        float w0 = 1.f / (1.f + ex);
        float w1 = ex / (1.f + ex);
        g_sel[tok * 2] = i0; g_sel[tok * 2 + 1] = i1;
        g_selw[tok * 2] = w0; g_selw[tok * 2 + 1] = w1;
        float mx = v0, sum = 0.f, pe[EE];
#pragma unroll
        for (int e = 0; e < EE; e++) { pe[e] = expf(part[e] - mx); sum += pe[e]; }
#pragma unroll
        for (int e = 0; e < EE; e++) g_probs[tok * EE + e] = pe[e] / sum;
        float lse = mx + logf(sum);
        g_lse2[tok] = lse * lse;
    }
}

// ---------------- aux loss ----------------
__global__ void aux_kernel() {
    __shared__ float red[256];
    int tid = threadIdx.x;
    float loadv[EE];
#pragma unroll
    for (int e = 0; e < EE; e++) loadv[e] = 0.f;
    for (int n = tid; n < NTOK; n += 256) {
#pragma unroll
        for (int e = 0; e < EE; e++) loadv[e] += g_probs[n * EE + e];
    }
    float loads[EE];
    for (int e = 0; e < EE; e++) {
        red[tid] = loadv[e]; __syncthreads();
        for (int o = 128; o > 0; o >>= 1) {
            if (tid < o) red[tid] += red[tid + o];
            __syncthreads();
        }
        loads[e] = red[0]; __syncthreads();
    }
    float zp = 0.f;
    for (int n = tid; n < NTOK; n += 256) zp += g_lse2[n];
    red[tid] = zp; __syncthreads();
    for (int o = 128; o > 0; o >>= 1) {
        if (tid < o) red[tid] += red[tid + o];
        __syncthreads();
    }
    if (tid == 0) {
        float tot = 0.f;
        for (int e = 0; e < EE; e++) tot += loads[e];
        float lb = 0.f;
        for (int e = 0; e < EE; e++) { float f = loads[e] / tot; lb += f * f; }
        lb *= (float)EE;
        float z = red[0] / (float)NTOK;
        g_aux = 0.01f * lb + 0.001f * z;
    }
}

__global__ void zero_cnt_kernel() { if (threadIdx.x < EE) g_cnt[threadIdx.x] = 0; }

__global__ void count_kernel() {
    int i = blockIdx.x * blockDim.x + threadIdx.x;
    if (i >= NTOK) return;
#pragma unroll
    for (int kk = 0; kk < TOPK; kk++)
        atomicAdd(&g_cnt[g_sel[i * 2 + kk]], 1);
}

__global__ void offsets_kernel() {
    if (threadIdx.x == 0) {
        int acc = 0;
        for (int e = 0; e < EE; e++) {
            g_off[e] = acc;
            acc += (g_cnt[e] + BM - 1) & ~(BM - 1);
            g_cnt2[e] = 0;
        }
        g_off[EE] = acc;
    }
}

__global__ void assign_kernel() {
    int i = blockIdx.x * blockDim.x + threadIdx.x;
    if (i >= NTOK) return;
#pragma unroll
    for (int kk = 0; kk < TOPK; kk++) {
        int e = g_sel[i * 2 + kk];
        int pos = atomicAdd(&g_cnt2[e], 1);
        int row = g_off[e] + pos;
        g_idx[row] = i;
        g_tokrow[i * 2 + kk] = row;
    }
}

__global__ void gather_all_kernel(__nv_bfloat16* __restrict__ dst,
                                  const __nv_bfloat16* __restrict__ src) {
    int b = blockIdx.x;
    if (b >= g_off[EE]) return;
    int e = 0;
    while (g_off[e + 1] <= b) e++;
    if (b - g_off[e] >= g_cnt[e]) return;
    int t = g_idx[b];
    uint4* d4 = (uint4*)(dst + (size_t)b * CC);
    const uint4* s4 = (const uint4*)(src + (size_t)t * CC);
    int i = threadIdx.x;
    if (i < CC * 2 / 16) d4[i] = s4[i];
}

// final: out = h + a_moe * (shared + w0*eo[r0] + w1*eo[r1]); writes aux too
__global__ void final_kernel(const float* __restrict__ h, const float* __restrict__ moe,
                             const float* __restrict__ eo,
                             const float* __restrict__ alpha, float* __restrict__ out,
                             int writeAux) {
    int t = blockIdx.x;
    if (writeAux && t == 0 && threadIdx.x == 0) out[OUT_MAIN] = g_aux;
    float w0 = g_selw[t * 2], w1 = g_selw[t * 2 + 1];
    int r0 = g_tokrow[t * 2], r1 = g_tokrow[t * 2 + 1];
    float a = *alpha;
    const float* hr = h + (size_t)t * CC;
    const float* mr = moe + (size_t)t * CC;
    const float* e0 = eo + (size_t)r0 * CC;
    const float* e1 = eo + (size_t)r1 * CC;
    float* orow = out + (size_t)t * CC;
    for (int i = threadIdx.x; i < CC; i += blockDim.x)
        orow[i] = hr[i] + a * (mr[i] + w0 * e0[i] + w1 * e1[i]);
}

// ---------------- launch ----------------
extern "C" void kernel_launch(void* const* d_in, const int* in_sizes, int n_in,
                              void* d_out, int out_size) {
    const float* x      = (const float*)d_in[0];
    const float* ln1    = (const float*)d_in[1];
    const float* ln2    = (const float*)d_in[2];
    const float* wq     = (const float*)d_in[3];
    const float* wk     = (const float*)d_in[4];
    const float* wv     = (const float*)d_in[5];
    const float* wo     = (const float*)d_in[6];
    const float* sw1    = (const float*)d_in[7];
    const float* sw2    = (const float*)d_in[8];
    const float* sw3    = (const float*)d_in[9];
    const float* ew1    = (const float*)d_in[10];
    const float* ew2    = (const float*)d_in[11];
    const float* ew3    = (const float*)d_in[12];
    const float* gatew  = (const float*)d_in[13];
    const float* a_attn = (const float*)d_in[14];
    const float* a_moe  = (const float*)d_in[15];
    float* out = (float*)d_out;

    void* p;
    float *qkv, *h, *xf, *moe, *eo;
    __nv_bfloat16 *xnb, *qb, *aob, *xfb, *xgb, *g1b, *kb, *vb;
    __nv_bfloat16 *wqkvt, *wot, *sw12t, *sw3t, *ew12t, *ew3t;
    cudaGetSymbolAddress(&p, g_qkv);  qkv  = (float*)p;
    cudaGetSymbolAddress(&p, g_h);    h    = (float*)p;
    cudaGetSymbolAddress(&p, g_xf);   xf   = (float*)p;
    cudaGetSymbolAddress(&p, g_moe);  moe  = (float*)p;
    cudaGetSymbolAddress(&p, g_eo);   eo   = (float*)p;
    cudaGetSymbolAddress(&p, g_xnb);  xnb  = (__nv_bfloat16*)p;
    cudaGetSymbolAddress(&p, g_qb);   qb   = (__nv_bfloat16*)p;
    cudaGetSymbolAddress(&p, g_aob);  aob  = (__nv_bfloat16*)p;
    cudaGetSymbolAddress(&p, g_xfb);  xfb  = (__nv_bfloat16*)p;
    cudaGetSymbolAddress(&p, g_xgb);  xgb  = (__nv_bfloat16*)p;
    cudaGetSymbolAddress(&p, g_g1b);  g1b  = (__nv_bfloat16*)p;
    cudaGetSymbolAddress(&p, g_kb);   kb   = (__nv_bfloat16*)p;
    cudaGetSymbolAddress(&p, g_vb);   vb   = (__nv_bfloat16*)p;
    cudaGetSymbolAddress(&p, g_wqkvt); wqkvt = (__nv_bfloat16*)p;
    cudaGetSymbolAddress(&p, g_wot);   wot   = (__nv_bfloat16*)p;
    cudaGetSymbolAddress(&p, g_sw12t); sw12t = (__nv_bfloat16*)p;
    cudaGetSymbolAddress(&p, g_sw3t);  sw3t  = (__nv_bfloat16*)p;
    cudaGetSymbolAddress(&p, g_ew12t); ew12t = (__nv_bfloat16*)p;
    cudaGetSymbolAddress(&p, g_ew3t);  ew3t  = (__nv_bfloat16*)p;

    static bool s_init = false;
    static cudaStream_t s2 = 0;
    static cudaEvent_t evA = 0, evB = 0, evC = 0, evD = 0, evE = 0;
    if (!s_init) {
        if (cudaStreamCreateWithFlags(&s2, cudaStreamNonBlocking) != cudaSuccess) s2 = 0;
        if (s2) {
            bool ok = true;
            ok &= (cudaEventCreateWithFlags(&evA, cudaEventDisableTiming) == cudaSuccess);
            ok &= (cudaEventCreateWithFlags(&evB, cudaEventDisableTiming) == cudaSuccess);
            ok &= (cudaEventCreateWithFlags(&evC, cudaEventDisableTiming) == cudaSuccess);
            ok &= (cudaEventCreateWithFlags(&evD, cudaEventDisableTiming) == cudaSuccess);
            ok &= (cudaEventCreateWithFlags(&evE, cudaEventDisableTiming) == cudaSuccess);
            if (!ok) s2 = 0;
        }
        s_init = true;
    }
    bool forked = (s2 != 0);

    // critical-path conversions (attention weights only)
    wcvt<<<512, 256>>>(wq, wqkvt, CC, QKVN, 0, 0, 0, (long)CC*CC/8);
    wcvt<<<128, 256>>>(wk, wqkvt, KVW, QKVN, CC, 0, 0, (long)CC*KVW/8);
    wcvt<<<128, 256>>>(wv, wqkvt, KVW, QKVN, CC+KVW, 0, 0, (long)CC*KVW/8);
    wcvt<<<512, 256>>>(wo, wot, CC, CC, 0, 0, 0, (long)CC*CC/8);

    // FFN weight conversions forked onto s2 (shared first, then experts)
    if (forked) {
        cudaEventRecord(evA, 0);
        cudaStreamWaitEvent(s2, evA, 0);
        wcvt_pair<<<4096, 256, 0, s2>>>(sw1, sw2, sw12t, FF, 0, 0, (long)CC*FF/4);
        wcvt<<<2048, 256, 0, s2>>>(sw3, sw3t, CC, CC, 0, 0, 0, (long)FF*CC/8);
        cudaEventRecord(evE, s2);
        wcvt_pair<<<dim3(4096,1,EE), 256, 0, s2>>>(ew1, ew2, ew12t, FF,
            (long)CC*FF, (long)CC*2*FF, (long)CC*FF/4);
        wcvt<<<dim3(2048,1,EE), 256, 0, s2>>>(ew3, ew3t, CC, CC, 0,
            (long)FF*CC, (long)FF*CC, (long)FF*CC/8);
        cudaEventRecord(evB, s2);
    } else {
        wcvt_pair<<<4096, 256>>>(sw1, sw2, sw12t, FF, 0, 0, (long)CC*FF/4);
        wcvt<<<2048, 256>>>(sw3, sw3t, CC, CC, 0, 0, 0, (long)FF*CC/8);
        wcvt_pair<<<dim3(4096,1,EE), 256>>>(ew1, ew2, ew12t, FF,
            (long)CC*FF, (long)CC*2*FF, (long)CC*FF/4);
        wcvt<<<dim3(2048,1,EE), 256>>>(ew3, ew3t, CC, CC, 0,
            (long)FF*CC, (long)FF*CC, (long)FF*CC/8);
    }

    // 1) pre-attn norm
    rmsnorm_kernel<<<NTOK, 256>>>(x, ln1, nullptr, xnb);
    // 2) fused QKV projection
    gemm_mma<<<dim3(QKVN/128, NTOK/128), 256>>>(xnb, wqkvt, qkv, QKVN, CC);
    // 3) fused RoPE(q,k) + Q/K/V bf16 compaction
    {
        int total = NTOK*HH*32 + NTOK*KVH*32 + NTOK*(KVW/2);
        rope_all_kernel<<<(total + 255) / 256, 256>>>(qkv, qb, kb, vb);
    }
    // 4) attention (tensor core, 64-row Q tiles, all bf16 operands)
    attn_mma<<<dim3(TT/64, HH, BB), 128>>>(qb, kb, vb, aob);
    // 5) output projection with fused ReZero residual
    gemm_mma_add<<<dim3(CC/128, NTOK/128), 256>>>(aob, wot, x, a_attn, h, CC, CC);
    // 6) post-attn norm
    rmsnorm_kernel<<<NTOK, 256>>>(h, ln2, xf, xfb);
    // 7) routing + aux + compaction — forked onto s2, overlapped with shared GEMMs
    if (forked) {
        cudaEventRecord(evC, 0);
        cudaStreamWaitEvent(s2, evC, 0);
        route_kernel<<<NTOK / 4, 128, 0, s2>>>(xf, gatew);
        aux_kernel<<<1, 256, 0, s2>>>();
        zero_cnt_kernel<<<1, 32, 0, s2>>>();
        count_kernel<<<(NTOK + 255) / 256, 256, 0, s2>>>();
        offsets_kernel<<<1, 32, 0, s2>>>();
        assign_kernel<<<(NTOK + 255) / 256, 256, 0, s2>>>();
        cudaEventRecord(evD, s2);
    } else {
        route_kernel<<<NTOK / 4, 128>>>(xf, gatew);
        aux_kernel<<<1, 256>>>();
        zero_cnt_kernel<<<1, 32>>>();
        count_kernel<<<(NTOK + 255) / 256, 256>>>();
        offsets_kernel<<<1, 32>>>();
        assign_kernel<<<(NTOK + 255) / 256, 256>>>();
    }
    // 8) shared expert: fused w12+SwiGLU, then w3 (join shared-weight conversion)
    if (forked) cudaStreamWaitEvent(0, evE, 0);
    gemm_swiglu<<<dim3(2*FF/128, NTOK/128), 256>>>(xfb, sw12t, g1b, 2*FF, CC);
    gemm_mma<<<dim3(CC/128, NTOK/128), 256>>>(g1b, sw3t, moe, CC, FF);
    // 9) routed experts, batched (join routing + expert weights first)
    if (forked) cudaStreamWaitEvent(0, evD, 0);
    gather_all_kernel<<<ECAP, 128>>>(xgb, xfb);
    if (forked) cudaStreamWaitEvent(0, evB, 0);
    gemm_moe_swiglu<<<dim3(2*FF/128, ECAP/128), 256>>>(xgb, ew12t, g1b, 2*FF, CC, (long)CC*2*FF);
    gemm_moe<<<dim3(CC/128, ECAP/128), 256>>>(g1b, ew3t, eo, CC, FF, (long)FF*CC);
    // 10) final combine + aux scalar (fused)
    final_kernel<<<NTOK, 256>>>(h, moe, eo, a_moe, out, out_size > OUT_MAIN ? 1 : 0);
}

// round 13
// speedup vs baseline: 1.2455x; 1.0019x over previous
#include <cuda_runtime.h>
#include <cuda_bf16.h>
#include <math.h>
#include <stdint.h>

// Problem constants
#define BB   2
#define TT   2048
#define CC   1024
#define HH   16
#define KVH  4
#define DH   64
#define NREP 4
#define FF   4096
#define EE   8
#define TOPK 2
#define WIN  1024
#define NTOK (BB*TT)            // 4096
#define OUT_MAIN (NTOK*CC)      // 4194304
#define QKVN (CC + 2*KVH*DH)    // 1536
#define KVW  (KVH*DH)           // 256
#define ECAP 9216               // 8192 real rows + padding, 128-aligned

// ---------------- scratch (device globals; no allocation) ----------------
__device__ float g_qkv [NTOK*QKVN];
__device__ float g_h   [NTOK*CC];
__device__ float g_xf  [NTOK*CC];
__device__ float g_moe [NTOK*CC];
__device__ float g_eo  [(size_t)ECAP*CC];
__device__ float g_probs[NTOK*EE];
__device__ float g_lse2[NTOK];
__device__ int   g_sel [NTOK*2];
__device__ float g_selw[NTOK*2];
__device__ int   g_cnt [EE];
__device__ int   g_cnt2[EE];
__device__ int   g_off [EE+1];
__device__ int   g_idx [ECAP];
__device__ int   g_tokrow[NTOK*2];
__device__ float g_aux;

// bf16 activations
__device__ __nv_bfloat16 g_xnb [NTOK*CC];
__device__ __nv_bfloat16 g_qb  [NTOK*CC];
__device__ __nv_bfloat16 g_aob [NTOK*CC];
__device__ __nv_bfloat16 g_xfb [NTOK*CC];
__device__ __nv_bfloat16 g_xgb [(size_t)ECAP*CC];
__device__ __nv_bfloat16 g_g1b [(size_t)ECAP*FF];
__device__ __nv_bfloat16 g_kb  [NTOK*KVW];
__device__ __nv_bfloat16 g_vb  [NTOK*KVW];

// bf16 weights, K-major [K,N] (w12 column-interleaved: w1->2f, w2->2f+1)
__device__ __nv_bfloat16 g_wqkvt[CC*QKVN];
__device__ __nv_bfloat16 g_wot  [CC*CC];
__device__ __nv_bfloat16 g_sw12t[CC*2*FF];
__device__ __nv_bfloat16 g_sw3t [FF*CC];
__device__ __nv_bfloat16 g_ew12t[(size_t)EE*CC*2*FF];
__device__ __nv_bfloat16 g_ew3t [(size_t)EE*FF*CC];

__device__ __forceinline__ uint32_t su32(const void* p) {
    uint32_t a;
    asm("{ .reg .u64 t; cvta.to.shared.u64 t, %1; cvt.u32.u64 %0, t; }" : "=r"(a) : "l"(p));
    return a;
}
__device__ __forceinline__ uint32_t packbf(float a, float b) {
    __nv_bfloat162 t = __floats2bfloat162_rn(a, b);
    return *(uint32_t*)&t;
}

#define CP_ASYNC16(d, s) asm volatile("cp.async.cg.shared.global [%0], [%1], 16;" :: "r"(d), "l"(s))
#define CP_COMMIT()      asm volatile("cp.async.commit_group;" ::: "memory")
#define CP_WAIT(n)       asm volatile("cp.async.wait_group %0;" :: "n"(n) : "memory")

#define BM 128
#define BN 128
#define BK 32
#define ASTR 40    // A smem row stride (bf16 elems)
#define BSTR 136   // B smem row stride (bf16 elems)

// ================= 2-stage GEMM mainloop; B is [K,N] via ldmatrix.x4.trans
#define GEMM_MAIN(A_, Bt_, N_, K_)                                             \
    __shared__ __align__(16) __nv_bfloat16 sA[2][BM * ASTR];                   \
    __shared__ __align__(16) __nv_bfloat16 sB[2][BK * BSTR];                   \
    int tid = threadIdx.x;                                                     \
    int wid = tid >> 5, lane = tid & 31;                                       \
    int wm = wid >> 2, wn = wid & 3;                                           \
    float cr[4][4][4];                                                         \
    _Pragma("unroll") for (int i = 0; i < 4; i++)                              \
    _Pragma("unroll") for (int j = 0; j < 4; j++)                              \
    _Pragma("unroll") for (int r = 0; r < 4; r++) cr[i][j][r] = 0.f;           \
    int lrow = tid >> 1;                                                       \
    int lc16 = (tid & 1) * 16;                                                 \
    int nCh = (K_) / BK;                                                       \
    {                                                                          \
        const __nv_bfloat16* srcA0 = (A_) + (size_t)(rowBase + lrow) * (K_) + lc16; \
        uint32_t dA0 = su32(&sA[0][lrow * ASTR + lc16]);                       \
        CP_ASYNC16(dA0, srcA0); CP_ASYNC16(dA0 + 16, srcA0 + 8);               \
        _Pragma("unroll") for (int bi = 0; bi < 2; bi++) {                     \
            int seg = tid + bi * 256;                                          \
            int brow = seg >> 4, bcol = (seg & 15) * 8;                        \
            const __nv_bfloat16* srcB = (Bt_) + (size_t)brow * (N_) + colBase + bcol; \
            CP_ASYNC16(su32(&sB[0][brow * BSTR + bcol]), srcB);                \
        }                                                                      \
        CP_COMMIT();                                                           \
    }                                                                          \
    for (int ch = 0; ch < nCh; ch++) {                                         \
        int st = ch & 1;                                                       \
        if (ch + 1 < nCh) {                                                    \
            int k0 = (ch + 1) * BK;                                            \
            const __nv_bfloat16* srcA = (A_) + (size_t)(rowBase + lrow) * (K_) + k0 + lc16; \
            uint32_t dA = su32(&sA[st ^ 1][lrow * ASTR + lc16]);               \
            CP_ASYNC16(dA, srcA); CP_ASYNC16(dA + 16, srcA + 8);               \
            _Pragma("unroll") for (int bi = 0; bi < 2; bi++) {                 \
                int seg = tid + bi * 256;                                      \
                int brow = seg >> 4, bcol = (seg & 15) * 8;                    \
                const __nv_bfloat16* srcB = (Bt_) + (size_t)(k0 + brow) * (N_) + colBase + bcol; \
                CP_ASYNC16(su32(&sB[st ^ 1][brow * BSTR + bcol]), srcB);       \
            }                                                                  \
            CP_COMMIT(); CP_WAIT(1);                                           \
        } else { CP_WAIT(0); }                                                 \
        __syncthreads();                                                       \
        int r16 = lane & 15, kh = lane >> 4;                                   \
        int brl = (lane & 7) + ((lane >> 3) & 1) * 8;   /* row within 16 */    \
        int bcl = ((lane >> 4) & 1) * 8;                /* col half */         \
        _Pragma("unroll") for (int kk = 0; kk < 2; kk++) {                     \
            uint32_t af[4][4];                                                 \
            _Pragma("unroll") for (int mf = 0; mf < 4; mf++) {                 \
                uint32_t ad = su32(&sA[st][(wm * 64 + mf * 16 + r16) * ASTR + kk * 16 + kh * 8]); \
                asm volatile("ldmatrix.sync.aligned.m8n8.x4.shared.b16 {%0,%1,%2,%3}, [%4];" \
                    : "=r"(af[mf][0]), "=r"(af[mf][1]), "=r"(af[mf][2]), "=r"(af[mf][3]) : "r"(ad)); \
            }                                                                  \
            uint32_t bfr[4][2];                                                \
            _Pragma("unroll") for (int nfp = 0; nfp < 2; nfp++) {              \
                uint32_t bd = su32(&sB[st][(kk * 16 + brl) * BSTR + wn * 32 + nfp * 16 + bcl]); \
                asm volatile("ldmatrix.sync.aligned.m8n8.x4.trans.shared.b16 {%0,%1,%2,%3}, [%4];" \
                    : "=r"(bfr[2*nfp][0]), "=r"(bfr[2*nfp][1]),                \
                      "=r"(bfr[2*nfp+1][0]), "=r"(bfr[2*nfp+1][1]) : "r"(bd)); \
            }                                                                  \
            _Pragma("unroll") for (int mf = 0; mf < 4; mf++)                   \
            _Pragma("unroll") for (int nf = 0; nf < 4; nf++) {                 \
                asm volatile(                                                  \
                    "mma.sync.aligned.m16n8k16.row.col.f32.bf16.bf16.f32 "     \
                    "{%0,%1,%2,%3}, {%4,%5,%6,%7}, {%8,%9}, {%0,%1,%2,%3};"    \
                    : "+f"(cr[mf][nf][0]), "+f"(cr[mf][nf][1]),                \
                      "+f"(cr[mf][nf][2]), "+f"(cr[mf][nf][3])                 \
                    : "r"(af[mf][0]), "r"(af[mf][1]), "r"(af[mf][2]), "r"(af[mf][3]), \
                      "r"(bfr[nf][0]), "r"(bfr[nf][1]));                       \
            }                                                                  \
        }                                                                      \
        __syncthreads();                                                       \
    }                                                                          \
    int rr = lane >> 2, cq = (lane & 3) * 2;

// ================= dense GEMM, fp32 out =================
__global__ __launch_bounds__(256) void gemm_mma(
    const __nv_bfloat16* __restrict__ A, const __nv_bfloat16* __restrict__ Bt,
    float* __restrict__ C, int N, int K)
{
    int rowBase = blockIdx.y * BM, colBase = blockIdx.x * BN;
    GEMM_MAIN(A, Bt, N, K)
#pragma unroll
    for (int mf = 0; mf < 4; mf++)
#pragma unroll
        for (int nf = 0; nf < 4; nf++) {
            int row0 = rowBase + wm * 64 + mf * 16 + rr;
            int col = colBase + wn * 32 + nf * 8 + cq;
            *(float2*)&C[(size_t)row0 * N + col] = make_float2(cr[mf][nf][0], cr[mf][nf][1]);
            *(float2*)&C[(size_t)(row0 + 8) * N + col] = make_float2(cr[mf][nf][2], cr[mf][nf][3]);
        }
}

// ===== dense GEMM with fused ReZero residual: C = X + (*alpha)*(A@Bt) ====
__global__ __launch_bounds__(256) void gemm_mma_add(
    const __nv_bfloat16* __restrict__ A, const __nv_bfloat16* __restrict__ Bt,
    const float* __restrict__ X, const float* __restrict__ alpha,
    float* __restrict__ C, int N, int K)
{
    int rowBase = blockIdx.y * BM, colBase = blockIdx.x * BN;
    GEMM_MAIN(A, Bt, N, K)
    float a = *alpha;
#pragma unroll
    for (int mf = 0; mf < 4; mf++)
#pragma unroll
        for (int nf = 0; nf < 4; nf++) {
            int row0 = rowBase + wm * 64 + mf * 16 + rr;
            int col = colBase + wn * 32 + nf * 8 + cq;
            float2 x0 = *(const float2*)&X[(size_t)row0 * N + col];
            float2 x1 = *(const float2*)&X[(size_t)(row0 + 8) * N + col];
            *(float2*)&C[(size_t)row0 * N + col] =
                make_float2(x0.x + a * cr[mf][nf][0], x0.y + a * cr[mf][nf][1]);
            *(float2*)&C[(size_t)(row0 + 8) * N + col] =
                make_float2(x1.x + a * cr[mf][nf][2], x1.y + a * cr[mf][nf][3]);
        }
}

// ================= dense GEMM, fused SwiGLU bf16 out (interleaved w12) ===
__global__ __launch_bounds__(256) void gemm_swiglu(
    const __nv_bfloat16* __restrict__ A, const __nv_bfloat16* __restrict__ Bt,
    __nv_bfloat16* __restrict__ Obf, int N2, int K)
{
    int rowBase = blockIdx.y * BM, colBase = blockIdx.x * BN;
    GEMM_MAIN(A, Bt, N2, K)
    int FFo = N2 >> 1;
#pragma unroll
    for (int mf = 0; mf < 4; mf++)
#pragma unroll
        for (int nf = 0; nf < 4; nf++) {
            int row0 = rowBase + wm * 64 + mf * 16 + rr;
            int f = (colBase + wn * 32 + nf * 8 + cq) >> 1;
            float a0 = cr[mf][nf][0], b0 = cr[mf][nf][1];
            Obf[(size_t)row0 * FFo + f] = __float2bfloat16(a0 / (1.f + __expf(-a0)) * b0);
            float a1 = cr[mf][nf][2], b1 = cr[mf][nf][3];
            Obf[(size_t)(row0 + 8) * FFo + f] = __float2bfloat16(a1 / (1.f + __expf(-a1)) * b1);
        }
}

// ================= MoE GEMM, fp32 out =================
__global__ __launch_bounds__(256) void gemm_moe(
    const __nv_bfloat16* __restrict__ A, const __nv_bfloat16* __restrict__ Wb,
    float* __restrict__ C, int N, int K, long wstride)
{
    int rowBase = blockIdx.y * BM;
    if (rowBase >= g_off[EE]) return;
    int colBase = blockIdx.x * BN;
    int e = 0;
    while (g_off[e + 1] <= rowBase) e++;
    const __nv_bfloat16* Bt = Wb + (size_t)e * wstride;
    GEMM_MAIN(A, Bt, N, K)
#pragma unroll
    for (int mf = 0; mf < 4; mf++)
#pragma unroll
        for (int nf = 0; nf < 4; nf++) {
            int row0 = rowBase + wm * 64 + mf * 16 + rr;
            int col = colBase + wn * 32 + nf * 8 + cq;
            *(float2*)&C[(size_t)row0 * N + col] = make_float2(cr[mf][nf][0], cr[mf][nf][1]);
            *(float2*)&C[(size_t)(row0 + 8) * N + col] = make_float2(cr[mf][nf][2], cr[mf][nf][3]);
        }
}

// ================= MoE GEMM, fused SwiGLU bf16 out =================
__global__ __launch_bounds__(256) void gemm_moe_swiglu(
    const __nv_bfloat16* __restrict__ A, const __nv_bfloat16* __restrict__ Wb,
    __nv_bfloat16* __restrict__ Obf, int N2, int K, long wstride)
{
    int rowBase = blockIdx.y * BM;
    if (rowBase >= g_off[EE]) return;
    int colBase = blockIdx.x * BN;
    int e = 0;
    while (g_off[e + 1] <= rowBase) e++;
    const __nv_bfloat16* Bt = Wb + (size_t)e * wstride;
    GEMM_MAIN(A, Bt, N2, K)
    int FFo = N2 >> 1;
#pragma unroll
    for (int mf = 0; mf < 4; mf++)
#pragma unroll
        for (int nf = 0; nf < 4; nf++) {
            int row0 = rowBase + wm * 64 + mf * 16 + rr;
            int f = (colBase + wn * 32 + nf * 8 + cq) >> 1;
            float a0 = cr[mf][nf][0], b0 = cr[mf][nf][1];
            Obf[(size_t)row0 * FFo + f] = __float2bfloat16(a0 / (1.f + __expf(-a0)) * b0);
            float a1 = cr[mf][nf][2], b1 = cr[mf][nf][3];
            Obf[(size_t)(row0 + 8) * FFo + f] = __float2bfloat16(a1 / (1.f + __expf(-a1)) * b1);
        }
}

// ---------------- streaming weight convert: [K,NWs] f32 -> [K,NWd] bf16 --
__global__ void wcvt(const float* __restrict__ src, __nv_bfloat16* __restrict__ dst,
                     int NWs, int NWd, int coff, long sstride, long dstride, long total8) {
    long i = (long)blockIdx.x * blockDim.x + threadIdx.x;
    if (i >= total8) return;
    long e = i * 8;
    int k = (int)(e / NWs);
    int n = (int)(e - (long)k * NWs);
    const float* s = src + (size_t)blockIdx.z * sstride + (size_t)k * NWs + n;
    float4 v0 = *(const float4*)s;
    float4 v1 = *(const float4*)(s + 4);
    __nv_bfloat16 o[8];
    o[0] = __float2bfloat16(v0.x); o[1] = __float2bfloat16(v0.y);
    o[2] = __float2bfloat16(v0.z); o[3] = __float2bfloat16(v0.w);
    o[4] = __float2bfloat16(v1.x); o[5] = __float2bfloat16(v1.y);
    o[6] = __float2bfloat16(v1.z); o[7] = __float2bfloat16(v1.w);
    *(uint4*)&dst[(size_t)blockIdx.z * dstride + (size_t)k * NWd + coff + n] = *(uint4*)o;
}

// ---------------- streaming pair convert: w1,w2 [K,NW] -> [K,2NW] interleaved
__global__ void wcvt_pair(const float* __restrict__ s1, const float* __restrict__ s2,
                          __nv_bfloat16* __restrict__ dst,
                          int NW, long sstride, long dstride, long total4) {
    long i = (long)blockIdx.x * blockDim.x + threadIdx.x;
    if (i >= total4) return;
    long e = i * 4;
    int k = (int)(e / NW);
    int f = (int)(e - (long)k * NW);
    size_t so = (size_t)blockIdx.z * sstride + (size_t)k * NW + f;
    float4 va = *(const float4*)(s1 + so);
    float4 vb = *(const float4*)(s2 + so);
    __nv_bfloat16 o[8];
    o[0] = __float2bfloat16(va.x); o[1] = __float2bfloat16(vb.x);
    o[2] = __float2bfloat16(va.y); o[3] = __float2bfloat16(vb.y);
    o[4] = __float2bfloat16(va.z); o[5] = __float2bfloat16(vb.z);
    o[6] = __float2bfloat16(va.w); o[7] = __float2bfloat16(vb.w);
    *(uint4*)&dst[(size_t)blockIdx.z * dstride + (size_t)k * (2 * NW) + 2 * f] = *(uint4*)o;
}

// ---------------- RMSNorm (dual output) ----------------
__global__ void rmsnorm_kernel(const float* __restrict__ x,
                               const float* __restrict__ w,
                               float* __restrict__ of,
                               __nv_bfloat16* __restrict__ ob) {
    int row = blockIdx.x;
    int tid = threadIdx.x;
    const float* xr = x + (size_t)row * CC;
    float s = 0.f;
    for (int i = tid; i < CC; i += 256) { float v = xr[i]; s += v * v; }
    __shared__ float red[256];
    red[tid] = s; __syncthreads();
    for (int o2 = 128; o2 > 0; o2 >>= 1) {
        if (tid < o2) red[tid] += red[tid + o2];
        __syncthreads();
    }
    float scale = rsqrtf(red[0] / (float)CC + 1e-6f);
    for (int i = tid; i < CC; i += 256) {
        float v = xr[i] * scale * w[i];
        if (of) of[(size_t)row * CC + i] = v;
        ob[(size_t)row * CC + i] = __float2bfloat16(v);
    }
}

// ------- fused RoPE(q,k) + Q bf16 (pre-scaled) + K/V bf16 compaction -----
__global__ void rope_all_kernel(const float* __restrict__ X,
                                __nv_bfloat16* __restrict__ Qb,
                                __nv_bfloat16* __restrict__ Kb,
                                __nv_bfloat16* __restrict__ Vb) {
    int i = blockIdx.x * blockDim.x + threadIdx.x;
    const int NQ = NTOK * HH * 32;
    const int NK = NTOK * KVH * 32;
    const int NV = NTOK * (KVW / 2);
    if (i < NQ) {
        int p = i & 31;
        int tmp = i >> 5;
        int hh = tmp % HH;
        int row = tmp / HH;
        int t = row % TT;
        float invf = expf(-(float)p * (logf(10000.f) / 32.f));
        float ang = (float)t * invf;
        float cs = cosf(ang), sn = sinf(ang);
        size_t base = (size_t)row * QKVN + hh * 64;
        float a = X[base + p];
        float b = X[base + p + 32];
        size_t qo = (size_t)row * CC + hh * 64;
        Qb[qo + p]      = __float2bfloat16(0.125f * (a * cs - b * sn));
        Qb[qo + p + 32] = __float2bfloat16(0.125f * (b * cs + a * sn));
    } else if (i < NQ + NK) {
        int j = i - NQ;
        int p = j & 31;
        int tmp = j >> 5;
        int hh = tmp % KVH;
        int row = tmp / KVH;
        int t = row % TT;
        float invf = expf(-(float)p * (logf(10000.f) / 32.f));
        float ang = (float)t * invf;
        float cs = cosf(ang), sn = sinf(ang);
        size_t base = (size_t)row * QKVN + CC + hh * 64;
        float a = X[base + p];
        float b = X[base + p + 32];
        Kb[(size_t)row * KVW + hh * 64 + p]      = __float2bfloat16(a * cs - b * sn);
        Kb[(size_t)row * KVW + hh * 64 + p + 32] = __float2bfloat16(b * cs + a * sn);
    } else if (i < NQ + NK + NV) {
        int j = i - NQ - NK;
        int row = j >> 7;
        int p2 = (j & 127) * 2;
        const float* base = X + (size_t)row * QKVN + CC + KVW;
        *(__nv_bfloat162*)&Vb[(size_t)row * KVW + p2] =
            __floats2bfloat162_rn(base[p2], base[p2 + 1]);
    }
}

// ------- flash attention: 2 heads/CTA (shared K/V), 64-row Q tiles -------
// grid (TT/64, HH/2, BB), 256 threads. Warps 0-3 -> head 2y, warps 4-7 -> 2y+1.
__global__ __launch_bounds__(256) void attn_mma(const __nv_bfloat16* __restrict__ Qb,
                                                const __nv_bfloat16* __restrict__ Kb,
                                                const __nv_bfloat16* __restrict__ Vb,
                                                __nv_bfloat16* __restrict__ O) {
    int qb = blockIdx.x, hp = blockIdx.y, b = blockIdx.z;
    int tid = threadIdx.x;
    int wid = tid >> 5, lane = tid & 31;
    int hw = wid >> 2;             // head within pair (0/1)
    int wq = wid & 3;              // warp within head-group
    int h = hp * 2 + hw;
    int kvh = (hp * 2) / NREP;     // both heads in pair share kvh

    __shared__ __align__(16) __nv_bfloat16 Qs[2][64 * 72];
    __shared__ __align__(16) __nv_bfloat16 Ks[64 * 72];
    __shared__ __align__(16) __nv_bfloat16 Vs[64 * 72];

    // load both heads' Q tiles (512 uint4 per head, 256 threads)
    for (int i = tid; i < 2 * 64 * 8; i += 256) {
        int hh = i >> 9;               // 0/1
        int j = i & 511;
        int row = j >> 3, g = (j & 7) * 8;
        *(uint4*)&Qs[hh][row * 72 + g] =
            *(const uint4*)&Qb[((size_t)(b * TT + qb * 64 + row)) * CC + (hp * 2 + hh) * DH + g];
    }
    __syncthreads();

    int r16 = lane & 15, kh = lane >> 4;
    int rn = lane & 7, knh = (lane >> 3) & 1;
    uint32_t qf[4][4];
#pragma unroll
    for (int kk = 0; kk < 4; kk++) {
        uint32_t ad = su32(&Qs[hw][(wq * 16 + r16) * 72 + kk * 16 + kh * 8]);
        asm volatile("ldmatrix.sync.aligned.m8n8.x4.shared.b16 {%0,%1,%2,%3}, [%4];"
            : "=r"(qf[kk][0]), "=r"(qf[kk][1]), "=r"(qf[kk][2]), "=r"(qf[kk][3]) : "r"(ad));
    }

    int rr = lane >> 2, cq = (lane & 3) * 2;
    int t0 = qb * 64 + wq * 16 + rr;   // second row = t0+8
    float m0 = -1e30f, m1 = -1e30f, l0 = 0.f, l1 = 0.f;
    float acc[8][4];
#pragma unroll
    for (int dn = 0; dn < 8; dn++)
#pragma unroll
        for (int r = 0; r < 4; r++) acc[dn][r] = 0.f;

    int kstart = qb * 64 - WIN; if (kstart < 0) kstart = 0;
    for (int k0 = kstart; k0 <= qb * 64; k0 += 64) {
        __syncthreads();
        for (int i = tid; i < 64 * 32; i += 256) {
            int row = i >> 5, p2 = (i & 31) * 2;
            size_t kr = ((size_t)(b * TT + k0 + row)) * KVW + kvh * DH;
            *(__nv_bfloat162*)&Ks[row * 72 + p2] = *(const __nv_bfloat162*)&Kb[kr + p2];
            *(__nv_bfloat162*)&Vs[row * 72 + p2] = *(const __nv_bfloat162*)&Vb[kr + p2];
        }
        __syncthreads();

        float s[8][4];
#pragma unroll
        for (int j = 0; j < 8; j++) {
            s[j][0] = s[j][1] = s[j][2] = s[j][3] = 0.f;
#pragma unroll
            for (int kk = 0; kk < 4; kk++) {
                uint32_t bfr[2];
                uint32_t bd = su32(&Ks[(j * 8 + rn) * 72 + kk * 16 + knh * 8]);
                asm volatile("ldmatrix.sync.aligned.m8n8.x2.shared.b16 {%0,%1}, [%2];"
                    : "=r"(bfr[0]), "=r"(bfr[1]) : "r"(bd));
                asm volatile(
                    "mma.sync.aligned.m16n8k16.row.col.f32.bf16.bf16.f32 "
                    "{%0,%1,%2,%3}, {%4,%5,%6,%7}, {%8,%9}, {%0,%1,%2,%3};"
                    : "+f"(s[j][0]), "+f"(s[j][1]), "+f"(s[j][2]), "+f"(s[j][3])
                    : "r"(qf[kk][0]), "r"(qf[kk][1]), "r"(qf[kk][2]), "r"(qf[kk][3]),
                      "r"(bfr[0]), "r"(bfr[1]));
            }
        }
#pragma unroll
        for (int j = 0; j < 8; j++) {
            int kg = k0 + j * 8 + cq;
            if (kg > t0 || kg < t0 - WIN) s[j][0] = -1e30f;
            if (kg + 1 > t0 || kg + 1 < t0 - WIN) s[j][1] = -1e30f;
            if (kg > t0 + 8 || kg < t0 + 8 - WIN) s[j][2] = -1e30f;
            if (kg + 1 > t0 + 8 || kg + 1 < t0 + 8 - WIN) s[j][3] = -1e30f;
        }
        float mx0 = -1e30f, mx1 = -1e30f;
#pragma unroll
        for (int j = 0; j < 8; j++) {
            mx0 = fmaxf(mx0, fmaxf(s[j][0], s[j][1]));
            mx1 = fmaxf(mx1, fmaxf(s[j][2], s[j][3]));
        }
        mx0 = fmaxf(mx0, __shfl_xor_sync(0xffffffffu, mx0, 1));
        mx0 = fmaxf(mx0, __shfl_xor_sync(0xffffffffu, mx0, 2));
        mx1 = fmaxf(mx1, __shfl_xor_sync(0xffffffffu, mx1, 1));
        mx1 = fmaxf(mx1, __shfl_xor_sync(0xffffffffu, mx1, 2));
        float mn0 = fmaxf(m0, mx0), mn1 = fmaxf(m1, mx1);
        float c0 = __expf(m0 - mn0), c1 = __expf(m1 - mn1);
        m0 = mn0; m1 = mn1;
        l0 *= c0; l1 *= c1;
#pragma unroll
        for (int dn = 0; dn < 8; dn++) {
            acc[dn][0] *= c0; acc[dn][1] *= c0;
            acc[dn][2] *= c1; acc[dn][3] *= c1;
        }
#pragma unroll
        for (int j = 0; j < 8; j++) {
            s[j][0] = __expf(s[j][0] - m0); s[j][1] = __expf(s[j][1] - m0);
            s[j][2] = __expf(s[j][2] - m1); s[j][3] = __expf(s[j][3] - m1);
            l0 += s[j][0] + s[j][1];
            l1 += s[j][2] + s[j][3];
        }
        uint32_t pa[4][4];
#pragma unroll
        for (int kk = 0; kk < 4; kk++) {
            int j0 = kk * 2, j1 = kk * 2 + 1;
            pa[kk][0] = packbf(s[j0][0], s[j0][1]);
            pa[kk][1] = packbf(s[j0][2], s[j0][3]);
            pa[kk][2] = packbf(s[j1][0], s[j1][1]);
            pa[kk][3] = packbf(s[j1][2], s[j1][3]);
        }
#pragma unroll
        for (int dn = 0; dn < 8; dn++)
#pragma unroll
            for (int kk = 0; kk < 4; kk++) {
                uint32_t bfr[2];
                uint32_t bd = su32(&Vs[(kk * 16 + knh * 8 + rn) * 72 + dn * 8]);
                asm volatile("ldmatrix.sync.aligned.m8n8.x2.trans.shared.b16 {%0,%1}, [%2];"
                    : "=r"(bfr[0]), "=r"(bfr[1]) : "r"(bd));
                asm volatile(
                    "mma.sync.aligned.m16n8k16.row.col.f32.bf16.bf16.f32 "
                    "{%0,%1,%2,%3}, {%4,%5,%6,%7}, {%8,%9}, {%0,%1,%2,%3};"
                    : "+f"(acc[dn][0]), "+f"(acc[dn][1]), "+f"(acc[dn][2]), "+f"(acc[dn][3])
                    : "r"(pa[kk][0]), "r"(pa[kk][1]), "r"(pa[kk][2]), "r"(pa[kk][3]),
                      "r"(bfr[0]), "r"(bfr[1]));
            }
    }
    l0 += __shfl_xor_sync(0xffffffffu, l0, 1);
    l0 += __shfl_xor_sync(0xffffffffu, l0, 2);
    l1 += __shfl_xor_sync(0xffffffffu, l1, 1);
    l1 += __shfl_xor_sync(0xffffffffu, l1, 2);
    float i0 = 1.f / l0, i1 = 1.f / l1;
    __nv_bfloat16* o0 = O + ((size_t)(b * TT + t0)) * CC + h * DH;
    __nv_bfloat16* o1 = o0 + (size_t)8 * CC;
#pragma unroll
    for (int dn = 0; dn < 8; dn++) {
        *(__nv_bfloat162*)&o0[dn * 8 + cq] =
            __floats2bfloat162_rn(acc[dn][0] * i0, acc[dn][1] * i0);
        *(__nv_bfloat162*)&o1[dn * 8 + cq] =
            __floats2bfloat162_rn(acc[dn][2] * i1, acc[dn][3] * i1);
    }
}

// ---------------- router ----------------
__global__ void route_kernel(const float* __restrict__ xf,
                             const float* __restrict__ gw) {
    int warp = threadIdx.x >> 5, lane = threadIdx.x & 31;
    int tok = blockIdx.x * 4 + warp;
    if (tok >= NTOK) return;
    const float* xr = xf + (size_t)tok * CC;
    float part[EE];
#pragma unroll
    for (int e = 0; e < EE; e++) part[e] = 0.f;
    for (int d = lane; d < CC; d += 32) {
        float xv = xr[d];
#pragma unroll
        for (int e = 0; e < EE; e++) part[e] += xv * gw[d * EE + e];
    }
#pragma unroll
    for (int e = 0; e < EE; e++)
#pragma unroll
        for (int o = 16; o > 0; o >>= 1)
            part[e] += __shfl_xor_sync(0xffffffffu, part[e], o);
    if (lane == 0) {
        float v0 = -1e30f; int i0 = 0;
#pragma unroll
        for (int e = 0; e < EE; e++) if (part[e] > v0) { v0 = part[e]; i0 = e; }
        float v1 = -1e30f; int i1 = 0;
#pragma unroll
        for (int e = 0; e < EE; e++)
            if (e != i0 && part[e] > v1) { v1 = part[e]; i1 = e; }
        float ex = expf(v1 - v0);
        float w0 = 1.f / (1.f + ex);
        float w1 = ex / (1.f + ex);
        g_sel[tok * 2] = i0; g_sel[tok * 2 + 1] = i1;
        g_selw[tok * 2] = w0; g_selw[tok * 2 + 1] = w1;
        float mx = v0, sum = 0.f, pe[EE];
#pragma unroll
        for (int e = 0; e < EE; e++) { pe[e] = expf(part[e] - mx); sum += pe[e]; }
#pragma unroll
        for (int e = 0; e < EE; e++) g_probs[tok * EE + e] = pe[e] / sum;
        float lse = mx + logf(sum);
        g_lse2[tok] = lse * lse;
    }
}

// ---------------- aux loss ----------------
__global__ void aux_kernel() {
    __shared__ float red[256];
    int tid = threadIdx.x;
    float loadv[EE];
#pragma unroll
    for (int e = 0; e < EE; e++) loadv[e] = 0.f;
    for (int n = tid; n < NTOK; n += 256) {
#pragma unroll
        for (int e = 0; e < EE; e++) loadv[e] += g_probs[n * EE + e];
    }
    float loads[EE];
    for (int e = 0; e < EE; e++) {
        red[tid] = loadv[e]; __syncthreads();
        for (int o = 128; o > 0; o >>= 1) {
            if (tid < o) red[tid] += red[tid + o];
            __syncthreads();
        }
        loads[e] = red[0]; __syncthreads();
    }
    float zp = 0.f;
    for (int n = tid; n < NTOK; n += 256) zp += g_lse2[n];
    red[tid] = zp; __syncthreads();
    for (int o = 128; o > 0; o >>= 1) {
        if (tid < o) red[tid] += red[tid + o];
        __syncthreads();
    }
    if (tid == 0) {
        float tot = 0.f;
        for (int e = 0; e < EE; e++) tot += loads[e];
        float lb = 0.f;
        for (int e = 0; e < EE; e++) { float f = loads[e] / tot; lb += f * f; }
        lb *= (float)EE;
        float z = red[0] / (float)NTOK;
        g_aux = 0.01f * lb + 0.001f * z;
    }
}

__global__ void zero_cnt_kernel() { if (threadIdx.x < EE) g_cnt[threadIdx.x] = 0; }

__global__ void count_kernel() {
    int i = blockIdx.x * blockDim.x + threadIdx.x;
    if (i >= NTOK) return;
#pragma unroll
    for (int kk = 0; kk < TOPK; kk++)
        atomicAdd(&g_cnt[g_sel[i * 2 + kk]], 1);
}

__global__ void offsets_kernel() {
    if (threadIdx.x == 0) {
        int acc = 0;
        for (int e = 0; e < EE; e++) {
            g_off[e] = acc;
            acc += (g_cnt[e] + BM - 1) & ~(BM - 1);
            g_cnt2[e] = 0;
        }
        g_off[EE] = acc;
    }
}

__global__ void assign_kernel() {
    int i = blockIdx.x * blockDim.x + threadIdx.x;
    if (i >= NTOK) return;
#pragma unroll
    for (int kk = 0; kk < TOPK; kk++) {
        int e = g_sel[i * 2 + kk];
        int pos = atomicAdd(&g_cnt2[e], 1);
        int row = g_off[e] + pos;
        g_idx[row] = i;
        g_tokrow[i * 2 + kk] = row;
    }
}

__global__ void gather_all_kernel(__nv_bfloat16* __restrict__ dst,
                                  const __nv_bfloat16* __restrict__ src) {
    int b = blockIdx.x;
    if (b >= g_off[EE]) return;
    int e = 0;
    while (g_off[e + 1] <= b) e++;
    if (b - g_off[e] >= g_cnt[e]) return;
    int t = g_idx[b];
    uint4* d4 = (uint4*)(dst + (size_t)b * CC);
    const uint4* s4 = (const uint4*)(src + (size_t)t * CC);
    int i = threadIdx.x;
    if (i < CC * 2 / 16) d4[i] = s4[i];
}

// final: out = h + a_moe * (shared + w0*eo[r0] + w1*eo[r1]); writes aux too
__global__ void final_kernel(const float* __restrict__ h, const float* __restrict__ moe,
                             const float* __restrict__ eo,
                             const float* __restrict__ alpha, float* __restrict__ out,
                             int writeAux) {
    int t = blockIdx.x;
    if (writeAux && t == 0 && threadIdx.x == 0) out[OUT_MAIN] = g_aux;
    float w0 = g_selw[t * 2], w1 = g_selw[t * 2 + 1];
    int r0 = g_tokrow[t * 2], r1 = g_tokrow[t * 2 + 1];
    float a = *alpha;
    const float* hr = h + (size_t)t * CC;
    const float* mr = moe + (size_t)t * CC;
    const float* e0 = eo + (size_t)r0 * CC;
    const float* e1 = eo + (size_t)r1 * CC;
    float* orow = out + (size_t)t * CC;
    for (int i = threadIdx.x; i < CC; i += blockDim.x)
        orow[i] = hr[i] + a * (mr[i] + w0 * e0[i] + w1 * e1[i]);
}

// ---------------- launch ----------------
extern "C" void kernel_launch(void* const* d_in, const int* in_sizes, int n_in,
                              void* d_out, int out_size) {
    const float* x      = (const float*)d_in[0];
    const float* ln1    = (const float*)d_in[1];
    const float* ln2    = (const float*)d_in[2];
    const float* wq     = (const float*)d_in[3];
    const float* wk     = (const float*)d_in[4];
    const float* wv     = (const float*)d_in[5];
    const float* wo     = (const float*)d_in[6];
    const float* sw1    = (const float*)d_in[7];
    const float* sw2    = (const float*)d_in[8];
    const float* sw3    = (const float*)d_in[9];
    const float* ew1    = (const float*)d_in[10];
    const float* ew2    = (const float*)d_in[11];
    const float* ew3    = (const float*)d_in[12];
    const float* gatew  = (const float*)d_in[13];
    const float* a_attn = (const float*)d_in[14];
    const float* a_moe  = (const float*)d_in[15];
    float* out = (float*)d_out;

    void* p;
    float *qkv, *h, *xf, *moe, *eo;
    __nv_bfloat16 *xnb, *qb, *aob, *xfb, *xgb, *g1b, *kb, *vb;
    __nv_bfloat16 *wqkvt, *wot, *sw12t, *sw3t, *ew12t, *ew3t;
    cudaGetSymbolAddress(&p, g_qkv);  qkv  = (float*)p;
    cudaGetSymbolAddress(&p, g_h);    h    = (float*)p;
    cudaGetSymbolAddress(&p, g_xf);   xf   = (float*)p;
    cudaGetSymbolAddress(&p, g_moe);  moe  = (float*)p;
    cudaGetSymbolAddress(&p, g_eo);   eo   = (float*)p;
    cudaGetSymbolAddress(&p, g_xnb);  xnb  = (__nv_bfloat16*)p;
    cudaGetSymbolAddress(&p, g_qb);   qb   = (__nv_bfloat16*)p;
    cudaGetSymbolAddress(&p, g_aob);  aob  = (__nv_bfloat16*)p;
    cudaGetSymbolAddress(&p, g_xfb);  xfb  = (__nv_bfloat16*)p;
    cudaGetSymbolAddress(&p, g_xgb);  xgb  = (__nv_bfloat16*)p;
    cudaGetSymbolAddress(&p, g_g1b);  g1b  = (__nv_bfloat16*)p;
    cudaGetSymbolAddress(&p, g_kb);   kb   = (__nv_bfloat16*)p;
    cudaGetSymbolAddress(&p, g_vb);   vb   = (__nv_bfloat16*)p;
    cudaGetSymbolAddress(&p, g_wqkvt); wqkvt = (__nv_bfloat16*)p;
    cudaGetSymbolAddress(&p, g_wot);   wot   = (__nv_bfloat16*)p;
    cudaGetSymbolAddress(&p, g_sw12t); sw12t = (__nv_bfloat16*)p;
    cudaGetSymbolAddress(&p, g_sw3t);  sw3t  = (__nv_bfloat16*)p;
    cudaGetSymbolAddress(&p, g_ew12t); ew12t = (__nv_bfloat16*)p;
    cudaGetSymbolAddress(&p, g_ew3t);  ew3t  = (__nv_bfloat16*)p;

    static bool s_init = false;
    static cudaStream_t s2 = 0;
    static cudaEvent_t evA = 0, evB = 0, evC = 0, evD = 0, evE = 0;
    if (!s_init) {
        if (cudaStreamCreateWithFlags(&s2, cudaStreamNonBlocking) != cudaSuccess) s2 = 0;
        if (s2) {
            bool ok = true;
            ok &= (cudaEventCreateWithFlags(&evA, cudaEventDisableTiming) == cudaSuccess);
            ok &= (cudaEventCreateWithFlags(&evB, cudaEventDisableTiming) == cudaSuccess);
            ok &= (cudaEventCreateWithFlags(&evC, cudaEventDisableTiming) == cudaSuccess);
            ok &= (cudaEventCreateWithFlags(&evD, cudaEventDisableTiming) == cudaSuccess);
            ok &= (cudaEventCreateWithFlags(&evE, cudaEventDisableTiming) == cudaSuccess);
            if (!ok) s2 = 0;
        }
        s_init = true;
    }
    bool forked = (s2 != 0);

    // critical-path conversions (attention weights only)
    wcvt<<<512, 256>>>(wq, wqkvt, CC, QKVN, 0, 0, 0, (long)CC*CC/8);
    wcvt<<<128, 256>>>(wk, wqkvt, KVW, QKVN, CC, 0, 0, (long)CC*KVW/8);
    wcvt<<<128, 256>>>(wv, wqkvt, KVW, QKVN, CC+KVW, 0, 0, (long)CC*KVW/8);
    wcvt<<<512, 256>>>(wo, wot, CC, CC, 0, 0, 0, (long)CC*CC/8);

    // FFN weight conversions forked onto s2 (shared first, then experts)
    if (forked) {
        cudaEventRecord(evA, 0);
        cudaStreamWaitEvent(s2, evA, 0);
        wcvt_pair<<<4096, 256, 0, s2>>>(sw1, sw2, sw12t, FF, 0, 0, (long)CC*FF/4);
        wcvt<<<2048, 256, 0, s2>>>(sw3, sw3t, CC, CC, 0, 0, 0, (long)FF*CC/8);
        cudaEventRecord(evE, s2);
        wcvt_pair<<<dim3(4096,1,EE), 256, 0, s2>>>(ew1, ew2, ew12t, FF,
            (long)CC*FF, (long)CC*2*FF, (long)CC*FF/4);
        wcvt<<<dim3(2048,1,EE), 256, 0, s2>>>(ew3, ew3t, CC, CC, 0,
            (long)FF*CC, (long)FF*CC, (long)FF*CC/8);
        cudaEventRecord(evB, s2);
    } else {
        wcvt_pair<<<4096, 256>>>(sw1, sw2, sw12t, FF, 0, 0, (long)CC*FF/4);
        wcvt<<<2048, 256>>>(sw3, sw3t, CC, CC, 0, 0, 0, (long)FF*CC/8);
        wcvt_pair<<<dim3(4096,1,EE), 256>>>(ew1, ew2, ew12t, FF,
            (long)CC*FF, (long)CC*2*FF, (long)CC*FF/4);
        wcvt<<<dim3(2048,1,EE), 256>>>(ew3, ew3t, CC, CC, 0,
            (long)FF*CC, (long)FF*CC, (long)FF*CC/8);
    }

    // 1) pre-attn norm
    rmsnorm_kernel<<<NTOK, 256>>>(x, ln1, nullptr, xnb);
    // 2) fused QKV projection
    gemm_mma<<<dim3(QKVN/128, NTOK/128), 256>>>(xnb, wqkvt, qkv, QKVN, CC);
    // 3) fused RoPE(q,k) + Q/K/V bf16 compaction
    {
        int total = NTOK*HH*32 + NTOK*KVH*32 + NTOK*(KVW/2);
        rope_all_kernel<<<(total + 255) / 256, 256>>>(qkv, qb, kb, vb);
    }
    // 4) attention (tensor core, 2 heads/CTA with shared K/V)
    attn_mma<<<dim3(TT/64, HH/2, BB), 256>>>(qb, kb, vb, aob);
    // 5) output projection with fused ReZero residual
    gemm_mma_add<<<dim3(CC/128, NTOK/128), 256>>>(aob, wot, x, a_attn, h, CC, CC);
    // 6) post-attn norm
    rmsnorm_kernel<<<NTOK, 256>>>(h, ln2, xf, xfb);
    // 7) routing + aux + compaction — forked onto s2, overlapped with shared GEMMs
    if (forked) {
        cudaEventRecord(evC, 0);
        cudaStreamWaitEvent(s2, evC, 0);
        route_kernel<<<NTOK / 4, 128, 0, s2>>>(xf, gatew);
        aux_kernel<<<1, 256, 0, s2>>>();
        zero_cnt_kernel<<<1, 32, 0, s2>>>();
        count_kernel<<<(NTOK + 255) / 256, 256, 0, s2>>>();
        offsets_kernel<<<1, 32, 0, s2>>>();
        assign_kernel<<<(NTOK + 255) / 256, 256, 0, s2>>>();
        cudaEventRecord(evD, s2);
    } else {
        route_kernel<<<NTOK / 4, 128>>>(xf, gatew);
        aux_kernel<<<1, 256>>>();
        zero_cnt_kernel<<<1, 32>>>();
        count_kernel<<<(NTOK + 255) / 256, 256>>>();
        offsets_kernel<<<1, 32>>>();
        assign_kernel<<<(NTOK + 255) / 256, 256>>>();
    }
    // 8) shared expert: fused w12+SwiGLU, then w3 (join shared-weight conversion)
    if (forked) cudaStreamWaitEvent(0, evE, 0);
    gemm_swiglu<<<dim3(2*FF/128, NTOK/128), 256>>>(xfb, sw12t, g1b, 2*FF, CC);
    gemm_mma<<<dim3(CC/128, NTOK/128), 256>>>(g1b, sw3t, moe, CC, FF);
    // 9) routed experts, batched (join routing + expert weights first)
    if (forked) cudaStreamWaitEvent(0, evD, 0);
    gather_all_kernel<<<ECAP, 128>>>(xgb, xfb);
    if (forked) cudaStreamWaitEvent(0, evB, 0);
    gemm_moe_swiglu<<<dim3(2*FF/128, ECAP/128), 256>>>(xgb, ew12t, g1b, 2*FF, CC, (long)CC*2*FF);
    gemm_moe<<<dim3(CC/128, ECAP/128), 256>>>(g1b, ew3t, eo, CC, FF, (long)FF*CC);
    // 10) final combine + aux scalar (fused)
    final_kernel<<<NTOK, 256>>>(h, moe, eo, a_moe, out, out_size > OUT_MAIN ? 1 : 0);
}

// round 14
// speedup vs baseline: 1.2505x; 1.0040x over previous
#include <cuda_runtime.h>
#include <cuda_bf16.h>
#include <math.h>
#include <stdint.h>

// Problem constants
#define BB   2
#define TT   2048
#define CC   1024
#define HH   16
#define KVH  4
#define DH   64
#define NREP 4
#define FF   4096
#define EE   8
#define TOPK 2
#define WIN  1024
#define NTOK (BB*TT)            // 4096
#define OUT_MAIN (NTOK*CC)      // 4194304
#define QKVN (CC + 2*KVH*DH)    // 1536
#define KVW  (KVH*DH)           // 256
#define ECAP 9216               // 8192 real rows + padding, 128-aligned

// ---------------- scratch (device globals; no allocation) ----------------
__device__ float g_qkv [NTOK*QKVN];
__device__ float g_h   [NTOK*CC];
__device__ float g_xf  [NTOK*CC];
__device__ float g_moe [NTOK*CC];
__device__ float g_eo  [(size_t)ECAP*CC];
__device__ float g_probs[NTOK*EE];
__device__ float g_lse2[NTOK];
__device__ int   g_sel [NTOK*2];
__device__ float g_selw[NTOK*2];
__device__ int   g_cnt [EE];
__device__ int   g_cnt2[EE];
__device__ int   g_off [EE+1];
__device__ int   g_idx [ECAP];
__device__ int   g_tokrow[NTOK*2];
__device__ float g_aux;

// bf16 activations
__device__ __nv_bfloat16 g_xnb [NTOK*CC];
__device__ __nv_bfloat16 g_qb  [NTOK*CC];
__device__ __nv_bfloat16 g_aob [NTOK*CC];
__device__ __nv_bfloat16 g_xfb [NTOK*CC];
__device__ __nv_bfloat16 g_xgb [(size_t)ECAP*CC];
__device__ __nv_bfloat16 g_g1b [(size_t)ECAP*FF];
__device__ __nv_bfloat16 g_kb  [NTOK*KVW];
__device__ __nv_bfloat16 g_vb  [NTOK*KVW];

// bf16 weights, K-major [K,N] (w12 column-interleaved: w1->2f, w2->2f+1)
__device__ __nv_bfloat16 g_wqkvt[CC*QKVN];
__device__ __nv_bfloat16 g_wot  [CC*CC];
__device__ __nv_bfloat16 g_sw12t[CC*2*FF];
__device__ __nv_bfloat16 g_sw3t [FF*CC];
__device__ __nv_bfloat16 g_ew12t[(size_t)EE*CC*2*FF];
__device__ __nv_bfloat16 g_ew3t [(size_t)EE*FF*CC];

__device__ __forceinline__ uint32_t su32(const void* p) {
    uint32_t a;
    asm("{ .reg .u64 t; cvta.to.shared.u64 t, %1; cvt.u32.u64 %0, t; }" : "=r"(a) : "l"(p));
    return a;
}
__device__ __forceinline__ uint32_t packbf(float a, float b) {
    __nv_bfloat162 t = __floats2bfloat162_rn(a, b);
    return *(uint32_t*)&t;
}

#define CP_ASYNC16(d, s) asm volatile("cp.async.cg.shared.global [%0], [%1], 16;" :: "r"(d), "l"(s))
#define CP_COMMIT()      asm volatile("cp.async.commit_group;" ::: "memory")
#define CP_WAIT(n)       asm volatile("cp.async.wait_group %0;" :: "n"(n) : "memory")

#define BM 128
#define BN 128
#define BK 32
#define ASTR 40    // A smem row stride (bf16 elems)
#define BSTR 136   // B smem row stride (bf16 elems)

// ================= 2-stage GEMM mainloop; B is [K,N] via ldmatrix.x4.trans
#define GEMM_MAIN(A_, Bt_, N_, K_)                                             \
    __shared__ __align__(16) __nv_bfloat16 sA[2][BM * ASTR];                   \
    __shared__ __align__(16) __nv_bfloat16 sB[2][BK * BSTR];                   \
    int tid = threadIdx.x;                                                     \
    int wid = tid >> 5, lane = tid & 31;                                       \
    int wm = wid >> 2, wn = wid & 3;                                           \
    float cr[4][4][4];                                                         \
    _Pragma("unroll") for (int i = 0; i < 4; i++)                              \
    _Pragma("unroll") for (int j = 0; j < 4; j++)                              \
    _Pragma("unroll") for (int r = 0; r < 4; r++) cr[i][j][r] = 0.f;           \
    int lrow = tid >> 1;                                                       \
    int lc16 = (tid & 1) * 16;                                                 \
    int nCh = (K_) / BK;                                                       \
    {                                                                          \
        const __nv_bfloat16* srcA0 = (A_) + (size_t)(rowBase + lrow) * (K_) + lc16; \
        uint32_t dA0 = su32(&sA[0][lrow * ASTR + lc16]);                       \
        CP_ASYNC16(dA0, srcA0); CP_ASYNC16(dA0 + 16, srcA0 + 8);               \
        _Pragma("unroll") for (int bi = 0; bi < 2; bi++) {                     \
            int seg = tid + bi * 256;                                          \
            int brow = seg >> 4, bcol = (seg & 15) * 8;                        \
            const __nv_bfloat16* srcB = (Bt_) + (size_t)brow * (N_) + colBase + bcol; \
            CP_ASYNC16(su32(&sB[0][brow * BSTR + bcol]), srcB);                \
        }                                                                      \
        CP_COMMIT();                                                           \
    }                                                                          \
    for (int ch = 0; ch < nCh; ch++) {                                         \
        int st = ch & 1;                                                       \
        if (ch + 1 < nCh) {                                                    \
            int k0 = (ch + 1) * BK;                                            \
            const __nv_bfloat16* srcA = (A_) + (size_t)(rowBase + lrow) * (K_) + k0 + lc16; \
            uint32_t dA = su32(&sA[st ^ 1][lrow * ASTR + lc16]);               \
            CP_ASYNC16(dA, srcA); CP_ASYNC16(dA + 16, srcA + 8);               \
            _Pragma("unroll") for (int bi = 0; bi < 2; bi++) {                 \
                int seg = tid + bi * 256;                                      \
                int brow = seg >> 4, bcol = (seg & 15) * 8;                    \
                const __nv_bfloat16* srcB = (Bt_) + (size_t)(k0 + brow) * (N_) + colBase + bcol; \
                CP_ASYNC16(su32(&sB[st ^ 1][brow * BSTR + bcol]), srcB);       \
            }                                                                  \
            CP_COMMIT(); CP_WAIT(1);                                           \
        } else { CP_WAIT(0); }                                                 \
        __syncthreads();                                                       \
        int r16 = lane & 15, kh = lane >> 4;                                   \
        int brl = (lane & 7) + ((lane >> 3) & 1) * 8;   /* row within 16 */    \
        int bcl = ((lane >> 4) & 1) * 8;                /* col half */         \
        _Pragma("unroll") for (int kk = 0; kk < 2; kk++) {                     \
            uint32_t af[4][4];                                                 \
            _Pragma("unroll") for (int mf = 0; mf < 4; mf++) {                 \
                uint32_t ad = su32(&sA[st][(wm * 64 + mf * 16 + r16) * ASTR + kk * 16 + kh * 8]); \
                asm volatile("ldmatrix.sync.aligned.m8n8.x4.shared.b16 {%0,%1,%2,%3}, [%4];" \
                    : "=r"(af[mf][0]), "=r"(af[mf][1]), "=r"(af[mf][2]), "=r"(af[mf][3]) : "r"(ad)); \
            }                                                                  \
            uint32_t bfr[4][2];                                                \
            _Pragma("unroll") for (int nfp = 0; nfp < 2; nfp++) {              \
                uint32_t bd = su32(&sB[st][(kk * 16 + brl) * BSTR + wn * 32 + nfp * 16 + bcl]); \
                asm volatile("ldmatrix.sync.aligned.m8n8.x4.trans.shared.b16 {%0,%1,%2,%3}, [%4];" \
                    : "=r"(bfr[2*nfp][0]), "=r"(bfr[2*nfp][1]),                \
                      "=r"(bfr[2*nfp+1][0]), "=r"(bfr[2*nfp+1][1]) : "r"(bd)); \
            }                                                                  \
            _Pragma("unroll") for (int mf = 0; mf < 4; mf++)                   \
            _Pragma("unroll") for (int nf = 0; nf < 4; nf++) {                 \
                asm volatile(                                                  \
                    "mma.sync.aligned.m16n8k16.row.col.f32.bf16.bf16.f32 "     \
                    "{%0,%1,%2,%3}, {%4,%5,%6,%7}, {%8,%9}, {%0,%1,%2,%3};"    \
                    : "+f"(cr[mf][nf][0]), "+f"(cr[mf][nf][1]),                \
                      "+f"(cr[mf][nf][2]), "+f"(cr[mf][nf][3])                 \
                    : "r"(af[mf][0]), "r"(af[mf][1]), "r"(af[mf][2]), "r"(af[mf][3]), \
                      "r"(bfr[nf][0]), "r"(bfr[nf][1]));                       \
            }                                                                  \
        }                                                                      \
        __syncthreads();                                                       \
    }                                                                          \
    int rr = lane >> 2, cq = (lane & 3) * 2;

// ================= dense GEMM, fp32 out =================
__global__ __launch_bounds__(256) void gemm_mma(
    const __nv_bfloat16* __restrict__ A, const __nv_bfloat16* __restrict__ Bt,
    float* __restrict__ C, int N, int K)
{
    int rowBase = blockIdx.y * BM, colBase = blockIdx.x * BN;
    GEMM_MAIN(A, Bt, N, K)
#pragma unroll
    for (int mf = 0; mf < 4; mf++)
#pragma unroll
        for (int nf = 0; nf < 4; nf++) {
            int row0 = rowBase + wm * 64 + mf * 16 + rr;
            int col = colBase + wn * 32 + nf * 8 + cq;
            *(float2*)&C[(size_t)row0 * N + col] = make_float2(cr[mf][nf][0], cr[mf][nf][1]);
            *(float2*)&C[(size_t)(row0 + 8) * N + col] = make_float2(cr[mf][nf][2], cr[mf][nf][3]);
        }
}

// ===== dense GEMM with fused ReZero residual: C = X + (*alpha)*(A@Bt) ====
__global__ __launch_bounds__(256) void gemm_mma_add(
    const __nv_bfloat16* __restrict__ A, const __nv_bfloat16* __restrict__ Bt,
    const float* __restrict__ X, const float* __restrict__ alpha,
    float* __restrict__ C, int N, int K)
{
    int rowBase = blockIdx.y * BM, colBase = blockIdx.x * BN;
    GEMM_MAIN(A, Bt, N, K)
    float a = *alpha;
#pragma unroll
    for (int mf = 0; mf < 4; mf++)
#pragma unroll
        for (int nf = 0; nf < 4; nf++) {
            int row0 = rowBase + wm * 64 + mf * 16 + rr;
            int col = colBase + wn * 32 + nf * 8 + cq;
            float2 x0 = *(const float2*)&X[(size_t)row0 * N + col];
            float2 x1 = *(const float2*)&X[(size_t)(row0 + 8) * N + col];
            *(float2*)&C[(size_t)row0 * N + col] =
                make_float2(x0.x + a * cr[mf][nf][0], x0.y + a * cr[mf][nf][1]);
            *(float2*)&C[(size_t)(row0 + 8) * N + col] =
                make_float2(x1.x + a * cr[mf][nf][2], x1.y + a * cr[mf][nf][3]);
        }
}

// ================= dense GEMM, fused SwiGLU bf16 out (interleaved w12) ===
__global__ __launch_bounds__(256) void gemm_swiglu(
    const __nv_bfloat16* __restrict__ A, const __nv_bfloat16* __restrict__ Bt,
    __nv_bfloat16* __restrict__ Obf, int N2, int K)
{
    int rowBase = blockIdx.y * BM, colBase = blockIdx.x * BN;
    GEMM_MAIN(A, Bt, N2, K)
    int FFo = N2 >> 1;
#pragma unroll
    for (int mf = 0; mf < 4; mf++)
#pragma unroll
        for (int nf = 0; nf < 4; nf++) {
            int row0 = rowBase + wm * 64 + mf * 16 + rr;
            int f = (colBase + wn * 32 + nf * 8 + cq) >> 1;
            float a0 = cr[mf][nf][0], b0 = cr[mf][nf][1];
            Obf[(size_t)row0 * FFo + f] = __float2bfloat16(a0 / (1.f + __expf(-a0)) * b0);
            float a1 = cr[mf][nf][2], b1 = cr[mf][nf][3];
            Obf[(size_t)(row0 + 8) * FFo + f] = __float2bfloat16(a1 / (1.f + __expf(-a1)) * b1);
        }
}

// ================= MoE GEMM, fp32 out =================
__global__ __launch_bounds__(256) void gemm_moe(
    const __nv_bfloat16* __restrict__ A, const __nv_bfloat16* __restrict__ Wb,
    float* __restrict__ C, int N, int K, long wstride)
{
    int rowBase = blockIdx.y * BM;
    if (rowBase >= g_off[EE]) return;
    int colBase = blockIdx.x * BN;
    int e = 0;
    while (g_off[e + 1] <= rowBase) e++;
    const __nv_bfloat16* Bt = Wb + (size_t)e * wstride;
    GEMM_MAIN(A, Bt, N, K)
#pragma unroll
    for (int mf = 0; mf < 4; mf++)
#pragma unroll
        for (int nf = 0; nf < 4; nf++) {
            int row0 = rowBase + wm * 64 + mf * 16 + rr;
            int col = colBase + wn * 32 + nf * 8 + cq;
            *(float2*)&C[(size_t)row0 * N + col] = make_float2(cr[mf][nf][0], cr[mf][nf][1]);
            *(float2*)&C[(size_t)(row0 + 8) * N + col] = make_float2(cr[mf][nf][2], cr[mf][nf][3]);
        }
}

// ================= MoE GEMM, fused SwiGLU bf16 out =================
__global__ __launch_bounds__(256) void gemm_moe_swiglu(
    const __nv_bfloat16* __restrict__ A, const __nv_bfloat16* __restrict__ Wb,
    __nv_bfloat16* __restrict__ Obf, int N2, int K, long wstride)
{
    int rowBase = blockIdx.y * BM;
    if (rowBase >= g_off[EE]) return;
    int colBase = blockIdx.x * BN;
    int e = 0;
    while (g_off[e + 1] <= rowBase) e++;
    const __nv_bfloat16* Bt = Wb + (size_t)e * wstride;
    GEMM_MAIN(A, Bt, N2, K)
    int FFo = N2 >> 1;
#pragma unroll
    for (int mf = 0; mf < 4; mf++)
#pragma unroll
        for (int nf = 0; nf < 4; nf++) {
            int row0 = rowBase + wm * 64 + mf * 16 + rr;
            int f = (colBase + wn * 32 + nf * 8 + cq) >> 1;
            float a0 = cr[mf][nf][0], b0 = cr[mf][nf][1];
            Obf[(size_t)row0 * FFo + f] = __float2bfloat16(a0 / (1.f + __expf(-a0)) * b0);
            float a1 = cr[mf][nf][2], b1 = cr[mf][nf][3];
            Obf[(size_t)(row0 + 8) * FFo + f] = __float2bfloat16(a1 / (1.f + __expf(-a1)) * b1);
        }
}

// ---------------- streaming weight convert: [K,NWs] f32 -> [K,NWd] bf16 --
__global__ void wcvt(const float* __restrict__ src, __nv_bfloat16* __restrict__ dst,
                     int NWs, int NWd, int coff, long sstride, long dstride, long total8) {
    long i = (long)blockIdx.x * blockDim.x + threadIdx.x;
    if (i >= total8) return;
    long e = i * 8;
    int k = (int)(e / NWs);
    int n = (int)(e - (long)k * NWs);
    const float* s = src + (size_t)blockIdx.z * sstride + (size_t)k * NWs + n;
    float4 v0 = *(const float4*)s;
    float4 v1 = *(const float4*)(s + 4);
    __nv_bfloat16 o[8];
    o[0] = __float2bfloat16(v0.x); o[1] = __float2bfloat16(v0.y);
    o[2] = __float2bfloat16(v0.z); o[3] = __float2bfloat16(v0.w);
    o[4] = __float2bfloat16(v1.x); o[5] = __float2bfloat16(v1.y);
    o[6] = __float2bfloat16(v1.z); o[7] = __float2bfloat16(v1.w);
    *(uint4*)&dst[(size_t)blockIdx.z * dstride + (size_t)k * NWd + coff + n] = *(uint4*)o;
}

// ---------------- streaming pair convert: w1,w2 [K,NW] -> [K,2NW] interleaved
__global__ void wcvt_pair(const float* __restrict__ s1, const float* __restrict__ s2,
                          __nv_bfloat16* __restrict__ dst,
                          int NW, long sstride, long dstride, long total4) {
    long i = (long)blockIdx.x * blockDim.x + threadIdx.x;
    if (i >= total4) return;
    long e = i * 4;
    int k = (int)(e / NW);
    int f = (int)(e - (long)k * NW);
    size_t so = (size_t)blockIdx.z * sstride + (size_t)k * NW + f;
    float4 va = *(const float4*)(s1 + so);
    float4 vb = *(const float4*)(s2 + so);
    __nv_bfloat16 o[8];
    o[0] = __float2bfloat16(va.x); o[1] = __float2bfloat16(vb.x);
    o[2] = __float2bfloat16(va.y); o[3] = __float2bfloat16(vb.y);
    o[4] = __float2bfloat16(va.z); o[5] = __float2bfloat16(vb.z);
    o[6] = __float2bfloat16(va.w); o[7] = __float2bfloat16(vb.w);
    *(uint4*)&dst[(size_t)blockIdx.z * dstride + (size_t)k * (2 * NW) + 2 * f] = *(uint4*)o;
}

// ---------------- RMSNorm (dual output) ----------------
__global__ void rmsnorm_kernel(const float* __restrict__ x,
                               const float* __restrict__ w,
                               float* __restrict__ of,
                               __nv_bfloat16* __restrict__ ob) {
    int row = blockIdx.x;
    int tid = threadIdx.x;
    const float* xr = x + (size_t)row * CC;
    float s = 0.f;
    for (int i = tid; i < CC; i += 256) { float v = xr[i]; s += v * v; }
    __shared__ float red[256];
    red[tid] = s; __syncthreads();
    for (int o2 = 128; o2 > 0; o2 >>= 1) {
        if (tid < o2) red[tid] += red[tid + o2];
        __syncthreads();
    }
    float scale = rsqrtf(red[0] / (float)CC + 1e-6f);
    for (int i = tid; i < CC; i += 256) {
        float v = xr[i] * scale * w[i];
        if (of) of[(size_t)row * CC + i] = v;
        ob[(size_t)row * CC + i] = __float2bfloat16(v);
    }
}

// ------- fused RoPE(q,k) + Q bf16 (pre-scaled) + K/V bf16 compaction -----
__global__ void rope_all_kernel(const float* __restrict__ X,
                                __nv_bfloat16* __restrict__ Qb,
                                __nv_bfloat16* __restrict__ Kb,
                                __nv_bfloat16* __restrict__ Vb) {
    int i = blockIdx.x * blockDim.x + threadIdx.x;
    const int NQ = NTOK * HH * 32;
    const int NK = NTOK * KVH * 32;
    const int NV = NTOK * (KVW / 2);
    if (i < NQ) {
        int p = i & 31;
        int tmp = i >> 5;
        int hh = tmp % HH;
        int row = tmp / HH;
        int t = row % TT;
        float invf = expf(-(float)p * (logf(10000.f) / 32.f));
        float ang = (float)t * invf;
        float cs = cosf(ang), sn = sinf(ang);
        size_t base = (size_t)row * QKVN + hh * 64;
        float a = X[base + p];
        float b = X[base + p + 32];
        size_t qo = (size_t)row * CC + hh * 64;
        Qb[qo + p]      = __float2bfloat16(0.125f * (a * cs - b * sn));
        Qb[qo + p + 32] = __float2bfloat16(0.125f * (b * cs + a * sn));
    } else if (i < NQ + NK) {
        int j = i - NQ;
        int p = j & 31;
        int tmp = j >> 5;
        int hh = tmp % KVH;
        int row = tmp / KVH;
        int t = row % TT;
        float invf = expf(-(float)p * (logf(10000.f) / 32.f));
        float ang = (float)t * invf;
        float cs = cosf(ang), sn = sinf(ang);
        size_t base = (size_t)row * QKVN + CC + hh * 64;
        float a = X[base + p];
        float b = X[base + p + 32];
        Kb[(size_t)row * KVW + hh * 64 + p]      = __float2bfloat16(a * cs - b * sn);
        Kb[(size_t)row * KVW + hh * 64 + p + 32] = __float2bfloat16(b * cs + a * sn);
    } else if (i < NQ + NK + NV) {
        int j = i - NQ - NK;
        int row = j >> 7;
        int p2 = (j & 127) * 2;
        const float* base = X + (size_t)row * QKVN + CC + KVW;
        *(__nv_bfloat162*)&Vb[(size_t)row * KVW + p2] =
            __floats2bfloat162_rn(base[p2], base[p2 + 1]);
    }
}

// ------- flash attention: 2 heads/CTA (shared K/V), 64-row Q tiles -------
// grid (TT/64, HH/2, BB), 256 threads. Warps 0-3 -> head 2y, warps 4-7 -> 2y+1.
__global__ __launch_bounds__(256) void attn_mma(const __nv_bfloat16* __restrict__ Qb,
                                                const __nv_bfloat16* __restrict__ Kb,
                                                const __nv_bfloat16* __restrict__ Vb,
                                                __nv_bfloat16* __restrict__ O) {
    int qb = blockIdx.x, hp = blockIdx.y, b = blockIdx.z;
    int tid = threadIdx.x;
    int wid = tid >> 5, lane = tid & 31;
    int hw = wid >> 2;             // head within pair (0/1)
    int wq = wid & 3;              // warp within head-group
    int h = hp * 2 + hw;
    int kvh = (hp * 2) / NREP;     // both heads in pair share kvh

    __shared__ __align__(16) __nv_bfloat16 Qs[2][64 * 72];
    __shared__ __align__(16) __nv_bfloat16 Ks[64 * 72];
    __shared__ __align__(16) __nv_bfloat16 Vs[64 * 72];

    // load both heads' Q tiles (512 uint4 per head, 256 threads)
    for (int i = tid; i < 2 * 64 * 8; i += 256) {
        int hh = i >> 9;               // 0/1
        int j = i & 511;
        int row = j >> 3, g = (j & 7) * 8;
        *(uint4*)&Qs[hh][row * 72 + g] =
            *(const uint4*)&Qb[((size_t)(b * TT + qb * 64 + row)) * CC + (hp * 2 + hh) * DH + g];
    }
    __syncthreads();

    int r16 = lane & 15, kh = lane >> 4;
    int rn = lane & 7, knh = (lane >> 3) & 1;
    uint32_t qf[4][4];
#pragma unroll
    for (int kk = 0; kk < 4; kk++) {
        uint32_t ad = su32(&Qs[hw][(wq * 16 + r16) * 72 + kk * 16 + kh * 8]);
        asm volatile("ldmatrix.sync.aligned.m8n8.x4.shared.b16 {%0,%1,%2,%3}, [%4];"
            : "=r"(qf[kk][0]), "=r"(qf[kk][1]), "=r"(qf[kk][2]), "=r"(qf[kk][3]) : "r"(ad));
    }

    int rr = lane >> 2, cq = (lane & 3) * 2;
    int t0 = qb * 64 + wq * 16 + rr;   // second row = t0+8
    float m0 = -1e30f, m1 = -1e30f, l0 = 0.f, l1 = 0.f;
    float acc[8][4];
#pragma unroll
    for (int dn = 0; dn < 8; dn++)
#pragma unroll
        for (int r = 0; r < 4; r++) acc[dn][r] = 0.f;

    int kstart = qb * 64 - WIN; if (kstart < 0) kstart = 0;
    for (int k0 = kstart; k0 <= qb * 64; k0 += 64) {
        __syncthreads();
        for (int i = tid; i < 64 * 32; i += 256) {
            int row = i >> 5, p2 = (i & 31) * 2;
            size_t kr = ((size_t)(b * TT + k0 + row)) * KVW + kvh * DH;
            *(__nv_bfloat162*)&Ks[row * 72 + p2] = *(const __nv_bfloat162*)&Kb[kr + p2];
            *(__nv_bfloat162*)&Vs[row * 72 + p2] = *(const __nv_bfloat162*)&Vb[kr + p2];
        }
        __syncthreads();

        float s[8][4];
#pragma unroll
        for (int j = 0; j < 8; j++) {
            s[j][0] = s[j][1] = s[j][2] = s[j][3] = 0.f;
#pragma unroll
            for (int kk = 0; kk < 4; kk++) {
                uint32_t bfr[2];
                uint32_t bd = su32(&Ks[(j * 8 + rn) * 72 + kk * 16 + knh * 8]);
                asm volatile("ldmatrix.sync.aligned.m8n8.x2.shared.b16 {%0,%1}, [%2];"
                    : "=r"(bfr[0]), "=r"(bfr[1]) : "r"(bd));
                asm volatile(
                    "mma.sync.aligned.m16n8k16.row.col.f32.bf16.bf16.f32 "
                    "{%0,%1,%2,%3}, {%4,%5,%6,%7}, {%8,%9}, {%0,%1,%2,%3};"
                    : "+f"(s[j][0]), "+f"(s[j][1]), "+f"(s[j][2]), "+f"(s[j][3])
                    : "r"(qf[kk][0]), "r"(qf[kk][1]), "r"(qf[kk][2]), "r"(qf[kk][3]),
                      "r"(bfr[0]), "r"(bfr[1]));
            }
        }
#pragma unroll
        for (int j = 0; j < 8; j++) {
            int kg = k0 + j * 8 + cq;
            if (kg > t0 || kg < t0 - WIN) s[j][0] = -1e30f;
            if (kg + 1 > t0 || kg + 1 < t0 - WIN) s[j][1] = -1e30f;
            if (kg > t0 + 8 || kg < t0 + 8 - WIN) s[j][2] = -1e30f;
            if (kg + 1 > t0 + 8 || kg + 1 < t0 + 8 - WIN) s[j][3] = -1e30f;
        }
        float mx0 = -1e30f, mx1 = -1e30f;
#pragma unroll
        for (int j = 0; j < 8; j++) {
            mx0 = fmaxf(mx0, fmaxf(s[j][0], s[j][1]));
            mx1 = fmaxf(mx1, fmaxf(s[j][2], s[j][3]));
        }
        mx0 = fmaxf(mx0, __shfl_xor_sync(0xffffffffu, mx0, 1));
        mx0 = fmaxf(mx0, __shfl_xor_sync(0xffffffffu, mx0, 2));
        mx1 = fmaxf(mx1, __shfl_xor_sync(0xffffffffu, mx1, 1));
        mx1 = fmaxf(mx1, __shfl_xor_sync(0xffffffffu, mx1, 2));
        float mn0 = fmaxf(m0, mx0), mn1 = fmaxf(m1, mx1);
        float c0 = __expf(m0 - mn0), c1 = __expf(m1 - mn1);
        m0 = mn0; m1 = mn1;
        l0 *= c0; l1 *= c1;
#pragma unroll
        for (int dn = 0; dn < 8; dn++) {
            acc[dn][0] *= c0; acc[dn][1] *= c0;
            acc[dn][2] *= c1; acc[dn][3] *= c1;
        }
#pragma unroll
        for (int j = 0; j < 8; j++) {
            s[j][0] = __expf(s[j][0] - m0); s[j][1] = __expf(s[j][1] - m0);
            s[j][2] = __expf(s[j][2] - m1); s[j][3] = __expf(s[j][3] - m1);
            l0 += s[j][0] + s[j][1];
            l1 += s[j][2] + s[j][3];
        }
        uint32_t pa[4][4];
#pragma unroll
        for (int kk = 0; kk < 4; kk++) {
            int j0 = kk * 2, j1 = kk * 2 + 1;
            pa[kk][0] = packbf(s[j0][0], s[j0][1]);
            pa[kk][1] = packbf(s[j0][2], s[j0][3]);
            pa[kk][2] = packbf(s[j1][0], s[j1][1]);
            pa[kk][3] = packbf(s[j1][2], s[j1][3]);
        }
#pragma unroll
        for (int dn = 0; dn < 8; dn++)
#pragma unroll
            for (int kk = 0; kk < 4; kk++) {
                uint32_t bfr[2];
                uint32_t bd = su32(&Vs[(kk * 16 + knh * 8 + rn) * 72 + dn * 8]);
                asm volatile("ldmatrix.sync.aligned.m8n8.x2.trans.shared.b16 {%0,%1}, [%2];"
                    : "=r"(bfr[0]), "=r"(bfr[1]) : "r"(bd));
                asm volatile(
                    "mma.sync.aligned.m16n8k16.row.col.f32.bf16.bf16.f32 "
                    "{%0,%1,%2,%3}, {%4,%5,%6,%7}, {%8,%9}, {%0,%1,%2,%3};"
                    : "+f"(acc[dn][0]), "+f"(acc[dn][1]), "+f"(acc[dn][2]), "+f"(acc[dn][3])
                    : "r"(pa[kk][0]), "r"(pa[kk][1]), "r"(pa[kk][2]), "r"(pa[kk][3]),
                      "r"(bfr[0]), "r"(bfr[1]));
            }
    }
    l0 += __shfl_xor_sync(0xffffffffu, l0, 1);
    l0 += __shfl_xor_sync(0xffffffffu, l0, 2);
    l1 += __shfl_xor_sync(0xffffffffu, l1, 1);
    l1 += __shfl_xor_sync(0xffffffffu, l1, 2);
    float i0 = 1.f / l0, i1 = 1.f / l1;
    __nv_bfloat16* o0 = O + ((size_t)(b * TT + t0)) * CC + h * DH;
    __nv_bfloat16* o1 = o0 + (size_t)8 * CC;
#pragma unroll
    for (int dn = 0; dn < 8; dn++) {
        *(__nv_bfloat162*)&o0[dn * 8 + cq] =
            __floats2bfloat162_rn(acc[dn][0] * i0, acc[dn][1] * i0);
        *(__nv_bfloat162*)&o1[dn * 8 + cq] =
            __floats2bfloat162_rn(acc[dn][2] * i1, acc[dn][3] * i1);
    }
}

// ---------------- router ----------------
__global__ void route_kernel(const float* __restrict__ xf,
                             const float* __restrict__ gw) {
    int warp = threadIdx.x >> 5, lane = threadIdx.x & 31;
    int tok = blockIdx.x * 4 + warp;
    if (tok >= NTOK) return;
    const float* xr = xf + (size_t)tok * CC;
    float part[EE];
#pragma unroll
    for (int e = 0; e < EE; e++) part[e] = 0.f;
    for (int d = lane; d < CC; d += 32) {
        float xv = xr[d];
#pragma unroll
        for (int e = 0; e < EE; e++) part[e] += xv * gw[d * EE + e];
    }
#pragma unroll
    for (int e = 0; e < EE; e++)
#pragma unroll
        for (int o = 16; o > 0; o >>= 1)
            part[e] += __shfl_xor_sync(0xffffffffu, part[e], o);
    if (lane == 0) {
        float v0 = -1e30f; int i0 = 0;
#pragma unroll
        for (int e = 0; e < EE; e++) if (part[e] > v0) { v0 = part[e]; i0 = e; }
        float v1 = -1e30f; int i1 = 0;
#pragma unroll
        for (int e = 0; e < EE; e++)
            if (e != i0 && part[e] > v1) { v1 = part[e]; i1 = e; }
        float ex = expf(v1 - v0);
        float w0 = 1.f / (1.f + ex);
        float w1 = ex / (1.f + ex);
        g_sel[tok * 2] = i0; g_sel[tok * 2 + 1] = i1;
        g_selw[tok * 2] = w0; g_selw[tok * 2 + 1] = w1;
        float mx = v0, sum = 0.f, pe[EE];
#pragma unroll
        for (int e = 0; e < EE; e++) { pe[e] = expf(part[e] - mx); sum += pe[e]; }
#pragma unroll
        for (int e = 0; e < EE; e++) g_probs[tok * EE + e] = pe[e] / sum;
        float lse = mx + logf(sum);
        g_lse2[tok] = lse * lse;
    }
}

// ---------------- aux loss ----------------
__global__ void aux_kernel() {
    __shared__ float red[256];
    int tid = threadIdx.x;
    float loadv[EE];
#pragma unroll
    for (int e = 0; e < EE; e++) loadv[e] = 0.f;
    for (int n = tid; n < NTOK; n += 256) {
#pragma unroll
        for (int e = 0; e < EE; e++) loadv[e] += g_probs[n * EE + e];
    }
    float loads[EE];
    for (int e = 0; e < EE; e++) {
        red[tid] = loadv[e]; __syncthreads();
        for (int o = 128; o > 0; o >>= 1) {
            if (tid < o) red[tid] += red[tid + o];
            __syncthreads();
        }
        loads[e] = red[0]; __syncthreads();
    }
    float zp = 0.f;
    for (int n = tid; n < NTOK; n += 256) zp += g_lse2[n];
    red[tid] = zp; __syncthreads();
    for (int o = 128; o > 0; o >>= 1) {
        if (tid < o) red[tid] += red[tid + o];
        __syncthreads();
    }
    if (tid == 0) {
        float tot = 0.f;
        for (int e = 0; e < EE; e++) tot += loads[e];
        float lb = 0.f;
        for (int e = 0; e < EE; e++) { float f = loads[e] / tot; lb += f * f; }
        lb *= (float)EE;
        float z = red[0] / (float)NTOK;
        g_aux = 0.01f * lb + 0.001f * z;
    }
}

__global__ void zero_cnt_kernel() { if (threadIdx.x < EE) g_cnt[threadIdx.x] = 0; }

__global__ void count_kernel() {
    int i = blockIdx.x * blockDim.x + threadIdx.x;
    if (i >= NTOK) return;
#pragma unroll
    for (int kk = 0; kk < TOPK; kk++)
        atomicAdd(&g_cnt[g_sel[i * 2 + kk]], 1);
}

__global__ void offsets_kernel() {
    if (threadIdx.x == 0) {
        int acc = 0;
        for (int e = 0; e < EE; e++) {
            g_off[e] = acc;
            acc += (g_cnt[e] + BM - 1) & ~(BM - 1);
            g_cnt2[e] = 0;
        }
        g_off[EE] = acc;
    }
}

__global__ void assign_kernel() {
    int i = blockIdx.x * blockDim.x + threadIdx.x;
    if (i >= NTOK) return;
#pragma unroll
    for (int kk = 0; kk < TOPK; kk++) {
        int e = g_sel[i * 2 + kk];
        int pos = atomicAdd(&g_cnt2[e], 1);
        int row = g_off[e] + pos;
        g_idx[row] = i;
        g_tokrow[i * 2 + kk] = row;
    }
}

__global__ void gather_all_kernel(__nv_bfloat16* __restrict__ dst,
                                  const __nv_bfloat16* __restrict__ src) {
    int b = blockIdx.x;
    if (b >= g_off[EE]) return;
    int e = 0;
    while (g_off[e + 1] <= b) e++;
    if (b - g_off[e] >= g_cnt[e]) return;
    int t = g_idx[b];
    uint4* d4 = (uint4*)(dst + (size_t)b * CC);
    const uint4* s4 = (const uint4*)(src + (size_t)t * CC);
    int i = threadIdx.x;
    if (i < CC * 2 / 16) d4[i] = s4[i];
}

// final: out = h + a_moe * (shared + w0*eo[r0] + w1*eo[r1]); writes aux too
__global__ void final_kernel(const float* __restrict__ h, const float* __restrict__ moe,
                             const float* __restrict__ eo,
                             const float* __restrict__ alpha, float* __restrict__ out,
                             int writeAux) {
    int t = blockIdx.x;
    if (writeAux && t == 0 && threadIdx.x == 0) out[OUT_MAIN] = g_aux;
    float w0 = g_selw[t * 2], w1 = g_selw[t * 2 + 1];
    int r0 = g_tokrow[t * 2], r1 = g_tokrow[t * 2 + 1];
    float a = *alpha;
    const float* hr = h + (size_t)t * CC;
    const float* mr = moe + (size_t)t * CC;
    const float* e0 = eo + (size_t)r0 * CC;
    const float* e1 = eo + (size_t)r1 * CC;
    float* orow = out + (size_t)t * CC;
    for (int i = threadIdx.x; i < CC; i += blockDim.x)
        orow[i] = hr[i] + a * (mr[i] + w0 * e0[i] + w1 * e1[i]);
}

// ---------------- launch ----------------
extern "C" void kernel_launch(void* const* d_in, const int* in_sizes, int n_in,
                              void* d_out, int out_size) {
    const float* x      = (const float*)d_in[0];
    const float* ln1    = (const float*)d_in[1];
    const float* ln2    = (const float*)d_in[2];
    const float* wq     = (const float*)d_in[3];
    const float* wk     = (const float*)d_in[4];
    const float* wv     = (const float*)d_in[5];
    const float* wo     = (const float*)d_in[6];
    const float* sw1    = (const float*)d_in[7];
    const float* sw2    = (const float*)d_in[8];
    const float* sw3    = (const float*)d_in[9];
    const float* ew1    = (const float*)d_in[10];
    const float* ew2    = (const float*)d_in[11];
    const float* ew3    = (const float*)d_in[12];
    const float* gatew  = (const float*)d_in[13];
    const float* a_attn = (const float*)d_in[14];
    const float* a_moe  = (const float*)d_in[15];
    float* out = (float*)d_out;

    void* p;
    float *qkv, *h, *xf, *moe, *eo;
    __nv_bfloat16 *xnb, *qb, *aob, *xfb, *xgb, *g1b, *kb, *vb;
    __nv_bfloat16 *wqkvt, *wot, *sw12t, *sw3t, *ew12t, *ew3t;
    cudaGetSymbolAddress(&p, g_qkv);  qkv  = (float*)p;
    cudaGetSymbolAddress(&p, g_h);    h    = (float*)p;
    cudaGetSymbolAddress(&p, g_xf);   xf   = (float*)p;
    cudaGetSymbolAddress(&p, g_moe);  moe  = (float*)p;
    cudaGetSymbolAddress(&p, g_eo);   eo   = (float*)p;
    cudaGetSymbolAddress(&p, g_xnb);  xnb  = (__nv_bfloat16*)p;
    cudaGetSymbolAddress(&p, g_qb);   qb   = (__nv_bfloat16*)p;
    cudaGetSymbolAddress(&p, g_aob);  aob  = (__nv_bfloat16*)p;
    cudaGetSymbolAddress(&p, g_xfb);  xfb  = (__nv_bfloat16*)p;
    cudaGetSymbolAddress(&p, g_xgb);  xgb  = (__nv_bfloat16*)p;
    cudaGetSymbolAddress(&p, g_g1b);  g1b  = (__nv_bfloat16*)p;
    cudaGetSymbolAddress(&p, g_kb);   kb   = (__nv_bfloat16*)p;
    cudaGetSymbolAddress(&p, g_vb);   vb   = (__nv_bfloat16*)p;
    cudaGetSymbolAddress(&p, g_wqkvt); wqkvt = (__nv_bfloat16*)p;
    cudaGetSymbolAddress(&p, g_wot);   wot   = (__nv_bfloat16*)p;
    cudaGetSymbolAddress(&p, g_sw12t); sw12t = (__nv_bfloat16*)p;
    cudaGetSymbolAddress(&p, g_sw3t);  sw3t  = (__nv_bfloat16*)p;
    cudaGetSymbolAddress(&p, g_ew12t); ew12t = (__nv_bfloat16*)p;
    cudaGetSymbolAddress(&p, g_ew3t);  ew3t  = (__nv_bfloat16*)p;

    static bool s_init = false;
    static cudaStream_t s2 = 0;
    static cudaEvent_t evA = 0, evB = 0, evC = 0, evD = 0, evE = 0;
    if (!s_init) {
        if (cudaStreamCreateWithFlags(&s2, cudaStreamNonBlocking) != cudaSuccess) s2 = 0;
        if (s2) {
            bool ok = true;
            ok &= (cudaEventCreateWithFlags(&evA, cudaEventDisableTiming) == cudaSuccess);
            ok &= (cudaEventCreateWithFlags(&evB, cudaEventDisableTiming) == cudaSuccess);
            ok &= (cudaEventCreateWithFlags(&evC, cudaEventDisableTiming) == cudaSuccess);
            ok &= (cudaEventCreateWithFlags(&evD, cudaEventDisableTiming) == cudaSuccess);
            ok &= (cudaEventCreateWithFlags(&evE, cudaEventDisableTiming) == cudaSuccess);
            if (!ok) s2 = 0;
        }
        s_init = true;
    }
    bool forked = (s2 != 0);

    // critical-path conversions (attention weights only)
    wcvt<<<512, 256>>>(wq, wqkvt, CC, QKVN, 0, 0, 0, (long)CC*CC/8);
    wcvt<<<128, 256>>>(wk, wqkvt, KVW, QKVN, CC, 0, 0, (long)CC*KVW/8);
    wcvt<<<128, 256>>>(wv, wqkvt, KVW, QKVN, CC+KVW, 0, 0, (long)CC*KVW/8);
    wcvt<<<512, 256>>>(wo, wot, CC, CC, 0, 0, 0, (long)CC*CC/8);

    // FFN weight conversions forked onto s2 (shared first, then experts)
    if (forked) {
        cudaEventRecord(evA, 0);
        cudaStreamWaitEvent(s2, evA, 0);
        wcvt_pair<<<4096, 256, 0, s2>>>(sw1, sw2, sw12t, FF, 0, 0, (long)CC*FF/4);
        wcvt<<<2048, 256, 0, s2>>>(sw3, sw3t, CC, CC, 0, 0, 0, (long)FF*CC/8);
        cudaEventRecord(evE, s2);
        wcvt_pair<<<dim3(4096,1,EE), 256, 0, s2>>>(ew1, ew2, ew12t, FF,
            (long)CC*FF, (long)CC*2*FF, (long)CC*FF/4);
        wcvt<<<dim3(2048,1,EE), 256, 0, s2>>>(ew3, ew3t, CC, CC, 0,
            (long)FF*CC, (long)FF*CC, (long)FF*CC/8);
        cudaEventRecord(evB, s2);
    } else {
        wcvt_pair<<<4096, 256>>>(sw1, sw2, sw12t, FF, 0, 0, (long)CC*FF/4);
        wcvt<<<2048, 256>>>(sw3, sw3t, CC, CC, 0, 0, 0, (long)FF*CC/8);
        wcvt_pair<<<dim3(4096,1,EE), 256>>>(ew1, ew2, ew12t, FF,
            (long)CC*FF, (long)CC*2*FF, (long)CC*FF/4);
        wcvt<<<dim3(2048,1,EE), 256>>>(ew3, ew3t, CC, CC, 0,
            (long)FF*CC, (long)FF*CC, (long)FF*CC/8);
    }

    // 1) pre-attn norm
    rmsnorm_kernel<<<NTOK, 256>>>(x, ln1, nullptr, xnb);
    // 2) fused QKV projection
    gemm_mma<<<dim3(QKVN/128, NTOK/128), 256>>>(xnb, wqkvt, qkv, QKVN, CC);
    // 3) fused RoPE(q,k) + Q/K/V bf16 compaction
    {
        int total = NTOK*HH*32 + NTOK*KVH*32 + NTOK*(KVW/2);
        rope_all_kernel<<<(total + 255) / 256, 256>>>(qkv, qb, kb, vb);
    }
    // 4) attention (tensor core, 2 heads/CTA with shared K/V)
    attn_mma<<<dim3(TT/64, HH/2, BB), 256>>>(qb, kb, vb, aob);
    // 5) output projection with fused ReZero residual
    gemm_mma_add<<<dim3(CC/128, NTOK/128), 256>>>(aob, wot, x, a_attn, h, CC, CC);
    // 6) post-attn norm
    rmsnorm_kernel<<<NTOK, 256>>>(h, ln2, xf, xfb);
    // 7) routing + aux + compaction — forked onto s2, overlapped with shared GEMMs
    if (forked) {
        cudaEventRecord(evC, 0);
        cudaStreamWaitEvent(s2, evC, 0);
        route_kernel<<<NTOK / 4, 128, 0, s2>>>(xf, gatew);
        aux_kernel<<<1, 256, 0, s2>>>();
        zero_cnt_kernel<<<1, 32, 0, s2>>>();
        count_kernel<<<(NTOK + 255) / 256, 256, 0, s2>>>();
        offsets_kernel<<<1, 32, 0, s2>>>();
        assign_kernel<<<(NTOK + 255) / 256, 256, 0, s2>>>();
        cudaEventRecord(evD, s2);
    } else {
        route_kernel<<<NTOK / 4, 128>>>(xf, gatew);
        aux_kernel<<<1, 256>>>();
        zero_cnt_kernel<<<1, 32>>>();
        count_kernel<<<(NTOK + 255) / 256, 256>>>();
        offsets_kernel<<<1, 32>>>();
        assign_kernel<<<(NTOK + 255) / 256, 256>>>();
    }
    // 8) shared expert: fused w12+SwiGLU, then w3 (join shared-weight conversion)
    if (forked) cudaStreamWaitEvent(0, evE, 0);
    gemm_swiglu<<<dim3(2*FF/128, NTOK/128), 256>>>(xfb, sw12t, g1b, 2*FF, CC);
    gemm_mma<<<dim3(CC/128, NTOK/128), 256>>>(g1b, sw3t, moe, CC, FF);
    // 9) routed experts, batched (join routing + expert weights first)
    if (forked) cudaStreamWaitEvent(0, evD, 0);
    gather_all_kernel<<<ECAP, 128>>>(xgb, xfb);
    if (forked) cudaStreamWaitEvent(0, evB, 0);
    gemm_moe_swiglu<<<dim3(2*FF/128, ECAP/128), 256>>>(xgb, ew12t, g1b, 2*FF, CC, (long)CC*2*FF);
    gemm_moe<<<dim3(CC/128, ECAP/128), 256>>>(g1b, ew3t, eo, CC, FF, (long)FF*CC);
    // 10) final combine + aux scalar (fused)
    final_kernel<<<NTOK, 256>>>(h, moe, eo, a_moe, out, out_size > OUT_MAIN ? 1 : 0);
}

// round 15
// speedup vs baseline: 1.2792x; 1.0230x over previous
#include <cuda_runtime.h>
#include <cuda_bf16.h>
#include <math.h>
#include <stdint.h>

// Problem constants
#define BB   2
#define TT   2048
#define CC   1024
#define HH   16
#define KVH  4
#define DH   64
#define NREP 4
#define FF   4096
#define EE   8
#define TOPK 2
#define WIN  1024
#define NTOK (BB*TT)            // 4096
#define OUT_MAIN (NTOK*CC)      // 4194304
#define QKVN (CC + 2*KVH*DH)    // 1536
#define KVW  (KVH*DH)           // 256
#define ECAP 9216               // 8192 real rows + padding, 128-aligned

// ---------------- scratch (device globals; no allocation) ----------------
__device__ float g_qkv [NTOK*QKVN];
__device__ float g_h   [NTOK*CC];
__device__ float g_xf  [NTOK*CC];
__device__ float g_moe [NTOK*CC];
__device__ float g_eo  [(size_t)ECAP*CC];
__device__ float g_probs[NTOK*EE];
__device__ float g_lse2[NTOK];
__device__ int   g_sel [NTOK*2];
__device__ float g_selw[NTOK*2];
__device__ int   g_cnt [EE];
__device__ int   g_cnt2[EE];
__device__ int   g_off [EE+1];
__device__ int   g_idx [ECAP];
__device__ int   g_tokrow[NTOK*2];
__device__ float g_aux;

// bf16 activations
__device__ __nv_bfloat16 g_xnb [NTOK*CC];
__device__ __nv_bfloat16 g_qb  [NTOK*CC];
__device__ __nv_bfloat16 g_aob [NTOK*CC];
__device__ __nv_bfloat16 g_xfb [NTOK*CC];
__device__ __nv_bfloat16 g_xgb [(size_t)ECAP*CC];
__device__ __nv_bfloat16 g_g1b [(size_t)NTOK*FF];   // shared-expert intermediate
__device__ __nv_bfloat16 g_g1e [(size_t)ECAP*FF];   // routed-expert intermediate
__device__ __nv_bfloat16 g_kb  [NTOK*KVW];
__device__ __nv_bfloat16 g_vb  [NTOK*KVW];

// bf16 weights, K-major [K,N] (w12 column-interleaved: w1->2f, w2->2f+1)
__device__ __nv_bfloat16 g_wqkvt[CC*QKVN];
__device__ __nv_bfloat16 g_wot  [CC*CC];
__device__ __nv_bfloat16 g_sw12t[CC*2*FF];
__device__ __nv_bfloat16 g_sw3t [FF*CC];
__device__ __nv_bfloat16 g_ew12t[(size_t)EE*CC*2*FF];
__device__ __nv_bfloat16 g_ew3t [(size_t)EE*FF*CC];

__device__ __forceinline__ uint32_t su32(const void* p) {
    uint32_t a;
    asm("{ .reg .u64 t; cvta.to.shared.u64 t, %1; cvt.u32.u64 %0, t; }" : "=r"(a) : "l"(p));
    return a;
}
__device__ __forceinline__ uint32_t packbf(float a, float b) {
    __nv_bfloat162 t = __floats2bfloat162_rn(a, b);
    return *(uint32_t*)&t;
}

#define CP_ASYNC16(d, s) asm volatile("cp.async.cg.shared.global [%0], [%1], 16;" :: "r"(d), "l"(s))
#define CP_COMMIT()      asm volatile("cp.async.commit_group;" ::: "memory")
#define CP_WAIT(n)       asm volatile("cp.async.wait_group %0;" :: "n"(n) : "memory")

#define BM 128
#define BN 128
#define BK 32
#define ASTR 40    // A smem row stride (bf16 elems)
#define BSTR 136   // B smem row stride (bf16 elems)

// ================= 2-stage GEMM mainloop; B is [K,N] via ldmatrix.x4.trans
#define GEMM_MAIN(A_, Bt_, N_, K_)                                             \
    __shared__ __align__(16) __nv_bfloat16 sA[2][BM * ASTR];                   \
    __shared__ __align__(16) __nv_bfloat16 sB[2][BK * BSTR];                   \
    int tid = threadIdx.x;                                                     \
    int wid = tid >> 5, lane = tid & 31;                                       \
    int wm = wid >> 2, wn = wid & 3;                                           \
    float cr[4][4][4];                                                         \
    _Pragma("unroll") for (int i = 0; i < 4; i++)                              \
    _Pragma("unroll") for (int j = 0; j < 4; j++)                              \
    _Pragma("unroll") for (int r = 0; r < 4; r++) cr[i][j][r] = 0.f;           \
    int lrow = tid >> 1;                                                       \
    int lc16 = (tid & 1) * 16;                                                 \
    int nCh = (K_) / BK;                                                       \
    {                                                                          \
        const __nv_bfloat16* srcA0 = (A_) + (size_t)(rowBase + lrow) * (K_) + lc16; \
        uint32_t dA0 = su32(&sA[0][lrow * ASTR + lc16]);                       \
        CP_ASYNC16(dA0, srcA0); CP_ASYNC16(dA0 + 16, srcA0 + 8);               \
        _Pragma("unroll") for (int bi = 0; bi < 2; bi++) {                     \
            int seg = tid + bi * 256;                                          \
            int brow = seg >> 4, bcol = (seg & 15) * 8;                        \
            const __nv_bfloat16* srcB = (Bt_) + (size_t)brow * (N_) + colBase + bcol; \
            CP_ASYNC16(su32(&sB[0][brow * BSTR + bcol]), srcB);                \
        }                                                                      \
        CP_COMMIT();                                                           \
    }                                                                          \
    for (int ch = 0; ch < nCh; ch++) {                                         \
        int st = ch & 1;                                                       \
        if (ch + 1 < nCh) {                                                    \
            int k0 = (ch + 1) * BK;                                            \
            const __nv_bfloat16* srcA = (A_) + (size_t)(rowBase + lrow) * (K_) + k0 + lc16; \
            uint32_t dA = su32(&sA[st ^ 1][lrow * ASTR + lc16]);               \
            CP_ASYNC16(dA, srcA); CP_ASYNC16(dA + 16, srcA + 8);               \
            _Pragma("unroll") for (int bi = 0; bi < 2; bi++) {                 \
                int seg = tid + bi * 256;                                      \
                int brow = seg >> 4, bcol = (seg & 15) * 8;                    \
                const __nv_bfloat16* srcB = (Bt_) + (size_t)(k0 + brow) * (N_) + colBase + bcol; \
                CP_ASYNC16(su32(&sB[st ^ 1][brow * BSTR + bcol]), srcB);       \
            }                                                                  \
            CP_COMMIT(); CP_WAIT(1);                                           \
        } else { CP_WAIT(0); }                                                 \
        __syncthreads();                                                       \
        int r16 = lane & 15, kh = lane >> 4;                                   \
        int brl = (lane & 7) + ((lane >> 3) & 1) * 8;   /* row within 16 */    \
        int bcl = ((lane >> 4) & 1) * 8;                /* col half */         \
        _Pragma("unroll") for (int kk = 0; kk < 2; kk++) {                     \
            uint32_t af[4][4];                                                 \
            _Pragma("unroll") for (int mf = 0; mf < 4; mf++) {                 \
                uint32_t ad = su32(&sA[st][(wm * 64 + mf * 16 + r16) * ASTR + kk * 16 + kh * 8]); \
                asm volatile("ldmatrix.sync.aligned.m8n8.x4.shared.b16 {%0,%1,%2,%3}, [%4];" \
                    : "=r"(af[mf][0]), "=r"(af[mf][1]), "=r"(af[mf][2]), "=r"(af[mf][3]) : "r"(ad)); \
            }                                                                  \
            uint32_t bfr[4][2];                                                \
            _Pragma("unroll") for (int nfp = 0; nfp < 2; nfp++) {              \
                uint32_t bd = su32(&sB[st][(kk * 16 + brl) * BSTR + wn * 32 + nfp * 16 + bcl]); \
                asm volatile("ldmatrix.sync.aligned.m8n8.x4.trans.shared.b16 {%0,%1,%2,%3}, [%4];" \
                    : "=r"(bfr[2*nfp][0]), "=r"(bfr[2*nfp][1]),                \
                      "=r"(bfr[2*nfp+1][0]), "=r"(bfr[2*nfp+1][1]) : "r"(bd)); \
            }                                                                  \
            _Pragma("unroll") for (int mf = 0; mf < 4; mf++)                   \
            _Pragma("unroll") for (int nf = 0; nf < 4; nf++) {                 \
                asm volatile(                                                  \
                    "mma.sync.aligned.m16n8k16.row.col.f32.bf16.bf16.f32 "     \
                    "{%0,%1,%2,%3}, {%4,%5,%6,%7}, {%8,%9}, {%0,%1,%2,%3};"    \
                    : "+f"(cr[mf][nf][0]), "+f"(cr[mf][nf][1]),                \
                      "+f"(cr[mf][nf][2]), "+f"(cr[mf][nf][3])                 \
                    : "r"(af[mf][0]), "r"(af[mf][1]), "r"(af[mf][2]), "r"(af[mf][3]), \
                      "r"(bfr[nf][0]), "r"(bfr[nf][1]));                       \
            }                                                                  \
        }                                                                      \
        __syncthreads();                                                       \
    }                                                                          \
    int rr = lane >> 2, cq = (lane & 3) * 2;

// ================= dense GEMM, fp32 out =================
__global__ __launch_bounds__(256) void gemm_mma(
    const __nv_bfloat16* __restrict__ A, const __nv_bfloat16* __restrict__ Bt,
    float* __restrict__ C, int N, int K)
{
    int rowBase = blockIdx.y * BM, colBase = blockIdx.x * BN;
    GEMM_MAIN(A, Bt, N, K)
#pragma unroll
    for (int mf = 0; mf < 4; mf++)
#pragma unroll
        for (int nf = 0; nf < 4; nf++) {
            int row0 = rowBase + wm * 64 + mf * 16 + rr;
            int col = colBase + wn * 32 + nf * 8 + cq;
            *(float2*)&C[(size_t)row0 * N + col] = make_float2(cr[mf][nf][0], cr[mf][nf][1]);
            *(float2*)&C[(size_t)(row0 + 8) * N + col] = make_float2(cr[mf][nf][2], cr[mf][nf][3]);
        }
}

// ===== dense GEMM with fused ReZero residual: C = X + (*alpha)*(A@Bt) ====
__global__ __launch_bounds__(256) void gemm_mma_add(
    const __nv_bfloat16* __restrict__ A, const __nv_bfloat16* __restrict__ Bt,
    const float* __restrict__ X, const float* __restrict__ alpha,
    float* __restrict__ C, int N, int K)
{
    int rowBase = blockIdx.y * BM, colBase = blockIdx.x * BN;
    GEMM_MAIN(A, Bt, N, K)
    float a = *alpha;
#pragma unroll
    for (int mf = 0; mf < 4; mf++)
#pragma unroll
        for (int nf = 0; nf < 4; nf++) {
            int row0 = rowBase + wm * 64 + mf * 16 + rr;
            int col = colBase + wn * 32 + nf * 8 + cq;
            float2 x0 = *(const float2*)&X[(size_t)row0 * N + col];
            float2 x1 = *(const float2*)&X[(size_t)(row0 + 8) * N + col];
            *(float2*)&C[(size_t)row0 * N + col] =
                make_float2(x0.x + a * cr[mf][nf][0], x0.y + a * cr[mf][nf][1]);
            *(float2*)&C[(size_t)(row0 + 8) * N + col] =
                make_float2(x1.x + a * cr[mf][nf][2], x1.y + a * cr[mf][nf][3]);
        }
}

// ================= dense GEMM, fused SwiGLU bf16 out (interleaved w12) ===
__global__ __launch_bounds__(256) void gemm_swiglu(
    const __nv_bfloat16* __restrict__ A, const __nv_bfloat16* __restrict__ Bt,
    __nv_bfloat16* __restrict__ Obf, int N2, int K)
{
    int rowBase = blockIdx.y * BM, colBase = blockIdx.x * BN;
    GEMM_MAIN(A, Bt, N2, K)
    int FFo = N2 >> 1;
#pragma unroll
    for (int mf = 0; mf < 4; mf++)
#pragma unroll
        for (int nf = 0; nf < 4; nf++) {
            int row0 = rowBase + wm * 64 + mf * 16 + rr;
            int f = (colBase + wn * 32 + nf * 8 + cq) >> 1;
            float a0 = cr[mf][nf][0], b0 = cr[mf][nf][1];
            Obf[(size_t)row0 * FFo + f] = __float2bfloat16(a0 / (1.f + __expf(-a0)) * b0);
            float a1 = cr[mf][nf][2], b1 = cr[mf][nf][3];
            Obf[(size_t)(row0 + 8) * FFo + f] = __float2bfloat16(a1 / (1.f + __expf(-a1)) * b1);
        }
}

// ================= MoE GEMM, fp32 out =================
__global__ __launch_bounds__(256) void gemm_moe(
    const __nv_bfloat16* __restrict__ A, const __nv_bfloat16* __restrict__ Wb,
    float* __restrict__ C, int N, int K, long wstride)
{
    int rowBase = blockIdx.y * BM;
    if (rowBase >= g_off[EE]) return;
    int colBase = blockIdx.x * BN;
    int e = 0;
    while (g_off[e + 1] <= rowBase) e++;
    const __nv_bfloat16* Bt = Wb + (size_t)e * wstride;
    GEMM_MAIN(A, Bt, N, K)
#pragma unroll
    for (int mf = 0; mf < 4; mf++)
#pragma unroll
        for (int nf = 0; nf < 4; nf++) {
            int row0 = rowBase + wm * 64 + mf * 16 + rr;
            int col = colBase + wn * 32 + nf * 8 + cq;
            *(float2*)&C[(size_t)row0 * N + col] = make_float2(cr[mf][nf][0], cr[mf][nf][1]);
            *(float2*)&C[(size_t)(row0 + 8) * N + col] = make_float2(cr[mf][nf][2], cr[mf][nf][3]);
        }
}

// ================= MoE GEMM, fused SwiGLU bf16 out =================
__global__ __launch_bounds__(256) void gemm_moe_swiglu(
    const __nv_bfloat16* __restrict__ A, const __nv_bfloat16* __restrict__ Wb,
    __nv_bfloat16* __restrict__ Obf, int N2, int K, long wstride)
{
    int rowBase = blockIdx.y * BM;
    if (rowBase >= g_off[EE]) return;
    int colBase = blockIdx.x * BN;
    int e = 0;
    while (g_off[e + 1] <= rowBase) e++;
    const __nv_bfloat16* Bt = Wb + (size_t)e * wstride;
    GEMM_MAIN(A, Bt, N2, K)
    int FFo = N2 >> 1;
#pragma unroll
    for (int mf = 0; mf < 4; mf++)
#pragma unroll
        for (int nf = 0; nf < 4; nf++) {
            int row0 = rowBase + wm * 64 + mf * 16 + rr;
            int f = (colBase + wn * 32 + nf * 8 + cq) >> 1;
            float a0 = cr[mf][nf][0], b0 = cr[mf][nf][1];
            Obf[(size_t)row0 * FFo + f] = __float2bfloat16(a0 / (1.f + __expf(-a0)) * b0);
            float a1 = cr[mf][nf][2], b1 = cr[mf][nf][3];
            Obf[(size_t)(row0 + 8) * FFo + f] = __float2bfloat16(a1 / (1.f + __expf(-a1)) * b1);
        }
}

// ---------------- streaming weight convert: [K,NWs] f32 -> [K,NWd] bf16 --
__global__ void wcvt(const float* __restrict__ src, __nv_bfloat16* __restrict__ dst,
                     int NWs, int NWd, int coff, long sstride, long dstride, long total8) {
    long i = (long)blockIdx.x * blockDim.x + threadIdx.x;
    if (i >= total8) return;
    long e = i * 8;
    int k = (int)(e / NWs);
    int n = (int)(e - (long)k * NWs);
    const float* s = src + (size_t)blockIdx.z * sstride + (size_t)k * NWs + n;
    float4 v0 = *(const float4*)s;
    float4 v1 = *(const float4*)(s + 4);
    __nv_bfloat16 o[8];
    o[0] = __float2bfloat16(v0.x); o[1] = __float2bfloat16(v0.y);
    o[2] = __float2bfloat16(v0.z); o[3] = __float2bfloat16(v0.w);
    o[4] = __float2bfloat16(v1.x); o[5] = __float2bfloat16(v1.y);
    o[6] = __float2bfloat16(v1.z); o[7] = __float2bfloat16(v1.w);
    *(uint4*)&dst[(size_t)blockIdx.z * dstride + (size_t)k * NWd + coff + n] = *(uint4*)o;
}

// ---------------- streaming pair convert: w1,w2 [K,NW] -> [K,2NW] interleaved
__global__ void wcvt_pair(const float* __restrict__ s1, const float* __restrict__ s2,
                          __nv_bfloat16* __restrict__ dst,
                          int NW, long sstride, long dstride, long total4) {
    long i = (long)blockIdx.x * blockDim.x + threadIdx.x;
    if (i >= total4) return;
    long e = i * 4;
    int k = (int)(e / NW);
    int f = (int)(e - (long)k * NW);
    size_t so = (size_t)blockIdx.z * sstride + (size_t)k * NW + f;
    float4 va = *(const float4*)(s1 + so);
    float4 vb = *(const float4*)(s2 + so);
    __nv_bfloat16 o[8];
    o[0] = __float2bfloat16(va.x); o[1] = __float2bfloat16(vb.x);
    o[2] = __float2bfloat16(va.y); o[3] = __float2bfloat16(vb.y);
    o[4] = __float2bfloat16(va.z); o[5] = __float2bfloat16(vb.z);
    o[6] = __float2bfloat16(va.w); o[7] = __float2bfloat16(vb.w);
    *(uint4*)&dst[(size_t)blockIdx.z * dstride + (size_t)k * (2 * NW) + 2 * f] = *(uint4*)o;
}

// ---------------- RMSNorm (dual output) ----------------
__global__ void rmsnorm_kernel(const float* __restrict__ x,
                               const float* __restrict__ w,
                               float* __restrict__ of,
                               __nv_bfloat16* __restrict__ ob) {
    int row = blockIdx.x;
    int tid = threadIdx.x;
    const float* xr = x + (size_t)row * CC;
    float s = 0.f;
    for (int i = tid; i < CC; i += 256) { float v = xr[i]; s += v * v; }
    __shared__ float red[256];
    red[tid] = s; __syncthreads();
    for (int o2 = 128; o2 > 0; o2 >>= 1) {
        if (tid < o2) red[tid] += red[tid + o2];
        __syncthreads();
    }
    float scale = rsqrtf(red[0] / (float)CC + 1e-6f);
    for (int i = tid; i < CC; i += 256) {
        float v = xr[i] * scale * w[i];
        if (of) of[(size_t)row * CC + i] = v;
        ob[(size_t)row * CC + i] = __float2bfloat16(v);
    }
}

// ------- fused RoPE(q,k) + Q bf16 (pre-scaled) + K/V bf16 compaction -----
__global__ void rope_all_kernel(const float* __restrict__ X,
                                __nv_bfloat16* __restrict__ Qb,
                                __nv_bfloat16* __restrict__ Kb,
                                __nv_bfloat16* __restrict__ Vb) {
    int i = blockIdx.x * blockDim.x + threadIdx.x;
    const int NQ = NTOK * HH * 32;
    const int NK = NTOK * KVH * 32;
    const int NV = NTOK * (KVW / 2);
    if (i < NQ) {
        int p = i & 31;
        int tmp = i >> 5;
        int hh = tmp % HH;
        int row = tmp / HH;
        int t = row % TT;
        float invf = expf(-(float)p * (logf(10000.f) / 32.f));
        float ang = (float)t * invf;
        float cs = cosf(ang), sn = sinf(ang);
        size_t base = (size_t)row * QKVN + hh * 64;
        float a = X[base + p];
        float b = X[base + p + 32];
        size_t qo = (size_t)row * CC + hh * 64;
        Qb[qo + p]      = __float2bfloat16(0.125f * (a * cs - b * sn));
        Qb[qo + p + 32] = __float2bfloat16(0.125f * (b * cs + a * sn));
    } else if (i < NQ + NK) {
        int j = i - NQ;
        int p = j & 31;
        int tmp = j >> 5;
        int hh = tmp % KVH;
        int row = tmp / KVH;
        int t = row % TT;
        float invf = expf(-(float)p * (logf(10000.f) / 32.f));
        float ang = (float)t * invf;
        float cs = cosf(ang), sn = sinf(ang);
        size_t base = (size_t)row * QKVN + CC + hh * 64;
        float a = X[base + p];
        float b = X[base + p + 32];
        Kb[(size_t)row * KVW + hh * 64 + p]      = __float2bfloat16(a * cs - b * sn);
        Kb[(size_t)row * KVW + hh * 64 + p + 32] = __float2bfloat16(b * cs + a * sn);
    } else if (i < NQ + NK + NV) {
        int j = i - NQ - NK;
        int row = j >> 7;
        int p2 = (j & 127) * 2;
        const float* base = X + (size_t)row * QKVN + CC + KVW;
        *(__nv_bfloat162*)&Vb[(size_t)row * KVW + p2] =
            __floats2bfloat162_rn(base[p2], base[p2 + 1]);
    }
}

// ------- flash attention: 2 heads/CTA (shared K/V), 64-row Q tiles -------
__global__ __launch_bounds__(256) void attn_mma(const __nv_bfloat16* __restrict__ Qb,
                                                const __nv_bfloat16* __restrict__ Kb,
                                                const __nv_bfloat16* __restrict__ Vb,
                                                __nv_bfloat16* __restrict__ O) {
    int qb = blockIdx.x, hp = blockIdx.y, b = blockIdx.z;
    int tid = threadIdx.x;
    int wid = tid >> 5, lane = tid & 31;
    int hw = wid >> 2;
    int wq = wid & 3;
    int h = hp * 2 + hw;
    int kvh = (hp * 2) / NREP;

    __shared__ __align__(16) __nv_bfloat16 Qs[2][64 * 72];
    __shared__ __align__(16) __nv_bfloat16 Ks[64 * 72];
    __shared__ __align__(16) __nv_bfloat16 Vs[64 * 72];

    for (int i = tid; i < 2 * 64 * 8; i += 256) {
        int hh = i >> 9;
        int j = i & 511;
        int row = j >> 3, g = (j & 7) * 8;
        *(uint4*)&Qs[hh][row * 72 + g] =
            *(const uint4*)&Qb[((size_t)(b * TT + qb * 64 + row)) * CC + (hp * 2 + hh) * DH + g];
    }
    __syncthreads();

    int r16 = lane & 15, kh = lane >> 4;
    int rn = lane & 7, knh = (lane >> 3) & 1;
    uint32_t qf[4][4];
#pragma unroll
    for (int kk = 0; kk < 4; kk++) {
        uint32_t ad = su32(&Qs[hw][(wq * 16 + r16) * 72 + kk * 16 + kh * 8]);
        asm volatile("ldmatrix.sync.aligned.m8n8.x4.shared.b16 {%0,%1,%2,%3}, [%4];"
            : "=r"(qf[kk][0]), "=r"(qf[kk][1]), "=r"(qf[kk][2]), "=r"(qf[kk][3]) : "r"(ad));
    }

    int rr = lane >> 2, cq = (lane & 3) * 2;
    int t0 = qb * 64 + wq * 16 + rr;
    float m0 = -1e30f, m1 = -1e30f, l0 = 0.f, l1 = 0.f;
    float acc[8][4];
#pragma unroll
    for (int dn = 0; dn < 8; dn++)
#pragma unroll
        for (int r = 0; r < 4; r++) acc[dn][r] = 0.f;

    int kstart = qb * 64 - WIN; if (kstart < 0) kstart = 0;
    for (int k0 = kstart; k0 <= qb * 64; k0 += 64) {
        __syncthreads();
        for (int i = tid; i < 64 * 32; i += 256) {
            int row = i >> 5, p2 = (i & 31) * 2;
            size_t kr = ((size_t)(b * TT + k0 + row)) * KVW + kvh * DH;
            *(__nv_bfloat162*)&Ks[row * 72 + p2] = *(const __nv_bfloat162*)&Kb[kr + p2];
            *(__nv_bfloat162*)&Vs[row * 72 + p2] = *(const __nv_bfloat162*)&Vb[kr + p2];
        }
        __syncthreads();

        float s[8][4];
#pragma unroll
        for (int j = 0; j < 8; j++) {
            s[j][0] = s[j][1] = s[j][2] = s[j][3] = 0.f;
#pragma unroll
            for (int kk = 0; kk < 4; kk++) {
                uint32_t bfr[2];
                uint32_t bd = su32(&Ks[(j * 8 + rn) * 72 + kk * 16 + knh * 8]);
                asm volatile("ldmatrix.sync.aligned.m8n8.x2.shared.b16 {%0,%1}, [%2];"
                    : "=r"(bfr[0]), "=r"(bfr[1]) : "r"(bd));
                asm volatile(
                    "mma.sync.aligned.m16n8k16.row.col.f32.bf16.bf16.f32 "
                    "{%0,%1,%2,%3}, {%4,%5,%6,%7}, {%8,%9}, {%0,%1,%2,%3};"
                    : "+f"(s[j][0]), "+f"(s[j][1]), "+f"(s[j][2]), "+f"(s[j][3])
                    : "r"(qf[kk][0]), "r"(qf[kk][1]), "r"(qf[kk][2]), "r"(qf[kk][3]),
                      "r"(bfr[0]), "r"(bfr[1]));
            }
        }
#pragma unroll
        for (int j = 0; j < 8; j++) {
            int kg = k0 + j * 8 + cq;
            if (kg > t0 || kg < t0 - WIN) s[j][0] = -1e30f;
            if (kg + 1 > t0 || kg + 1 < t0 - WIN) s[j][1] = -1e30f;
            if (kg > t0 + 8 || kg < t0 + 8 - WIN) s[j][2] = -1e30f;
            if (kg + 1 > t0 + 8 || kg + 1 < t0 + 8 - WIN) s[j][3] = -1e30f;
        }
        float mx0 = -1e30f, mx1 = -1e30f;
#pragma unroll
        for (int j = 0; j < 8; j++) {
            mx0 = fmaxf(mx0, fmaxf(s[j][0], s[j][1]));
            mx1 = fmaxf(mx1, fmaxf(s[j][2], s[j][3]));
        }
        mx0 = fmaxf(mx0, __shfl_xor_sync(0xffffffffu, mx0, 1));
        mx0 = fmaxf(mx0, __shfl_xor_sync(0xffffffffu, mx0, 2));
        mx1 = fmaxf(mx1, __shfl_xor_sync(0xffffffffu, mx1, 1));
        mx1 = fmaxf(mx1, __shfl_xor_sync(0xffffffffu, mx1, 2));
        float mn0 = fmaxf(m0, mx0), mn1 = fmaxf(m1, mx1);
        float c0 = __expf(m0 - mn0), c1 = __expf(m1 - mn1);
        m0 = mn0; m1 = mn1;
        l0 *= c0; l1 *= c1;
#pragma unroll
        for (int dn = 0; dn < 8; dn++) {
            acc[dn][0] *= c0; acc[dn][1] *= c0;
            acc[dn][2] *= c1; acc[dn][3] *= c1;
        }
#pragma unroll
        for (int j = 0; j < 8; j++) {
            s[j][0] = __expf(s[j][0] - m0); s[j][1] = __expf(s[j][1] - m0);
            s[j][2] = __expf(s[j][2] - m1); s[j][3] = __expf(s[j][3] - m1);
            l0 += s[j][0] + s[j][1];
            l1 += s[j][2] + s[j][3];
        }
        uint32_t pa[4][4];
#pragma unroll
        for (int kk = 0; kk < 4; kk++) {
            int j0 = kk * 2, j1 = kk * 2 + 1;
            pa[kk][0] = packbf(s[j0][0], s[j0][1]);
            pa[kk][1] = packbf(s[j0][2], s[j0][3]);
            pa[kk][2] = packbf(s[j1][0], s[j1][1]);
            pa[kk][3] = packbf(s[j1][2], s[j1][3]);
        }
#pragma unroll
        for (int dn = 0; dn < 8; dn++)
#pragma unroll
            for (int kk = 0; kk < 4; kk++) {
                uint32_t bfr[2];
                uint32_t bd = su32(&Vs[(kk * 16 + knh * 8 + rn) * 72 + dn * 8]);
                asm volatile("ldmatrix.sync.aligned.m8n8.x2.trans.shared.b16 {%0,%1}, [%2];"
                    : "=r"(bfr[0]), "=r"(bfr[1]) : "r"(bd));
                asm volatile(
                    "mma.sync.aligned.m16n8k16.row.col.f32.bf16.bf16.f32 "
                    "{%0,%1,%2,%3}, {%4,%5,%6,%7}, {%8,%9}, {%0,%1,%2,%3};"
                    : "+f"(acc[dn][0]), "+f"(acc[dn][1]), "+f"(acc[dn][2]), "+f"(acc[dn][3])
                    : "r"(pa[kk][0]), "r"(pa[kk][1]), "r"(pa[kk][2]), "r"(pa[kk][3]),
                      "r"(bfr[0]), "r"(bfr[1]));
            }
    }
    l0 += __shfl_xor_sync(0xffffffffu, l0, 1);
    l0 += __shfl_xor_sync(0xffffffffu, l0, 2);
    l1 += __shfl_xor_sync(0xffffffffu, l1, 1);
    l1 += __shfl_xor_sync(0xffffffffu, l1, 2);
    float i0 = 1.f / l0, i1 = 1.f / l1;
    __nv_bfloat16* o0 = O + ((size_t)(b * TT + t0)) * CC + h * DH;
    __nv_bfloat16* o1 = o0 + (size_t)8 * CC;
#pragma unroll
    for (int dn = 0; dn < 8; dn++) {
        *(__nv_bfloat162*)&o0[dn * 8 + cq] =
            __floats2bfloat162_rn(acc[dn][0] * i0, acc[dn][1] * i0);
        *(__nv_bfloat162*)&o1[dn * 8 + cq] =
            __floats2bfloat162_rn(acc[dn][2] * i1, acc[dn][3] * i1);
    }
}

// ---------------- router ----------------
__global__ void route_kernel(const float* __restrict__ xf,
                             const float* __restrict__ gw) {
    int warp = threadIdx.x >> 5, lane = threadIdx.x & 31;
    int tok = blockIdx.x * 4 + warp;
    if (tok >= NTOK) return;
    const float* xr = xf + (size_t)tok * CC;
    float part[EE];
#pragma unroll
    for (int e = 0; e < EE; e++) part[e] = 0.f;
    for (int d = lane; d < CC; d += 32) {
        float xv = xr[d];
#pragma unroll
        for (int e = 0; e < EE; e++) part[e] += xv * gw[d * EE + e];
    }
#pragma unroll
    for (int e = 0; e < EE; e++)
#pragma unroll
        for (int o = 16; o > 0; o >>= 1)
            part[e] += __shfl_xor_sync(0xffffffffu, part[e], o);
    if (lane == 0) {
        float v0 = -1e30f; int i0 = 0;
#pragma unroll
        for (int e = 0; e < EE; e++) if (part[e] > v0) { v0 = part[e]; i0 = e; }
        float v1 = -1e30f; int i1 = 0;
#pragma unroll
        for (int e = 0; e < EE; e++)
            if (e != i0 && part[e] > v1) { v1 = part[e]; i1 = e; }
        float ex = expf(v1 - v0);
        float w0 = 1.f / (1.f + ex);
        float w1 = ex / (1.f + ex);
        g_sel[tok * 2] = i0; g_sel[tok * 2 + 1] = i1;
        g_selw[tok * 2] = w0; g_selw[tok * 2 + 1] = w1;
        float mx = v0, sum = 0.f, pe[EE];
#pragma unroll
        for (int e = 0; e < EE; e++) { pe[e] = expf(part[e] - mx); sum += pe[e]; }
#pragma unroll
        for (int e = 0; e < EE; e++) g_probs[tok * EE + e] = pe[e] / sum;
        float lse = mx + logf(sum);
        g_lse2[tok] = lse * lse;
    }
}

// ---------------- aux loss ----------------
__global__ void aux_kernel() {
    __shared__ float red[256];
    int tid = threadIdx.x;
    float loadv[EE];
#pragma unroll
    for (int e = 0; e < EE; e++) loadv[e] = 0.f;
    for (int n = tid; n < NTOK; n += 256) {
#pragma unroll
        for (int e = 0; e < EE; e++) loadv[e] += g_probs[n * EE + e];
    }
    float loads[EE];
    for (int e = 0; e < EE; e++) {
        red[tid] = loadv[e]; __syncthreads();
        for (int o = 128; o > 0; o >>= 1) {
            if (tid < o) red[tid] += red[tid + o];
            __syncthreads();
        }
        loads[e] = red[0]; __syncthreads();
    }
    float zp = 0.f;
    for (int n = tid; n < NTOK; n += 256) zp += g_lse2[n];
    red[tid] = zp; __syncthreads();
    for (int o = 128; o > 0; o >>= 1) {
        if (tid < o) red[tid] += red[tid + o];
        __syncthreads();
    }
    if (tid == 0) {
        float tot = 0.f;
        for (int e = 0; e < EE; e++) tot += loads[e];
        float lb = 0.f;
        for (int e = 0; e < EE; e++) { float f = loads[e] / tot; lb += f * f; }
        lb *= (float)EE;
        float z = red[0] / (float)NTOK;
        g_aux = 0.01f * lb + 0.001f * z;
    }
}

__global__ void zero_cnt_kernel() { if (threadIdx.x < EE) g_cnt[threadIdx.x] = 0; }

__global__ void count_kernel() {
    int i = blockIdx.x * blockDim.x + threadIdx.x;
    if (i >= NTOK) return;
#pragma unroll
    for (int kk = 0; kk < TOPK; kk++)
        atomicAdd(&g_cnt[g_sel[i * 2 + kk]], 1);
}

__global__ void offsets_kernel() {
    if (threadIdx.x == 0) {
        int acc = 0;
        for (int e = 0; e < EE; e++) {
            g_off[e] = acc;
            acc += (g_cnt[e] + BM - 1) & ~(BM - 1);
            g_cnt2[e] = 0;
        }
        g_off[EE] = acc;
    }
}

__global__ void assign_kernel() {
    int i = blockIdx.x * blockDim.x + threadIdx.x;
    if (i >= NTOK) return;
#pragma unroll
    for (int kk = 0; kk < TOPK; kk++) {
        int e = g_sel[i * 2 + kk];
        int pos = atomicAdd(&g_cnt2[e], 1);
        int row = g_off[e] + pos;
        g_idx[row] = i;
        g_tokrow[i * 2 + kk] = row;
    }
}

__global__ void gather_all_kernel(__nv_bfloat16* __restrict__ dst,
                                  const __nv_bfloat16* __restrict__ src) {
    int b = blockIdx.x;
    if (b >= g_off[EE]) return;
    int e = 0;
    while (g_off[e + 1] <= b) e++;
    if (b - g_off[e] >= g_cnt[e]) return;
    int t = g_idx[b];
    uint4* d4 = (uint4*)(dst + (size_t)b * CC);
    const uint4* s4 = (const uint4*)(src + (size_t)t * CC);
    int i = threadIdx.x;
    if (i < CC * 2 / 16) d4[i] = s4[i];
}

// final: out = h + a_moe * (shared + w0*eo[r0] + w1*eo[r1]); writes aux too
__global__ void final_kernel(const float* __restrict__ h, const float* __restrict__ moe,
                             const float* __restrict__ eo,
                             const float* __restrict__ alpha, float* __restrict__ out,
                             int writeAux) {
    int t = blockIdx.x;
    if (writeAux && t == 0 && threadIdx.x == 0) out[OUT_MAIN] = g_aux;
    float w0 = g_selw[t * 2], w1 = g_selw[t * 2 + 1];
    int r0 = g_tokrow[t * 2], r1 = g_tokrow[t * 2 + 1];
    float a = *alpha;
    const float* hr = h + (size_t)t * CC;
    const float* mr = moe + (size_t)t * CC;
    const float* e0 = eo + (size_t)r0 * CC;
    const float* e1 = eo + (size_t)r1 * CC;
    float* orow = out + (size_t)t * CC;
    for (int i = threadIdx.x; i < CC; i += blockDim.x)
        orow[i] = hr[i] + a * (mr[i] + w0 * e0[i] + w1 * e1[i]);
}

// ---------------- launch ----------------
extern "C" void kernel_launch(void* const* d_in, const int* in_sizes, int n_in,
                              void* d_out, int out_size) {
    const float* x      = (const float*)d_in[0];
    const float* ln1    = (const float*)d_in[1];
    const float* ln2    = (const float*)d_in[2];
    const float* wq     = (const float*)d_in[3];
    const float* wk     = (const float*)d_in[4];
    const float* wv     = (const float*)d_in[5];
    const float* wo     = (const float*)d_in[6];
    const float* sw1    = (const float*)d_in[7];
    const float* sw2    = (const float*)d_in[8];
    const float* sw3    = (const float*)d_in[9];
    const float* ew1    = (const float*)d_in[10];
    const float* ew2    = (const float*)d_in[11];
    const float* ew3    = (const float*)d_in[12];
    const float* gatew  = (const float*)d_in[13];
    const float* a_attn = (const float*)d_in[14];
    const float* a_moe  = (const float*)d_in[15];
    float* out = (float*)d_out;

    void* p;
    float *qkv, *h, *xf, *moe, *eo;
    __nv_bfloat16 *xnb, *qb, *aob, *xfb, *xgb, *g1b, *g1e, *kb, *vb;
    __nv_bfloat16 *wqkvt, *wot, *sw12t, *sw3t, *ew12t, *ew3t;
    cudaGetSymbolAddress(&p, g_qkv);  qkv  = (float*)p;
    cudaGetSymbolAddress(&p, g_h);    h    = (float*)p;
    cudaGetSymbolAddress(&p, g_xf);   xf   = (float*)p;
    cudaGetSymbolAddress(&p, g_moe);  moe  = (float*)p;
    cudaGetSymbolAddress(&p, g_eo);   eo   = (float*)p;
    cudaGetSymbolAddress(&p, g_xnb);  xnb  = (__nv_bfloat16*)p;
    cudaGetSymbolAddress(&p, g_qb);   qb   = (__nv_bfloat16*)p;
    cudaGetSymbolAddress(&p, g_aob);  aob  = (__nv_bfloat16*)p;
    cudaGetSymbolAddress(&p, g_xfb);  xfb  = (__nv_bfloat16*)p;
    cudaGetSymbolAddress(&p, g_xgb);  xgb  = (__nv_bfloat16*)p;
    cudaGetSymbolAddress(&p, g_g1b);  g1b  = (__nv_bfloat16*)p;
    cudaGetSymbolAddress(&p, g_g1e);  g1e  = (__nv_bfloat16*)p;
    cudaGetSymbolAddress(&p, g_kb);   kb   = (__nv_bfloat16*)p;
    cudaGetSymbolAddress(&p, g_vb);   vb   = (__nv_bfloat16*)p;
    cudaGetSymbolAddress(&p, g_wqkvt); wqkvt = (__nv_bfloat16*)p;
    cudaGetSymbolAddress(&p, g_wot);   wot   = (__nv_bfloat16*)p;
    cudaGetSymbolAddress(&p, g_sw12t); sw12t = (__nv_bfloat16*)p;
    cudaGetSymbolAddress(&p, g_sw3t);  sw3t  = (__nv_bfloat16*)p;
    cudaGetSymbolAddress(&p, g_ew12t); ew12t = (__nv_bfloat16*)p;
    cudaGetSymbolAddress(&p, g_ew3t);  ew3t  = (__nv_bfloat16*)p;

    static bool s_init = false;
    static cudaStream_t s2 = 0;
    static cudaEvent_t evA = 0, evB = 0, evC = 0, evD = 0, evE = 0, evF = 0, evG = 0;
    if (!s_init) {
        if (cudaStreamCreateWithFlags(&s2, cudaStreamNonBlocking) != cudaSuccess) s2 = 0;
        if (s2) {
            bool ok = true;
            ok &= (cudaEventCreateWithFlags(&evA, cudaEventDisableTiming) == cudaSuccess);
            ok &= (cudaEventCreateWithFlags(&evB, cudaEventDisableTiming) == cudaSuccess);
            ok &= (cudaEventCreateWithFlags(&evC, cudaEventDisableTiming) == cudaSuccess);
            ok &= (cudaEventCreateWithFlags(&evD, cudaEventDisableTiming) == cudaSuccess);
            ok &= (cudaEventCreateWithFlags(&evE, cudaEventDisableTiming) == cudaSuccess);
            ok &= (cudaEventCreateWithFlags(&evF, cudaEventDisableTiming) == cudaSuccess);
            ok &= (cudaEventCreateWithFlags(&evG, cudaEventDisableTiming) == cudaSuccess);
            if (!ok) s2 = 0;
        }
        s_init = true;
    }
    bool forked = (s2 != 0);

    // critical-path conversions (attention weights only)
    wcvt<<<512, 256>>>(wq, wqkvt, CC, QKVN, 0, 0, 0, (long)CC*CC/8);
    wcvt<<<128, 256>>>(wk, wqkvt, KVW, QKVN, CC, 0, 0, (long)CC*KVW/8);
    wcvt<<<128, 256>>>(wv, wqkvt, KVW, QKVN, CC+KVW, 0, 0, (long)CC*KVW/8);
    wcvt<<<512, 256>>>(wo, wot, CC, CC, 0, 0, 0, (long)CC*CC/8);

    // FFN weight conversions forked onto s2 (shared first, then experts)
    if (forked) {
        cudaEventRecord(evA, 0);
        cudaStreamWaitEvent(s2, evA, 0);
        wcvt_pair<<<4096, 256, 0, s2>>>(sw1, sw2, sw12t, FF, 0, 0, (long)CC*FF/4);
        wcvt<<<2048, 256, 0, s2>>>(sw3, sw3t, CC, CC, 0, 0, 0, (long)FF*CC/8);
        cudaEventRecord(evE, s2);
        wcvt_pair<<<dim3(4096,1,EE), 256, 0, s2>>>(ew1, ew2, ew12t, FF,
            (long)CC*FF, (long)CC*2*FF, (long)CC*FF/4);
        wcvt<<<dim3(2048,1,EE), 256, 0, s2>>>(ew3, ew3t, CC, CC, 0,
            (long)FF*CC, (long)FF*CC, (long)FF*CC/8);
        cudaEventRecord(evB, s2);
    } else {
        wcvt_pair<<<4096, 256>>>(sw1, sw2, sw12t, FF, 0, 0, (long)CC*FF/4);
        wcvt<<<2048, 256>>>(sw3, sw3t, CC, CC, 0, 0, 0, (long)FF*CC/8);
        wcvt_pair<<<dim3(4096,1,EE), 256>>>(ew1, ew2, ew12t, FF,
            (long)CC*FF, (long)CC*2*FF, (long)CC*FF/4);
        wcvt<<<dim3(2048,1,EE), 256>>>(ew3, ew3t, CC, CC, 0,
            (long)FF*CC, (long)FF*CC, (long)FF*CC/8);
    }

    // 1) pre-attn norm
    rmsnorm_kernel<<<NTOK, 256>>>(x, ln1, nullptr, xnb);
    // 2) fused QKV projection
    gemm_mma<<<dim3(QKVN/128, NTOK/128), 256>>>(xnb, wqkvt, qkv, QKVN, CC);
    // 3) fused RoPE(q,k) + Q/K/V bf16 compaction
    {
        int total = NTOK*HH*32 + NTOK*KVH*32 + NTOK*(KVW/2);
        rope_all_kernel<<<(total + 255) / 256, 256>>>(qkv, qb, kb, vb);
    }
    // 4) attention (tensor core, 2 heads/CTA with shared K/V)
    attn_mma<<<dim3(TT/64, HH/2, BB), 256>>>(qb, kb, vb, aob);
    // 5) output projection with fused ReZero residual
    gemm_mma_add<<<dim3(CC/128, NTOK/128), 256>>>(aob, wot, x, a_attn, h, CC, CC);
    // 6) post-attn norm
    rmsnorm_kernel<<<NTOK, 256>>>(h, ln2, xf, xfb);
    // 7) routing + aux + compaction — forked onto s2, overlapped with shared GEMM
    if (forked) {
        cudaEventRecord(evC, 0);
        cudaStreamWaitEvent(s2, evC, 0);
        route_kernel<<<NTOK / 4, 128, 0, s2>>>(xf, gatew);
        aux_kernel<<<1, 256, 0, s2>>>();
        zero_cnt_kernel<<<1, 32, 0, s2>>>();
        count_kernel<<<(NTOK + 255) / 256, 256, 0, s2>>>();
        offsets_kernel<<<1, 32, 0, s2>>>();
        assign_kernel<<<(NTOK + 255) / 256, 256, 0, s2>>>();
        cudaEventRecord(evD, s2);
    } else {
        route_kernel<<<NTOK / 4, 128>>>(xf, gatew);
        aux_kernel<<<1, 256>>>();
        zero_cnt_kernel<<<1, 32>>>();
        count_kernel<<<(NTOK + 255) / 256, 256>>>();
        offsets_kernel<<<1, 32>>>();
        assign_kernel<<<(NTOK + 255) / 256, 256>>>();
    }
    // 8) shared expert w12+SwiGLU on main (join shared-weight conversion)
    if (forked) cudaStreamWaitEvent(0, evE, 0);
    gemm_swiglu<<<dim3(2*FF/128, NTOK/128), 256>>>(xfb, sw12t, g1b, 2*FF, CC);
    if (forked) {
        // shared w3 (256 blocks) on s2, overlapping the expert GEMM tail
        cudaEventRecord(evF, 0);
        cudaStreamWaitEvent(s2, evF, 0);
        gemm_mma<<<dim3(CC/128, NTOK/128), 256, 0, s2>>>(g1b, sw3t, moe, CC, FF);
        cudaEventRecord(evG, s2);
    } else {
        gemm_mma<<<dim3(CC/128, NTOK/128), 256>>>(g1b, sw3t, moe, CC, FF);
    }
    // 9) routed experts on main (own intermediate buffer g1e; join routing + weights)
    if (forked) cudaStreamWaitEvent(0, evD, 0);
    gather_all_kernel<<<ECAP, 128>>>(xgb, xfb);
    if (forked) cudaStreamWaitEvent(0, evB, 0);
    gemm_moe_swiglu<<<dim3(2*FF/128, ECAP/128), 256>>>(xgb, ew12t, g1e, 2*FF, CC, (long)CC*2*FF);
    gemm_moe<<<dim3(CC/128, ECAP/128), 256>>>(g1e, ew3t, eo, CC, FF, (long)FF*CC);
    // 10) final combine (join shared w3) + aux scalar
    if (forked) cudaStreamWaitEvent(0, evG, 0);
    final_kernel<<<NTOK, 256>>>(h, moe, eo, a_moe, out, out_size > OUT_MAIN ? 1 : 0);
}